// round 1
// baseline (speedup 1.0000x reference)
#include <cuda_runtime.h>
#include <cuda_bf16.h>
#include <math_constants.h>

// Problem constants
#define BATCH 2
#define SEQ   2048
#define EMB   1024
#define HEADS 16
#define DHEAD 64
#define MTOT  (BATCH*SEQ)      // 4096
#define NORD  4

// ---------------- scratch (device globals; no cudaMalloc allowed) ------------
__device__ float g_q[MTOT * EMB];
__device__ float g_k[MTOT * EMB];
__device__ float g_v[MTOT * EMB];
__device__ float g_h[MTOT * EMB];     // relu(x@Wo1 + bo1)
__device__ float g_org[MTOT * EMB];   // attention output (pre-mixing)
__device__ float g_o[MTOT * NORD];    // order weights

// ---------------- Projection GEMM: C = X @ W + b (optional relu) -------------
// 128x128 block tile, BK=16, 256 threads, 8x8 per thread, double buffered.
__global__ __launch_bounds__(256) void proj_gemm_kernel(
    const float* __restrict__ X,
    const float* __restrict__ Wq, const float* __restrict__ bq,
    const float* __restrict__ Wk, const float* __restrict__ bk,
    const float* __restrict__ Wv, const float* __restrict__ bv,
    const float* __restrict__ Wo1, const float* __restrict__ bo1)
{
    constexpr int BM = 128, BN = 128, BK = 16;
    const int z = blockIdx.z;
    const float* W;
    const float* bias;
    float* C;
    bool relu = false;
    if (z == 0)      { W = Wq;  bias = bq;  C = g_q; }
    else if (z == 1) { W = Wk;  bias = bk;  C = g_k; }
    else if (z == 2) { W = Wv;  bias = bv;  C = g_v; }
    else             { W = Wo1; bias = bo1; C = g_h; relu = true; }

    const int K = EMB, N = EMB;
    __shared__ float As[2][BK][BM];
    __shared__ float Bs[2][BK][BN];

    const int tid = threadIdx.x;
    const int bM = blockIdx.y * BM;
    const int bN = blockIdx.x * BN;

    // A-load mapping: 128 rows x 16 cols, float4 along K
    const int arow = tid >> 2;          // 0..63 (and +64)
    const int acol = (tid & 3) << 2;    // 0,4,8,12
    // B-load mapping: 16 rows x 128 cols, float4 along N
    const int brow = tid >> 5;          // 0..7 (and +8)
    const int bcol = (tid & 31) << 2;   // 0..124

    const float* Aptr = X + (size_t)bM * K;
    const float* Bptr = W + bN;

    // preload tile 0
    {
        float4 a0 = *(const float4*)(Aptr + arow * K + acol);
        float4 a1 = *(const float4*)(Aptr + (arow + 64) * K + acol);
        As[0][acol + 0][arow] = a0.x; As[0][acol + 1][arow] = a0.y;
        As[0][acol + 2][arow] = a0.z; As[0][acol + 3][arow] = a0.w;
        As[0][acol + 0][arow + 64] = a1.x; As[0][acol + 1][arow + 64] = a1.y;
        As[0][acol + 2][arow + 64] = a1.z; As[0][acol + 3][arow + 64] = a1.w;
        float4 b0 = *(const float4*)(Bptr + (size_t)brow * N + bcol);
        float4 b1 = *(const float4*)(Bptr + (size_t)(brow + 8) * N + bcol);
        *(float4*)&Bs[0][brow][bcol] = b0;
        *(float4*)&Bs[0][brow + 8][bcol] = b1;
    }
    __syncthreads();

    float acc[8][8];
#pragma unroll
    for (int i = 0; i < 8; i++)
#pragma unroll
        for (int j = 0; j < 8; j++) acc[i][j] = 0.0f;

    const int tr = (tid >> 4) << 3;   // output row base within tile
    const int tc = (tid & 15) << 3;   // output col base within tile

    const int nT = K / BK;            // 64
    float4 pa0, pa1, pb0, pb1;
    for (int t = 0; t < nT; t++) {
        const int buf = t & 1;
        if (t + 1 < nT) {
            pa0 = *(const float4*)(Aptr + arow * K + (t + 1) * BK + acol);
            pa1 = *(const float4*)(Aptr + (arow + 64) * K + (t + 1) * BK + acol);
            pb0 = *(const float4*)(Bptr + (size_t)((t + 1) * BK + brow) * N + bcol);
            pb1 = *(const float4*)(Bptr + (size_t)((t + 1) * BK + brow + 8) * N + bcol);
        }
#pragma unroll
        for (int k = 0; k < BK; k++) {
            float rm[8], rn[8];
            *(float4*)&rm[0] = *(float4*)&As[buf][k][tr];
            *(float4*)&rm[4] = *(float4*)&As[buf][k][tr + 4];
            *(float4*)&rn[0] = *(float4*)&Bs[buf][k][tc];
            *(float4*)&rn[4] = *(float4*)&Bs[buf][k][tc + 4];
#pragma unroll
            for (int i = 0; i < 8; i++)
#pragma unroll
                for (int j = 0; j < 8; j++)
                    acc[i][j] = fmaf(rm[i], rn[j], acc[i][j]);
        }
        if (t + 1 < nT) {
            const int nb = buf ^ 1;
            As[nb][acol + 0][arow] = pa0.x; As[nb][acol + 1][arow] = pa0.y;
            As[nb][acol + 2][arow] = pa0.z; As[nb][acol + 3][arow] = pa0.w;
            As[nb][acol + 0][arow + 64] = pa1.x; As[nb][acol + 1][arow + 64] = pa1.y;
            As[nb][acol + 2][arow + 64] = pa1.z; As[nb][acol + 3][arow + 64] = pa1.w;
            *(float4*)&Bs[nb][brow][bcol] = pb0;
            *(float4*)&Bs[nb][brow + 8][bcol] = pb1;
        }
        __syncthreads();
    }

    // epilogue: bias (+relu), vectorized stores
#pragma unroll
    for (int i = 0; i < 8; i++) {
        const int row = bM + tr + i;
#pragma unroll
        for (int j4 = 0; j4 < 8; j4 += 4) {
            const int col = bN + tc + j4;
            float4 bv = *(const float4*)(bias + col);
            float4 r;
            r.x = acc[i][j4 + 0] + bv.x;
            r.y = acc[i][j4 + 1] + bv.y;
            r.z = acc[i][j4 + 2] + bv.z;
            r.w = acc[i][j4 + 3] + bv.w;
            if (relu) {
                r.x = fmaxf(r.x, 0.0f); r.y = fmaxf(r.y, 0.0f);
                r.z = fmaxf(r.z, 0.0f); r.w = fmaxf(r.w, 0.0f);
            }
            *(float4*)(C + (size_t)row * N + col) = r;
        }
    }
}

// ------------- order-weight head: o = relu_h @ Wo2 + bo2 (N=4) ---------------
// one warp per row of h (memory-bound: 16MB read)
__global__ __launch_bounds__(256) void owt_kernel(
    const float* __restrict__ h, const float* __restrict__ Wo2,
    const float* __restrict__ bo2, float* __restrict__ o)
{
    const int warp = (blockIdx.x * blockDim.x + threadIdx.x) >> 5;
    const int lane = threadIdx.x & 31;
    if (warp >= MTOT) return;
    const float* hr = h + (size_t)warp * EMB;
    float a0 = 0.f, a1 = 0.f, a2 = 0.f, a3 = 0.f;
#pragma unroll 4
    for (int k = lane; k < EMB; k += 32) {
        float hv = hr[k];
        float4 w = *(const float4*)(Wo2 + (size_t)k * 4);
        a0 = fmaf(hv, w.x, a0);
        a1 = fmaf(hv, w.y, a1);
        a2 = fmaf(hv, w.z, a2);
        a3 = fmaf(hv, w.w, a3);
    }
#pragma unroll
    for (int m = 16; m > 0; m >>= 1) {
        a0 += __shfl_xor_sync(0xffffffffu, a0, m);
        a1 += __shfl_xor_sync(0xffffffffu, a1, m);
        a2 += __shfl_xor_sync(0xffffffffu, a2, m);
        a3 += __shfl_xor_sync(0xffffffffu, a3, m);
    }
    if (lane == 0) {
        o[warp * 4 + 0] = a0 + bo2[0];
        o[warp * 4 + 1] = a1 + bo2[1];
        o[warp * 4 + 2] = a2 + bo2[2];
        o[warp * 4 + 3] = a3 + bo2[3];
    }
}

// -------------------- flash attention (fp32, no 1/sqrt(Dh)) ------------------
// CTA: 64 queries of one (b, head). Key/Value tiles of 32. 256 threads (16x16).
__global__ __launch_bounds__(256) void attn_kernel(
    const float* __restrict__ Q, const float* __restrict__ K,
    const float* __restrict__ V, float* __restrict__ O)
{
    const int qt = blockIdx.x;     // 0..31
    const int hd = blockIdx.y;     // 0..15
    const int b  = blockIdx.z;     // 0..1
    const int q0 = qt * 64;

    __shared__ float Qs[64][68];
    __shared__ float Ks[32][68];
    __shared__ float Vs[32][68];
    __shared__ float Ps[64][36];

    const int tid = threadIdx.x;
    const int tx = tid & 15;       // column group
    const int ty = tid >> 4;       // row group

    const float* Qb = Q + ((size_t)b * SEQ + q0) * EMB + hd * DHEAD;
    const float* Kb = K + (size_t)b * SEQ * EMB + hd * DHEAD;
    const float* Vb = V + (size_t)b * SEQ * EMB + hd * DHEAD;

    // load Q tile 64x64
    {
        const int r = tid >> 2;          // 0..63
        const int c0 = tid & 3;          // float4 group base
#pragma unroll
        for (int i = 0; i < 4; i++) {
            const int c = (c0 + 4 * i) << 2;   // 0..60
            float4 v4 = *(const float4*)(Qb + (size_t)r * EMB + c);
            *(float4*)&Qs[r][c] = v4;
        }
    }

    float m_i[4], l_i[4], oacc[4][4];
#pragma unroll
    for (int ri = 0; ri < 4; ri++) {
        m_i[ri] = -CUDART_INF_F;
        l_i[ri] = 0.0f;
#pragma unroll
        for (int dj = 0; dj < 4; dj++) oacc[ri][dj] = 0.0f;
    }
    __syncthreads();

    for (int kt = 0; kt < SEQ / 32; kt++) {
        const int k0 = kt * 32;
        // load K, V tiles 32x64
        {
            const int r = tid >> 3;       // 0..31
            const int cb = tid & 7;       // float4 idx (and +8)
            const float* kr = Kb + (size_t)(k0 + r) * EMB;
            const float* vr = Vb + (size_t)(k0 + r) * EMB;
            float4 ka = *(const float4*)(kr + (cb << 2));
            float4 kb2 = *(const float4*)(kr + ((cb + 8) << 2));
            float4 va = *(const float4*)(vr + (cb << 2));
            float4 vb2 = *(const float4*)(vr + ((cb + 8) << 2));
            *(float4*)&Ks[r][cb << 2] = ka;
            *(float4*)&Ks[r][(cb + 8) << 2] = kb2;
            *(float4*)&Vs[r][cb << 2] = va;
            *(float4*)&Vs[r][(cb + 8) << 2] = vb2;
        }
        __syncthreads();

        // S = Q K^T : each thread 4 rows x 2 cols
        float s[4][2];
#pragma unroll
        for (int ri = 0; ri < 4; ri++) { s[ri][0] = 0.f; s[ri][1] = 0.f; }
#pragma unroll
        for (int kk = 0; kk < DHEAD; kk += 4) {
            float4 qv[4], kv[2];
#pragma unroll
            for (int ri = 0; ri < 4; ri++) qv[ri] = *(float4*)&Qs[ty + 16 * ri][kk];
#pragma unroll
            for (int cj = 0; cj < 2; cj++) kv[cj] = *(float4*)&Ks[tx + 16 * cj][kk];
#pragma unroll
            for (int ri = 0; ri < 4; ri++)
#pragma unroll
                for (int cj = 0; cj < 2; cj++) {
                    s[ri][cj] = fmaf(qv[ri].x, kv[cj].x, s[ri][cj]);
                    s[ri][cj] = fmaf(qv[ri].y, kv[cj].y, s[ri][cj]);
                    s[ri][cj] = fmaf(qv[ri].z, kv[cj].z, s[ri][cj]);
                    s[ri][cj] = fmaf(qv[ri].w, kv[cj].w, s[ri][cj]);
                }
        }

        // online softmax update (row reductions across the 16 tx-lanes)
        float scale[4];
#pragma unroll
        for (int ri = 0; ri < 4; ri++) {
            float tm = fmaxf(s[ri][0], s[ri][1]);
#pragma unroll
            for (int m = 1; m < 16; m <<= 1)
                tm = fmaxf(tm, __shfl_xor_sync(0xffffffffu, tm, m));
            const float mnew = fmaxf(m_i[ri], tm);
            scale[ri] = __expf(m_i[ri] - mnew);
            float psum = 0.0f;
#pragma unroll
            for (int cj = 0; cj < 2; cj++) {
                float p = __expf(s[ri][cj] - mnew);
                Ps[ty + 16 * ri][tx + 16 * cj] = p;
                psum += p;
            }
#pragma unroll
            for (int m = 1; m < 16; m <<= 1)
                psum += __shfl_xor_sync(0xffffffffu, psum, m);
            l_i[ri] = l_i[ri] * scale[ri] + psum;
            m_i[ri] = mnew;
#pragma unroll
            for (int dj = 0; dj < 4; dj++) oacc[ri][dj] *= scale[ri];
        }
        __syncthreads();

        // O += P @ V  (thread covers rows ty+16ri, d-cols tx*4..tx*4+3)
#pragma unroll 8
        for (int j = 0; j < 32; j++) {
            float4 vv = *(float4*)&Vs[j][tx << 2];
            float pv[4];
#pragma unroll
            for (int ri = 0; ri < 4; ri++) pv[ri] = Ps[ty + 16 * ri][j];
#pragma unroll
            for (int ri = 0; ri < 4; ri++) {
                oacc[ri][0] = fmaf(pv[ri], vv.x, oacc[ri][0]);
                oacc[ri][1] = fmaf(pv[ri], vv.y, oacc[ri][1]);
                oacc[ri][2] = fmaf(pv[ri], vv.z, oacc[ri][2]);
                oacc[ri][3] = fmaf(pv[ri], vv.w, oacc[ri][3]);
            }
        }
        __syncthreads();
    }

    // write out: O / l
    float* Ob = O + ((size_t)b * SEQ + q0) * EMB + hd * DHEAD;
#pragma unroll
    for (int ri = 0; ri < 4; ri++) {
        const int r = ty + 16 * ri;
        const float inv = 1.0f / l_i[ri];
        float4 r4;
        r4.x = oacc[ri][0] * inv;
        r4.y = oacc[ri][1] * inv;
        r4.z = oacc[ri][2] * inv;
        r4.w = oacc[ri][3] * inv;
        *(float4*)(Ob + (size_t)r * EMB + (tx << 2)) = r4;
    }
}

// ------------- polynomial order-weighted mixing (elementwise) ----------------
// out = org*(o0 + org*(o1 + org*(o2 + org*o3)))
__global__ __launch_bounds__(256) void mix_kernel(
    const float* __restrict__ org, const float* __restrict__ o,
    float* __restrict__ out)
{
    const int idx = blockIdx.x * blockDim.x + threadIdx.x;  // float4 index
    if (idx >= MTOT * EMB / 4) return;
    const int m = idx >> 8;   // EMB/4 = 256 float4 per row
    float4 g = ((const float4*)org)[idx];
    float4 w = ((const float4*)o)[m];   // o0..o3 for this token
    float4 r;
    r.x = g.x * fmaf(g.x, fmaf(g.x, fmaf(g.x, w.w, w.z), w.y), w.x);
    r.y = g.y * fmaf(g.y, fmaf(g.y, fmaf(g.y, w.w, w.z), w.y), w.x);
    r.z = g.z * fmaf(g.z, fmaf(g.z, fmaf(g.z, w.w, w.z), w.y), w.x);
    r.w = g.w * fmaf(g.w, fmaf(g.w, fmaf(g.w, w.w, w.z), w.y), w.x);
    ((float4*)out)[idx] = r;
}

// ------------------------------ launch -------------------------------------
extern "C" void kernel_launch(void* const* d_in, const int* in_sizes, int n_in,
                              void* d_out, int out_size)
{
    const float* x   = (const float*)d_in[0];
    const float* Wq  = (const float*)d_in[1];
    const float* bq  = (const float*)d_in[2];
    const float* Wk  = (const float*)d_in[3];
    const float* bk  = (const float*)d_in[4];
    const float* Wv  = (const float*)d_in[5];
    const float* bv  = (const float*)d_in[6];
    const float* Wo1 = (const float*)d_in[7];
    const float* bo1 = (const float*)d_in[8];
    const float* Wo2 = (const float*)d_in[9];
    const float* bo2 = (const float*)d_in[10];
    float* out = (float*)d_out;

    float *q, *k, *v, *h, *org, *o;
    cudaGetSymbolAddress((void**)&q, g_q);
    cudaGetSymbolAddress((void**)&k, g_k);
    cudaGetSymbolAddress((void**)&v, g_v);
    cudaGetSymbolAddress((void**)&h, g_h);
    cudaGetSymbolAddress((void**)&org, g_org);
    cudaGetSymbolAddress((void**)&o, g_o);

    // 1) projections q,k,v + relu-hidden h
    dim3 gGrid(EMB / 128, MTOT / 128, 4);
    proj_gemm_kernel<<<gGrid, 256>>>(x, Wq, bq, Wk, bk, Wv, bv, Wo1, bo1);

    // 2) order weights o = h @ Wo2 + bo2
    owt_kernel<<<(MTOT * 32 + 255) / 256, 256>>>(h, Wo2, bo2, o);

    // 3) flash attention -> org
    dim3 aGrid(SEQ / 64, HEADS, BATCH);
    attn_kernel<<<aGrid, 256>>>(q, k, v, org);

    // 4) polynomial mixing -> out
    const int nv4 = MTOT * EMB / 4;
    mix_kernel<<<(nv4 + 255) / 256, 256>>>(org, o, out);
}

// round 3
// speedup vs baseline: 1.2656x; 1.2656x over previous
#include <cuda_runtime.h>
#include <cuda_bf16.h>
#include <cstdint>
#include <math_constants.h>

// Problem constants
#define BATCH 2
#define SEQ   2048
#define EMB   1024
#define HEADS 16
#define DHEAD 64
#define MTOT  (BATCH*SEQ)      // 4096
#define NORD  4

// ---------------- scratch (device globals; no cudaMalloc allowed) ------------
__device__ float g_q[MTOT * EMB];
__device__ float g_k[MTOT * EMB];
__device__ float g_v[MTOT * EMB];
__device__ float g_h[MTOT * EMB];     // relu(x@Wo1 + bo1)
__device__ float g_org[MTOT * EMB];   // attention output (pre-mixing)
__device__ float g_o[MTOT * NORD];    // order weights

// bf16 split operands for HMMA GEMMs
__device__ __align__(16) __nv_bfloat16 g_xhi[MTOT * EMB];
__device__ __align__(16) __nv_bfloat16 g_xlo[MTOT * EMB];
__device__ __align__(16) __nv_bfloat16 g_wthi[4 * EMB * EMB];  // W^T per weight, [n][k]
__device__ __align__(16) __nv_bfloat16 g_wtlo[4 * EMB * EMB];

// ======================= PTX helpers (arch-portable) =========================
__device__ __forceinline__ uint32_t smem_u32(const void* p) {
    uint32_t a;
    asm("{ .reg .u64 t; cvta.to.shared.u64 t, %1; cvt.u32.u64 %0, t; }"
        : "=r"(a) : "l"(p));
    return a;
}

#define CP_ASYNC16(dst, src) \
    asm volatile("cp.async.cg.shared.global [%0], [%1], 16;" :: "r"(dst), "l"(src))
#define CP_COMMIT() asm volatile("cp.async.commit_group;" ::: "memory")
#define CP_WAIT(n)  asm volatile("cp.async.wait_group %0;" :: "n"(n) : "memory")

__device__ __forceinline__ void ldsm_x4(uint32_t* r, uint32_t addr) {
    asm volatile("ldmatrix.sync.aligned.m8n8.x4.shared.b16 {%0,%1,%2,%3}, [%4];"
        : "=r"(r[0]), "=r"(r[1]), "=r"(r[2]), "=r"(r[3]) : "r"(addr));
}

// D(f32) += A(bf16) * B(bf16), m16n8k16
__device__ __forceinline__ void mma16816(float* c, const uint32_t* a, const uint32_t* b) {
    asm volatile(
        "mma.sync.aligned.m16n8k16.row.col.f32.bf16.bf16.f32 "
        "{%0,%1,%2,%3}, {%4,%5,%6,%7}, {%8,%9}, {%0,%1,%2,%3};"
        : "+f"(c[0]), "+f"(c[1]), "+f"(c[2]), "+f"(c[3])
        : "r"(a[0]), "r"(a[1]), "r"(a[2]), "r"(a[3]), "r"(b[0]), "r"(b[1]));
}

// ====================== split / transpose prep kernels =======================
__global__ __launch_bounds__(256) void split_x_kernel(
    const float* __restrict__ x, __nv_bfloat16* __restrict__ hi,
    __nv_bfloat16* __restrict__ lo)
{
    const int i4 = blockIdx.x * blockDim.x + threadIdx.x;
    if (i4 >= MTOT * EMB / 4) return;
    float4 v = ((const float4*)x)[i4];
    __nv_bfloat16 h0 = __float2bfloat16(v.x);
    __nv_bfloat16 h1 = __float2bfloat16(v.y);
    __nv_bfloat16 h2 = __float2bfloat16(v.z);
    __nv_bfloat16 h3 = __float2bfloat16(v.w);
    __nv_bfloat16 l0 = __float2bfloat16(v.x - __bfloat162float(h0));
    __nv_bfloat16 l1 = __float2bfloat16(v.y - __bfloat162float(h1));
    __nv_bfloat16 l2 = __float2bfloat16(v.z - __bfloat162float(h2));
    __nv_bfloat16 l3 = __float2bfloat16(v.w - __bfloat162float(h3));
    *(__nv_bfloat162*)(hi + 4 * (size_t)i4)     = __halves2bfloat162(h0, h1);
    *(__nv_bfloat162*)(hi + 4 * (size_t)i4 + 2) = __halves2bfloat162(h2, h3);
    *(__nv_bfloat162*)(lo + 4 * (size_t)i4)     = __halves2bfloat162(l0, l1);
    *(__nv_bfloat162*)(lo + 4 * (size_t)i4 + 2) = __halves2bfloat162(l2, l3);
}

// transpose W [k][n] -> W^T [n][k] with hi/lo split, per-weight (blockIdx.z)
__global__ __launch_bounds__(256) void split_wt_kernel(
    const float* __restrict__ Wq, const float* __restrict__ Wk,
    const float* __restrict__ Wv, const float* __restrict__ Wo1,
    __nv_bfloat16* __restrict__ wthi, __nv_bfloat16* __restrict__ wtlo)
{
    const int z = blockIdx.z;
    const float* W = (z == 0) ? Wq : (z == 1) ? Wk : (z == 2) ? Wv : Wo1;
    __shared__ float ts[32][33];
    const int n0 = blockIdx.x * 32;
    const int k0 = blockIdx.y * 32;
    const int tx = threadIdx.x, ty = threadIdx.y;   // 32 x 8
#pragma unroll
    for (int i = 0; i < 4; i++)
        ts[ty + 8 * i][tx] = W[(size_t)(k0 + ty + 8 * i) * EMB + n0 + tx];
    __syncthreads();
    __nv_bfloat16* oh = wthi + (size_t)z * EMB * EMB;
    __nv_bfloat16* ol = wtlo + (size_t)z * EMB * EMB;
#pragma unroll
    for (int i = 0; i < 4; i++) {
        const int n = n0 + ty + 8 * i;
        float v = ts[tx][ty + 8 * i];          // = W[k0+tx][n]
        __nv_bfloat16 h = __float2bfloat16(v);
        __nv_bfloat16 l = __float2bfloat16(v - __bfloat162float(h));
        oh[(size_t)n * EMB + k0 + tx] = h;
        ol[(size_t)n * EMB + k0 + tx] = l;
    }
}

// =================== HMMA projection GEMM (bf16x3 split) =====================
// C[128x128] = X[128x1024] @ W[1024x128] + b  via  hi*hi + hi*lo + lo*hi.
// 8 warps, each 64x32. BK=32 bf16. cp.async double buffer. ldmatrix frags.
#define PSTRIDE 40                       // bf16 per smem row (32 + 8 pad = 80B)
#define TILE_BYTES (128 * PSTRIDE * 2)   // 10240
#define STAGE_BYTES (4 * TILE_BYTES)     // 40960 (Ah, Al, Bh, Bl)
#define PROJ_SMEM_BYTES (2 * STAGE_BYTES)

__global__ __launch_bounds__(256, 1) void proj_mma_kernel(
    const __nv_bfloat16* __restrict__ xhi, const __nv_bfloat16* __restrict__ xlo,
    const __nv_bfloat16* __restrict__ wthi, const __nv_bfloat16* __restrict__ wtlo,
    const float* __restrict__ bq, const float* __restrict__ bk,
    const float* __restrict__ bv, const float* __restrict__ bo1)
{
    extern __shared__ char smem[];
    const uint32_t sbase = smem_u32(smem);

    const int z = blockIdx.z;
    const float* bias = (z == 0) ? bq : (z == 1) ? bk : (z == 2) ? bv : bo1;
    float* C = (z == 0) ? g_q : (z == 1) ? g_k : (z == 2) ? g_v : g_h;
    const bool relu = (z == 3);

    const int tid = threadIdx.x;
    const int wid = tid >> 5;
    const int lane = tid & 31;
    const int wr = wid >> 2;          // warp row (0/1): rows wr*64
    const int wc = wid & 3;           // warp col (0..3): cols wc*32
    const int m0 = blockIdx.y * 128;
    const int n0 = blockIdx.x * 128;

    const __nv_bfloat16* Ah = xhi + (size_t)m0 * EMB;
    const __nv_bfloat16* Al = xlo + (size_t)m0 * EMB;
    const __nv_bfloat16* Bh = wthi + (size_t)z * EMB * EMB + (size_t)n0 * EMB;
    const __nv_bfloat16* Bl = wtlo + (size_t)z * EMB * EMB + (size_t)n0 * EMB;

    // stage loader: 4 tiles x 128 rows x 64B, 16B per cp.async, 8 per thread
    auto load_stage = [&](int s, int kc) {
        const __nv_bfloat16* srcs[4] = { Ah + kc * 32, Al + kc * 32,
                                         Bh + kc * 32, Bl + kc * 32 };
        const uint32_t dbase = sbase + (uint32_t)s * STAGE_BYTES;
#pragma unroll
        for (int t = 0; t < 8; t++) {
            const int idx = tid + t * 256;
            const int tile = idx >> 9;
            const int w = idx & 511;
            const int row = w >> 2;
            const int c16 = w & 3;
            const uint32_t dst = dbase + tile * TILE_BYTES + row * (PSTRIDE * 2) + c16 * 16;
            const void* src = srcs[tile] + (size_t)row * EMB + c16 * 8;
            CP_ASYNC16(dst, src);
        }
    };

    float acc[4][4][4];
#pragma unroll
    for (int mi = 0; mi < 4; mi++)
#pragma unroll
        for (int nj = 0; nj < 4; nj++)
#pragma unroll
            for (int e = 0; e < 4; e++) acc[mi][nj][e] = 0.0f;

    // ldmatrix lane address components
    const int arow = lane & 15;              // A: 16 rows
    const int ahalf = lane >> 4;             // A: k half (0/1) -> +16B
    const int brow = (lane & 7) + ((lane >> 4) << 3);  // B: n row within 16
    const int bkoff = ((lane >> 3) & 1) * 16;          // B: k half bytes

    load_stage(0, 0);
    CP_COMMIT();

    const int NCH = EMB / 32;    // 32
    for (int kc = 0; kc < NCH; kc++) {
        const int s = kc & 1;
        if (kc + 1 < NCH) {
            load_stage(s ^ 1, kc + 1);
            CP_COMMIT();
            CP_WAIT(1);
        } else {
            CP_WAIT(0);
        }
        __syncthreads();

        const uint32_t st = sbase + (uint32_t)s * STAGE_BYTES;
#pragma unroll
        for (int k16 = 0; k16 < 2; k16++) {
            uint32_t ah[4][4], al[4][4], bh[4][2], bl[4][2];
#pragma unroll
            for (int mi = 0; mi < 4; mi++) {
                const uint32_t ra = (uint32_t)(wr * 64 + mi * 16 + arow) * (PSTRIDE * 2)
                                    + k16 * 32 + ahalf * 16;
                ldsm_x4(ah[mi], st + 0 * TILE_BYTES + ra);
                ldsm_x4(al[mi], st + 1 * TILE_BYTES + ra);
            }
#pragma unroll
            for (int p = 0; p < 2; p++) {
                const uint32_t rb = (uint32_t)(wc * 32 + p * 16 + brow) * (PSTRIDE * 2)
                                    + k16 * 32 + bkoff;
                uint32_t tmp[4];
                ldsm_x4(tmp, st + 2 * TILE_BYTES + rb);
                bh[2 * p][0] = tmp[0]; bh[2 * p][1] = tmp[1];
                bh[2 * p + 1][0] = tmp[2]; bh[2 * p + 1][1] = tmp[3];
                ldsm_x4(tmp, st + 3 * TILE_BYTES + rb);
                bl[2 * p][0] = tmp[0]; bl[2 * p][1] = tmp[1];
                bl[2 * p + 1][0] = tmp[2]; bl[2 * p + 1][1] = tmp[3];
            }
#pragma unroll
            for (int mi = 0; mi < 4; mi++)
#pragma unroll
                for (int nj = 0; nj < 4; nj++) {
                    mma16816(acc[mi][nj], ah[mi], bh[nj]);
                    mma16816(acc[mi][nj], ah[mi], bl[nj]);
                    mma16816(acc[mi][nj], al[mi], bh[nj]);
                }
        }
        __syncthreads();
    }

    // epilogue: bias (+relu)
    const int erow = lane >> 2;
    const int ecol = (lane & 3) * 2;
#pragma unroll
    for (int mi = 0; mi < 4; mi++) {
#pragma unroll
        for (int nj = 0; nj < 4; nj++) {
            const int row = m0 + wr * 64 + mi * 16 + erow;
            const int col = n0 + wc * 32 + nj * 8 + ecol;
            const float b0 = bias[col], b1 = bias[col + 1];
            float2 r0, r1;
            r0.x = acc[mi][nj][0] + b0; r0.y = acc[mi][nj][1] + b1;
            r1.x = acc[mi][nj][2] + b0; r1.y = acc[mi][nj][3] + b1;
            if (relu) {
                r0.x = fmaxf(r0.x, 0.0f); r0.y = fmaxf(r0.y, 0.0f);
                r1.x = fmaxf(r1.x, 0.0f); r1.y = fmaxf(r1.y, 0.0f);
            }
            *(float2*)(C + (size_t)row * EMB + col) = r0;
            *(float2*)(C + (size_t)(row + 8) * EMB + col) = r1;
        }
    }
}

// ------------- order-weight head: o = relu_h @ Wo2 + bo2 (N=4) ---------------
__global__ __launch_bounds__(256) void owt_kernel(
    const float* __restrict__ h, const float* __restrict__ Wo2,
    const float* __restrict__ bo2, float* __restrict__ o)
{
    const int warp = (blockIdx.x * blockDim.x + threadIdx.x) >> 5;
    const int lane = threadIdx.x & 31;
    if (warp >= MTOT) return;
    const float* hr = h + (size_t)warp * EMB;
    float a0 = 0.f, a1 = 0.f, a2 = 0.f, a3 = 0.f;
#pragma unroll 4
    for (int k = lane; k < EMB; k += 32) {
        float hv = hr[k];
        float4 w = *(const float4*)(Wo2 + (size_t)k * 4);
        a0 = fmaf(hv, w.x, a0);
        a1 = fmaf(hv, w.y, a1);
        a2 = fmaf(hv, w.z, a2);
        a3 = fmaf(hv, w.w, a3);
    }
#pragma unroll
    for (int m = 16; m > 0; m >>= 1) {
        a0 += __shfl_xor_sync(0xffffffffu, a0, m);
        a1 += __shfl_xor_sync(0xffffffffu, a1, m);
        a2 += __shfl_xor_sync(0xffffffffu, a2, m);
        a3 += __shfl_xor_sync(0xffffffffu, a3, m);
    }
    if (lane == 0) {
        o[warp * 4 + 0] = a0 + bo2[0];
        o[warp * 4 + 1] = a1 + bo2[1];
        o[warp * 4 + 2] = a2 + bo2[2];
        o[warp * 4 + 3] = a3 + bo2[3];
    }
}

// -------------------- flash attention (fp32, no 1/sqrt(Dh)) ------------------
__global__ __launch_bounds__(256) void attn_kernel(
    const float* __restrict__ Q, const float* __restrict__ K,
    const float* __restrict__ V, float* __restrict__ O)
{
    const int qt = blockIdx.x;
    const int hd = blockIdx.y;
    const int b  = blockIdx.z;
    const int q0 = qt * 64;

    __shared__ float Qs[64][68];
    __shared__ float Ks[32][68];
    __shared__ float Vs[32][68];
    __shared__ float Ps[64][36];

    const int tid = threadIdx.x;
    const int tx = tid & 15;
    const int ty = tid >> 4;

    const float* Qb = Q + ((size_t)b * SEQ + q0) * EMB + hd * DHEAD;
    const float* Kb = K + (size_t)b * SEQ * EMB + hd * DHEAD;
    const float* Vb = V + (size_t)b * SEQ * EMB + hd * DHEAD;

    {
        const int r = tid >> 2;
        const int c0 = tid & 3;
#pragma unroll
        for (int i = 0; i < 4; i++) {
            const int c = (c0 + 4 * i) << 2;
            float4 v4 = *(const float4*)(Qb + (size_t)r * EMB + c);
            *(float4*)&Qs[r][c] = v4;
        }
    }

    float m_i[4], l_i[4], oacc[4][4];
#pragma unroll
    for (int ri = 0; ri < 4; ri++) {
        m_i[ri] = -CUDART_INF_F;
        l_i[ri] = 0.0f;
#pragma unroll
        for (int dj = 0; dj < 4; dj++) oacc[ri][dj] = 0.0f;
    }
    __syncthreads();

    for (int kt = 0; kt < SEQ / 32; kt++) {
        const int k0 = kt * 32;
        {
            const int r = tid >> 3;
            const int cb = tid & 7;
            const float* kr = Kb + (size_t)(k0 + r) * EMB;
            const float* vr = Vb + (size_t)(k0 + r) * EMB;
            float4 ka = *(const float4*)(kr + (cb << 2));
            float4 kb2 = *(const float4*)(kr + ((cb + 8) << 2));
            float4 va = *(const float4*)(vr + (cb << 2));
            float4 vb2 = *(const float4*)(vr + ((cb + 8) << 2));
            *(float4*)&Ks[r][cb << 2] = ka;
            *(float4*)&Ks[r][(cb + 8) << 2] = kb2;
            *(float4*)&Vs[r][cb << 2] = va;
            *(float4*)&Vs[r][(cb + 8) << 2] = vb2;
        }
        __syncthreads();

        float s[4][2];
#pragma unroll
        for (int ri = 0; ri < 4; ri++) { s[ri][0] = 0.f; s[ri][1] = 0.f; }
#pragma unroll
        for (int kk = 0; kk < DHEAD; kk += 4) {
            float4 qv[4], kv[2];
#pragma unroll
            for (int ri = 0; ri < 4; ri++) qv[ri] = *(float4*)&Qs[ty + 16 * ri][kk];
#pragma unroll
            for (int cj = 0; cj < 2; cj++) kv[cj] = *(float4*)&Ks[tx + 16 * cj][kk];
#pragma unroll
            for (int ri = 0; ri < 4; ri++)
#pragma unroll
                for (int cj = 0; cj < 2; cj++) {
                    s[ri][cj] = fmaf(qv[ri].x, kv[cj].x, s[ri][cj]);
                    s[ri][cj] = fmaf(qv[ri].y, kv[cj].y, s[ri][cj]);
                    s[ri][cj] = fmaf(qv[ri].z, kv[cj].z, s[ri][cj]);
                    s[ri][cj] = fmaf(qv[ri].w, kv[cj].w, s[ri][cj]);
                }
        }

        float scale[4];
#pragma unroll
        for (int ri = 0; ri < 4; ri++) {
            float tm = fmaxf(s[ri][0], s[ri][1]);
#pragma unroll
            for (int m = 1; m < 16; m <<= 1)
                tm = fmaxf(tm, __shfl_xor_sync(0xffffffffu, tm, m));
            const float mnew = fmaxf(m_i[ri], tm);
            scale[ri] = __expf(m_i[ri] - mnew);
            float psum = 0.0f;
#pragma unroll
            for (int cj = 0; cj < 2; cj++) {
                float p = __expf(s[ri][cj] - mnew);
                Ps[ty + 16 * ri][tx + 16 * cj] = p;
                psum += p;
            }
#pragma unroll
            for (int m = 1; m < 16; m <<= 1)
                psum += __shfl_xor_sync(0xffffffffu, psum, m);
            l_i[ri] = l_i[ri] * scale[ri] + psum;
            m_i[ri] = mnew;
#pragma unroll
            for (int dj = 0; dj < 4; dj++) oacc[ri][dj] *= scale[ri];
        }
        __syncthreads();

#pragma unroll 8
        for (int j = 0; j < 32; j++) {
            float4 vv = *(float4*)&Vs[j][tx << 2];
            float pv[4];
#pragma unroll
            for (int ri = 0; ri < 4; ri++) pv[ri] = Ps[ty + 16 * ri][j];
#pragma unroll
            for (int ri = 0; ri < 4; ri++) {
                oacc[ri][0] = fmaf(pv[ri], vv.x, oacc[ri][0]);
                oacc[ri][1] = fmaf(pv[ri], vv.y, oacc[ri][1]);
                oacc[ri][2] = fmaf(pv[ri], vv.z, oacc[ri][2]);
                oacc[ri][3] = fmaf(pv[ri], vv.w, oacc[ri][3]);
            }
        }
        __syncthreads();
    }

    float* Ob = O + ((size_t)b * SEQ + q0) * EMB + hd * DHEAD;
#pragma unroll
    for (int ri = 0; ri < 4; ri++) {
        const int r = ty + 16 * ri;
        const float inv = 1.0f / l_i[ri];
        float4 r4;
        r4.x = oacc[ri][0] * inv;
        r4.y = oacc[ri][1] * inv;
        r4.z = oacc[ri][2] * inv;
        r4.w = oacc[ri][3] * inv;
        *(float4*)(Ob + (size_t)r * EMB + (tx << 2)) = r4;
    }
}

// ------------- polynomial order-weighted mixing (elementwise) ----------------
__global__ __launch_bounds__(256) void mix_kernel(
    const float* __restrict__ org, const float* __restrict__ o,
    float* __restrict__ out)
{
    const int idx = blockIdx.x * blockDim.x + threadIdx.x;
    if (idx >= MTOT * EMB / 4) return;
    const int m = idx >> 8;
    float4 g = ((const float4*)org)[idx];
    float4 w = ((const float4*)o)[m];
    float4 r;
    r.x = g.x * fmaf(g.x, fmaf(g.x, fmaf(g.x, w.w, w.z), w.y), w.x);
    r.y = g.y * fmaf(g.y, fmaf(g.y, fmaf(g.y, w.w, w.z), w.y), w.x);
    r.z = g.z * fmaf(g.z, fmaf(g.z, fmaf(g.z, w.w, w.z), w.y), w.x);
    r.w = g.w * fmaf(g.w, fmaf(g.w, fmaf(g.w, w.w, w.z), w.y), w.x);
    ((float4*)out)[idx] = r;
}

// ------------------------------ launch -------------------------------------
extern "C" void kernel_launch(void* const* d_in, const int* in_sizes, int n_in,
                              void* d_out, int out_size)
{
    const float* x   = (const float*)d_in[0];
    const float* Wq  = (const float*)d_in[1];
    const float* bq  = (const float*)d_in[2];
    const float* Wk  = (const float*)d_in[3];
    const float* bk  = (const float*)d_in[4];
    const float* Wv  = (const float*)d_in[5];
    const float* bv  = (const float*)d_in[6];
    const float* Wo1 = (const float*)d_in[7];
    const float* bo1 = (const float*)d_in[8];
    const float* Wo2 = (const float*)d_in[9];
    const float* bo2 = (const float*)d_in[10];
    float* out = (float*)d_out;

    float *q, *k, *v, *h, *org, *o;
    __nv_bfloat16 *xhi, *xlo, *wthi, *wtlo;
    cudaGetSymbolAddress((void**)&q, g_q);
    cudaGetSymbolAddress((void**)&k, g_k);
    cudaGetSymbolAddress((void**)&v, g_v);
    cudaGetSymbolAddress((void**)&h, g_h);
    cudaGetSymbolAddress((void**)&org, g_org);
    cudaGetSymbolAddress((void**)&o, g_o);
    cudaGetSymbolAddress((void**)&xhi, g_xhi);
    cudaGetSymbolAddress((void**)&xlo, g_xlo);
    cudaGetSymbolAddress((void**)&wthi, g_wthi);
    cudaGetSymbolAddress((void**)&wtlo, g_wtlo);

    cudaFuncSetAttribute(proj_mma_kernel,
                         cudaFuncAttributeMaxDynamicSharedMemorySize, PROJ_SMEM_BYTES);

    // 1) split x and W^T into bf16 hi/lo
    const int nv4 = MTOT * EMB / 4;
    split_x_kernel<<<(nv4 + 255) / 256, 256>>>(x, xhi, xlo);
    split_wt_kernel<<<dim3(EMB / 32, EMB / 32, 4), dim3(32, 8)>>>(
        Wq, Wk, Wv, Wo1, wthi, wtlo);

    // 2) HMMA projections q,k,v + relu-hidden h
    proj_mma_kernel<<<dim3(EMB / 128, MTOT / 128, 4), 256, PROJ_SMEM_BYTES>>>(
        xhi, xlo, wthi, wtlo, bq, bk, bv, bo1);

    // 3) order weights o = h @ Wo2 + bo2
    owt_kernel<<<(MTOT * 32 + 255) / 256, 256>>>(h, Wo2, bo2, o);

    // 4) flash attention -> org
    dim3 aGrid(SEQ / 64, HEADS, BATCH);
    attn_kernel<<<aGrid, 256>>>(q, k, v, org);

    // 5) polynomial mixing -> out
    mix_kernel<<<(nv4 + 255) / 256, 256>>>(org, o, out);
}

// round 4
// speedup vs baseline: 2.6010x; 2.0552x over previous
#include <cuda_runtime.h>
#include <cuda_bf16.h>
#include <cuda_fp16.h>
#include <cstdint>
#include <math_constants.h>

// Problem constants
#define BATCH 2
#define SEQ   2048
#define EMB   1024
#define HEADS 16
#define DHEAD 64
#define MTOT  (BATCH*SEQ)      // 4096
#define NORD  4

// ---------------- scratch (device globals; no cudaMalloc allowed) ------------
__device__ float g_h[MTOT * EMB];     // relu(x@Wo1 + bo1)
__device__ float g_org[MTOT * EMB];   // attention output (pre-mixing)
__device__ float g_o[MTOT * NORD];    // order weights

// fp16 hi/lo split q,k,v (written by proj epilogue, consumed by attention)
__device__ __align__(16) __half g_qh[MTOT * EMB];
__device__ __align__(16) __half g_ql[MTOT * EMB];
__device__ __align__(16) __half g_kh[MTOT * EMB];
__device__ __align__(16) __half g_kl[MTOT * EMB];
__device__ __align__(16) __half g_vh[MTOT * EMB];
__device__ __align__(16) __half g_vl[MTOT * EMB];

// bf16 split operands for HMMA projection GEMMs
__device__ __align__(16) __nv_bfloat16 g_xhi[MTOT * EMB];
__device__ __align__(16) __nv_bfloat16 g_xlo[MTOT * EMB];
__device__ __align__(16) __nv_bfloat16 g_wthi[4 * EMB * EMB];  // W^T per weight, [n][k]
__device__ __align__(16) __nv_bfloat16 g_wtlo[4 * EMB * EMB];

// ======================= PTX helpers (arch-portable) =========================
__device__ __forceinline__ uint32_t smem_u32(const void* p) {
    uint32_t a;
    asm("{ .reg .u64 t; cvta.to.shared.u64 t, %1; cvt.u32.u64 %0, t; }"
        : "=r"(a) : "l"(p));
    return a;
}

#define CP_ASYNC16(dst, src) \
    asm volatile("cp.async.cg.shared.global [%0], [%1], 16;" :: "r"(dst), "l"(src))
#define CP_COMMIT() asm volatile("cp.async.commit_group;" ::: "memory")
#define CP_WAIT(n)  asm volatile("cp.async.wait_group %0;" :: "n"(n) : "memory")

__device__ __forceinline__ void ldsm_x4(uint32_t* r, uint32_t addr) {
    asm volatile("ldmatrix.sync.aligned.m8n8.x4.shared.b16 {%0,%1,%2,%3}, [%4];"
        : "=r"(r[0]), "=r"(r[1]), "=r"(r[2]), "=r"(r[3]) : "r"(addr));
}
__device__ __forceinline__ void ldsm_x4_t(uint32_t* r, uint32_t addr) {
    asm volatile("ldmatrix.sync.aligned.m8n8.x4.trans.shared.b16 {%0,%1,%2,%3}, [%4];"
        : "=r"(r[0]), "=r"(r[1]), "=r"(r[2]), "=r"(r[3]) : "r"(addr));
}

// D(f32) += A(bf16) * B(bf16), m16n8k16
__device__ __forceinline__ void mma16816(float* c, const uint32_t* a, const uint32_t* b) {
    asm volatile(
        "mma.sync.aligned.m16n8k16.row.col.f32.bf16.bf16.f32 "
        "{%0,%1,%2,%3}, {%4,%5,%6,%7}, {%8,%9}, {%0,%1,%2,%3};"
        : "+f"(c[0]), "+f"(c[1]), "+f"(c[2]), "+f"(c[3])
        : "r"(a[0]), "r"(a[1]), "r"(a[2]), "r"(a[3]), "r"(b[0]), "r"(b[1]));
}
// D(f32) += A(f16) * B(f16), m16n8k16
__device__ __forceinline__ void mma16816h(float* c, const uint32_t* a, const uint32_t* b) {
    asm volatile(
        "mma.sync.aligned.m16n8k16.row.col.f32.f16.f16.f32 "
        "{%0,%1,%2,%3}, {%4,%5,%6,%7}, {%8,%9}, {%0,%1,%2,%3};"
        : "+f"(c[0]), "+f"(c[1]), "+f"(c[2]), "+f"(c[3])
        : "r"(a[0]), "r"(a[1]), "r"(a[2]), "r"(a[3]), "r"(b[0]), "r"(b[1]));
}

__device__ __forceinline__ uint32_t pack_h2(float a, float b) {
    __half2 h = __floats2half2_rn(a, b);
    return *reinterpret_cast<uint32_t*>(&h);
}

// ====================== split / transpose prep kernels =======================
__global__ __launch_bounds__(256) void split_x_kernel(
    const float* __restrict__ x, __nv_bfloat16* __restrict__ hi,
    __nv_bfloat16* __restrict__ lo)
{
    const int i4 = blockIdx.x * blockDim.x + threadIdx.x;
    if (i4 >= MTOT * EMB / 4) return;
    float4 v = ((const float4*)x)[i4];
    __nv_bfloat16 h0 = __float2bfloat16(v.x);
    __nv_bfloat16 h1 = __float2bfloat16(v.y);
    __nv_bfloat16 h2 = __float2bfloat16(v.z);
    __nv_bfloat16 h3 = __float2bfloat16(v.w);
    __nv_bfloat16 l0 = __float2bfloat16(v.x - __bfloat162float(h0));
    __nv_bfloat16 l1 = __float2bfloat16(v.y - __bfloat162float(h1));
    __nv_bfloat16 l2 = __float2bfloat16(v.z - __bfloat162float(h2));
    __nv_bfloat16 l3 = __float2bfloat16(v.w - __bfloat162float(h3));
    *(__nv_bfloat162*)(hi + 4 * (size_t)i4)     = __halves2bfloat162(h0, h1);
    *(__nv_bfloat162*)(hi + 4 * (size_t)i4 + 2) = __halves2bfloat162(h2, h3);
    *(__nv_bfloat162*)(lo + 4 * (size_t)i4)     = __halves2bfloat162(l0, l1);
    *(__nv_bfloat162*)(lo + 4 * (size_t)i4 + 2) = __halves2bfloat162(l2, l3);
}

// transpose W [k][n] -> W^T [n][k] with hi/lo split, per-weight (blockIdx.z)
__global__ __launch_bounds__(256) void split_wt_kernel(
    const float* __restrict__ Wq, const float* __restrict__ Wk,
    const float* __restrict__ Wv, const float* __restrict__ Wo1,
    __nv_bfloat16* __restrict__ wthi, __nv_bfloat16* __restrict__ wtlo)
{
    const int z = blockIdx.z;
    const float* W = (z == 0) ? Wq : (z == 1) ? Wk : (z == 2) ? Wv : Wo1;
    __shared__ float ts[32][33];
    const int n0 = blockIdx.x * 32;
    const int k0 = blockIdx.y * 32;
    const int tx = threadIdx.x, ty = threadIdx.y;   // 32 x 8
#pragma unroll
    for (int i = 0; i < 4; i++)
        ts[ty + 8 * i][tx] = W[(size_t)(k0 + ty + 8 * i) * EMB + n0 + tx];
    __syncthreads();
    __nv_bfloat16* oh = wthi + (size_t)z * EMB * EMB;
    __nv_bfloat16* ol = wtlo + (size_t)z * EMB * EMB;
#pragma unroll
    for (int i = 0; i < 4; i++) {
        const int n = n0 + ty + 8 * i;
        float v = ts[tx][ty + 8 * i];          // = W[k0+tx][n]
        __nv_bfloat16 h = __float2bfloat16(v);
        __nv_bfloat16 l = __float2bfloat16(v - __bfloat162float(h));
        oh[(size_t)n * EMB + k0 + tx] = h;
        ol[(size_t)n * EMB + k0 + tx] = l;
    }
}

// =================== HMMA projection GEMM (bf16x3 split) =====================
// C[128x128] = X[128x1024] @ W[1024x128] + b  via  hi*hi + hi*lo + lo*hi.
// z in {0,1,2}: output fp16 hi/lo pair (q/k/v); z==3: fp32 + relu (h).
#define PSTRIDE 40                       // bf16 per smem row (32 + 8 pad = 80B)
#define TILE_BYTES (128 * PSTRIDE * 2)   // 10240
#define STAGE_BYTES (4 * TILE_BYTES)     // 40960 (Ah, Al, Bh, Bl)
#define PROJ_SMEM_BYTES (2 * STAGE_BYTES)

__global__ __launch_bounds__(256, 1) void proj_mma_kernel(
    const __nv_bfloat16* __restrict__ xhi, const __nv_bfloat16* __restrict__ xlo,
    const __nv_bfloat16* __restrict__ wthi, const __nv_bfloat16* __restrict__ wtlo,
    const float* __restrict__ bq, const float* __restrict__ bk,
    const float* __restrict__ bv, const float* __restrict__ bo1)
{
    extern __shared__ char smem[];
    const uint32_t sbase = smem_u32(smem);

    const int z = blockIdx.z;
    const float* bias = (z == 0) ? bq : (z == 1) ? bk : (z == 2) ? bv : bo1;
    __half* Ch = (z == 0) ? g_qh : (z == 1) ? g_kh : (z == 2) ? g_vh : nullptr;
    __half* Cl = (z == 0) ? g_ql : (z == 1) ? g_kl : (z == 2) ? g_vl : nullptr;

    const int tid = threadIdx.x;
    const int wid = tid >> 5;
    const int lane = tid & 31;
    const int wr = wid >> 2;          // warp row (0/1): rows wr*64
    const int wc = wid & 3;           // warp col (0..3): cols wc*32
    const int m0 = blockIdx.y * 128;
    const int n0 = blockIdx.x * 128;

    const __nv_bfloat16* Ah = xhi + (size_t)m0 * EMB;
    const __nv_bfloat16* Al = xlo + (size_t)m0 * EMB;
    const __nv_bfloat16* Bh = wthi + (size_t)z * EMB * EMB + (size_t)n0 * EMB;
    const __nv_bfloat16* Bl = wtlo + (size_t)z * EMB * EMB + (size_t)n0 * EMB;

    auto load_stage = [&](int s, int kc) {
        const __nv_bfloat16* srcs[4] = { Ah + kc * 32, Al + kc * 32,
                                         Bh + kc * 32, Bl + kc * 32 };
        const uint32_t dbase = sbase + (uint32_t)s * STAGE_BYTES;
#pragma unroll
        for (int t = 0; t < 8; t++) {
            const int idx = tid + t * 256;
            const int tile = idx >> 9;
            const int w = idx & 511;
            const int row = w >> 2;
            const int c16 = w & 3;
            const uint32_t dst = dbase + tile * TILE_BYTES + row * (PSTRIDE * 2) + c16 * 16;
            const void* src = srcs[tile] + (size_t)row * EMB + c16 * 8;
            CP_ASYNC16(dst, src);
        }
    };

    float acc[4][4][4];
#pragma unroll
    for (int mi = 0; mi < 4; mi++)
#pragma unroll
        for (int nj = 0; nj < 4; nj++)
#pragma unroll
            for (int e = 0; e < 4; e++) acc[mi][nj][e] = 0.0f;

    const int arow = lane & 15;
    const int ahalf = lane >> 4;
    const int brow = (lane & 7) + ((lane >> 4) << 3);
    const int bkoff = ((lane >> 3) & 1) * 16;

    load_stage(0, 0);
    CP_COMMIT();

    const int NCH = EMB / 32;    // 32
    for (int kc = 0; kc < NCH; kc++) {
        const int s = kc & 1;
        if (kc + 1 < NCH) {
            load_stage(s ^ 1, kc + 1);
            CP_COMMIT();
            CP_WAIT(1);
        } else {
            CP_WAIT(0);
        }
        __syncthreads();

        const uint32_t st = sbase + (uint32_t)s * STAGE_BYTES;
#pragma unroll
        for (int k16 = 0; k16 < 2; k16++) {
            uint32_t ah[4][4], al[4][4], bh[4][2], bl[4][2];
#pragma unroll
            for (int mi = 0; mi < 4; mi++) {
                const uint32_t ra = (uint32_t)(wr * 64 + mi * 16 + arow) * (PSTRIDE * 2)
                                    + k16 * 32 + ahalf * 16;
                ldsm_x4(ah[mi], st + 0 * TILE_BYTES + ra);
                ldsm_x4(al[mi], st + 1 * TILE_BYTES + ra);
            }
#pragma unroll
            for (int p = 0; p < 2; p++) {
                const uint32_t rb = (uint32_t)(wc * 32 + p * 16 + brow) * (PSTRIDE * 2)
                                    + k16 * 32 + bkoff;
                uint32_t tmp[4];
                ldsm_x4(tmp, st + 2 * TILE_BYTES + rb);
                bh[2 * p][0] = tmp[0]; bh[2 * p][1] = tmp[1];
                bh[2 * p + 1][0] = tmp[2]; bh[2 * p + 1][1] = tmp[3];
                ldsm_x4(tmp, st + 3 * TILE_BYTES + rb);
                bl[2 * p][0] = tmp[0]; bl[2 * p][1] = tmp[1];
                bl[2 * p + 1][0] = tmp[2]; bl[2 * p + 1][1] = tmp[3];
            }
#pragma unroll
            for (int mi = 0; mi < 4; mi++)
#pragma unroll
                for (int nj = 0; nj < 4; nj++) {
                    mma16816(acc[mi][nj], ah[mi], bh[nj]);
                    mma16816(acc[mi][nj], ah[mi], bl[nj]);
                    mma16816(acc[mi][nj], al[mi], bh[nj]);
                }
        }
        __syncthreads();
    }

    // epilogue
    const int erow = lane >> 2;
    const int ecol = (lane & 3) * 2;
#pragma unroll
    for (int mi = 0; mi < 4; mi++) {
#pragma unroll
        for (int nj = 0; nj < 4; nj++) {
            const int row = m0 + wr * 64 + mi * 16 + erow;
            const int col = n0 + wc * 32 + nj * 8 + ecol;
            const float b0 = bias[col], b1 = bias[col + 1];
            float v00 = acc[mi][nj][0] + b0, v01 = acc[mi][nj][1] + b1;
            float v10 = acc[mi][nj][2] + b0, v11 = acc[mi][nj][3] + b1;
            if (z == 3) {
                float2 r0 = { fmaxf(v00, 0.0f), fmaxf(v01, 0.0f) };
                float2 r1 = { fmaxf(v10, 0.0f), fmaxf(v11, 0.0f) };
                *(float2*)(g_h + (size_t)row * EMB + col) = r0;
                *(float2*)(g_h + (size_t)(row + 8) * EMB + col) = r1;
            } else {
                __half h00 = __float2half_rn(v00), h01 = __float2half_rn(v01);
                __half h10 = __float2half_rn(v10), h11 = __float2half_rn(v11);
                *(uint32_t*)(Ch + (size_t)row * EMB + col) = pack_h2(v00, v01);
                *(uint32_t*)(Ch + (size_t)(row + 8) * EMB + col) = pack_h2(v10, v11);
                *(uint32_t*)(Cl + (size_t)row * EMB + col) =
                    pack_h2(v00 - __half2float(h00), v01 - __half2float(h01));
                *(uint32_t*)(Cl + (size_t)(row + 8) * EMB + col) =
                    pack_h2(v10 - __half2float(h10), v11 - __half2float(h11));
            }
        }
    }
}

// ------------- order-weight head: o = relu_h @ Wo2 + bo2 (N=4) ---------------
__global__ __launch_bounds__(256) void owt_kernel(
    const float* __restrict__ h, const float* __restrict__ Wo2,
    const float* __restrict__ bo2, float* __restrict__ o)
{
    const int warp = (blockIdx.x * blockDim.x + threadIdx.x) >> 5;
    const int lane = threadIdx.x & 31;
    if (warp >= MTOT) return;
    const float* hr = h + (size_t)warp * EMB;
    float a0 = 0.f, a1 = 0.f, a2 = 0.f, a3 = 0.f;
#pragma unroll 4
    for (int k = lane; k < EMB; k += 32) {
        float hv = hr[k];
        float4 w = *(const float4*)(Wo2 + (size_t)k * 4);
        a0 = fmaf(hv, w.x, a0);
        a1 = fmaf(hv, w.y, a1);
        a2 = fmaf(hv, w.z, a2);
        a3 = fmaf(hv, w.w, a3);
    }
#pragma unroll
    for (int m = 16; m > 0; m >>= 1) {
        a0 += __shfl_xor_sync(0xffffffffu, a0, m);
        a1 += __shfl_xor_sync(0xffffffffu, a1, m);
        a2 += __shfl_xor_sync(0xffffffffu, a2, m);
        a3 += __shfl_xor_sync(0xffffffffu, a3, m);
    }
    if (lane == 0) {
        o[warp * 4 + 0] = a0 + bo2[0];
        o[warp * 4 + 1] = a1 + bo2[1];
        o[warp * 4 + 2] = a2 + bo2[2];
        o[warp * 4 + 3] = a3 + bo2[3];
    }
}

// =================== HMMA flash attention (fp16x3 split) =====================
// CTA: 128 queries x 1 head. K/V tiles of 64. 8 warps x 16 rows.
// S = (Qh+Ql)(Kh+Kl)^T ~ 3 passes; P kept in registers as fp16 hi/lo A-frags;
// O += (Ph+Pl)(Vh+Vl) ~ 3 passes with ldmatrix.trans V.
#define ASTR 144                          // smem row stride bytes (72 halfs)
#define QBUF (128 * ASTR)                 // 18432
#define KVBUF (64 * ASTR)                 // 9216
#define ATT_STAGE (4 * KVBUF)             // 36864 (Kh,Kl,Vh,Vl)
#define ATT_SMEM_BYTES (2 * QBUF + 2 * ATT_STAGE)   // 110592

__global__ __launch_bounds__(256, 1) void attn_mma_kernel(float* __restrict__ O)
{
    extern __shared__ char smem[];
    const uint32_t sb = smem_u32(smem);
    const uint32_t sQH = sb, sQL = sb + QBUF, sST = sb + 2 * QBUF;

    const int qt = blockIdx.x;     // 0..15
    const int hd = blockIdx.y;     // 0..15
    const int b  = blockIdx.z;     // 0..1
    const int q0 = qt * 128;
    const int tid = threadIdx.x;
    const int wid = tid >> 5;
    const int lane = tid & 31;
    const size_t tok0 = (size_t)b * SEQ;
    const size_t hoff = (size_t)hd * DHEAD;

    const __half* Qh = g_qh + (tok0 + q0) * EMB + hoff;
    const __half* Ql = g_ql + (tok0 + q0) * EMB + hoff;
    const __half* Kh = g_kh + tok0 * EMB + hoff;
    const __half* Kl = g_kl + tok0 * EMB + hoff;
    const __half* Vh = g_vh + tok0 * EMB + hoff;
    const __half* Vl = g_vl + tok0 * EMB + hoff;

    // ---- Q load (own commit group) ----
#pragma unroll
    for (int t = 0; t < 8; t++) {
        const int idx = tid + t * 256;     // 0..2047
        const int arr = idx >> 10;         // 0: hi, 1: lo
        const int w = idx & 1023;
        const int row = w >> 3;
        const int c = w & 7;
        const uint32_t dst = (arr ? sQL : sQH) + row * ASTR + c * 16;
        const void* src = (arr ? Ql : Qh) + (size_t)row * EMB + c * 8;
        CP_ASYNC16(dst, src);
    }
    CP_COMMIT();

    auto load_stage = [&](int s, int kt) {
        const int k0 = kt * 64;
        const __half* srcs[4] = { Kh, Kl, Vh, Vl };
        const uint32_t dbase = sST + (uint32_t)s * ATT_STAGE;
#pragma unroll
        for (int t = 0; t < 8; t++) {
            const int idx = tid + t * 256;   // 0..2047
            const int arr = idx >> 9;
            const int w = idx & 511;
            const int row = w >> 3;
            const int c = w & 7;
            const uint32_t dst = dbase + arr * KVBUF + row * ASTR + c * 16;
            const void* src = srcs[arr] + (size_t)(k0 + row) * EMB + c * 8;
            CP_ASYNC16(dst, src);
        }
    };

    load_stage(0, 0);
    CP_COMMIT();
    CP_WAIT(1);                    // Q group done
    __syncthreads();

    // ---- Q fragments (resident all mainloop) ----
    uint32_t aqh[4][4], aql[4][4];
    {
        const uint32_t qrow = (uint32_t)(wid * 16 + (lane & 15));
#pragma unroll
        for (int ks = 0; ks < 4; ks++) {
            const uint32_t off = qrow * ASTR + ks * 32 + (lane >> 4) * 16;
            ldsm_x4(aqh[ks], sQH + off);
            ldsm_x4(aql[ks], sQL + off);
        }
    }

    float m0 = -CUDART_INF_F, m1 = -CUDART_INF_F, l0 = 0.f, l1 = 0.f;
    float oacc[8][4];
#pragma unroll
    for (int nt = 0; nt < 8; nt++)
#pragma unroll
        for (int e = 0; e < 4; e++) oacc[nt][e] = 0.f;

    // ldmatrix address components
    const uint32_t kbrow = (uint32_t)((lane & 7) + ((lane >> 4) << 3));
    const uint32_t kboff = (uint32_t)(((lane >> 3) & 1) << 4);
    const uint32_t vbrow = (uint32_t)((lane & 7) + (((lane >> 3) & 1) << 3));
    const uint32_t vboff = (uint32_t)((lane >> 4) << 4);

    const int NT = SEQ / 64;   // 32
    for (int kt = 0; kt < NT; kt++) {
        const int s = kt & 1;
        if (kt + 1 < NT) {
            load_stage(s ^ 1, kt + 1);
            CP_COMMIT();
            CP_WAIT(1);
        } else {
            CP_WAIT(0);
        }
        __syncthreads();

        const uint32_t st = sST + (uint32_t)s * ATT_STAGE;

        // ---- S = Q K^T (3 split passes) ----
        float sacc[8][4];
#pragma unroll
        for (int nt = 0; nt < 8; nt++)
#pragma unroll
            for (int e = 0; e < 4; e++) sacc[nt][e] = 0.f;

#pragma unroll
        for (int ks = 0; ks < 4; ks++) {
#pragma unroll
            for (int p = 0; p < 4; p++) {
                const uint32_t boff = (p * 16 + kbrow) * ASTR + ks * 32 + kboff;
                uint32_t th[4], tl[4];
                ldsm_x4(th, st + 0 * KVBUF + boff);
                ldsm_x4(tl, st + 1 * KVBUF + boff);
                mma16816h(sacc[2 * p],     aqh[ks], th);
                mma16816h(sacc[2 * p + 1], aqh[ks], th + 2);
                mma16816h(sacc[2 * p],     aqh[ks], tl);
                mma16816h(sacc[2 * p + 1], aqh[ks], tl + 2);
                mma16816h(sacc[2 * p],     aql[ks], th);
                mma16816h(sacc[2 * p + 1], aql[ks], th + 2);
            }
        }

        // ---- online softmax (quad reductions) ----
        float tmax0 = -CUDART_INF_F, tmax1 = -CUDART_INF_F;
#pragma unroll
        for (int nt = 0; nt < 8; nt++) {
            tmax0 = fmaxf(tmax0, fmaxf(sacc[nt][0], sacc[nt][1]));
            tmax1 = fmaxf(tmax1, fmaxf(sacc[nt][2], sacc[nt][3]));
        }
#pragma unroll
        for (int m = 1; m < 4; m <<= 1) {
            tmax0 = fmaxf(tmax0, __shfl_xor_sync(0xffffffffu, tmax0, m));
            tmax1 = fmaxf(tmax1, __shfl_xor_sync(0xffffffffu, tmax1, m));
        }
        const float mnew0 = fmaxf(m0, tmax0);
        const float mnew1 = fmaxf(m1, tmax1);
        const float sc0 = __expf(m0 - mnew0);
        const float sc1 = __expf(m1 - mnew1);

        uint32_t ph[8][2], pl[8][2];
        float sum0 = 0.f, sum1 = 0.f;
#pragma unroll
        for (int nt = 0; nt < 8; nt++) {
            float p00 = __expf(sacc[nt][0] - mnew0);
            float p01 = __expf(sacc[nt][1] - mnew0);
            float p10 = __expf(sacc[nt][2] - mnew1);
            float p11 = __expf(sacc[nt][3] - mnew1);
            sum0 += p00 + p01;
            sum1 += p10 + p11;
            __half h00 = __float2half_rn(p00), h01 = __float2half_rn(p01);
            __half h10 = __float2half_rn(p10), h11 = __float2half_rn(p11);
            __half2 hv0 = __halves2half2(h00, h01);
            __half2 hv1 = __halves2half2(h10, h11);
            ph[nt][0] = *reinterpret_cast<uint32_t*>(&hv0);
            ph[nt][1] = *reinterpret_cast<uint32_t*>(&hv1);
            pl[nt][0] = pack_h2(p00 - __half2float(h00), p01 - __half2float(h01));
            pl[nt][1] = pack_h2(p10 - __half2float(h10), p11 - __half2float(h11));
        }
#pragma unroll
        for (int m = 1; m < 4; m <<= 1) {
            sum0 += __shfl_xor_sync(0xffffffffu, sum0, m);
            sum1 += __shfl_xor_sync(0xffffffffu, sum1, m);
        }
        l0 = l0 * sc0 + sum0;
        l1 = l1 * sc1 + sum1;
        m0 = mnew0;
        m1 = mnew1;
#pragma unroll
        for (int nt = 0; nt < 8; nt++) {
            oacc[nt][0] *= sc0; oacc[nt][1] *= sc0;
            oacc[nt][2] *= sc1; oacc[nt][3] *= sc1;
        }

        // ---- O += P V (3 split passes, V via ldmatrix.trans) ----
#pragma unroll
        for (int ks = 0; ks < 4; ks++) {
            uint32_t Ah_[4] = { ph[2 * ks][0], ph[2 * ks][1],
                                ph[2 * ks + 1][0], ph[2 * ks + 1][1] };
            uint32_t Al_[4] = { pl[2 * ks][0], pl[2 * ks][1],
                                pl[2 * ks + 1][0], pl[2 * ks + 1][1] };
#pragma unroll
            for (int p = 0; p < 4; p++) {
                const uint32_t voff = (ks * 16 + vbrow) * ASTR + p * 32 + vboff;
                uint32_t th[4], tl[4];
                ldsm_x4_t(th, st + 2 * KVBUF + voff);
                ldsm_x4_t(tl, st + 3 * KVBUF + voff);
                mma16816h(oacc[2 * p],     Ah_, th);
                mma16816h(oacc[2 * p + 1], Ah_, th + 2);
                mma16816h(oacc[2 * p],     Ah_, tl);
                mma16816h(oacc[2 * p + 1], Ah_, tl + 2);
                mma16816h(oacc[2 * p],     Al_, th);
                mma16816h(oacc[2 * p + 1], Al_, th + 2);
            }
        }
        __syncthreads();
    }

    // ---- epilogue: normalize + store fp32 ----
    const float inv0 = 1.0f / l0;
    const float inv1 = 1.0f / l1;
    const int r0 = q0 + wid * 16 + (lane >> 2);
    const int r1 = r0 + 8;
#pragma unroll
    for (int nt = 0; nt < 8; nt++) {
        const int col = (int)hoff + nt * 8 + (lane & 3) * 2;
        float2 w0 = { oacc[nt][0] * inv0, oacc[nt][1] * inv0 };
        float2 w1 = { oacc[nt][2] * inv1, oacc[nt][3] * inv1 };
        *(float2*)(O + (tok0 + r0) * EMB + col) = w0;
        *(float2*)(O + (tok0 + r1) * EMB + col) = w1;
    }
}

// ------------- polynomial order-weighted mixing (elementwise) ----------------
__global__ __launch_bounds__(256) void mix_kernel(
    const float* __restrict__ org, const float* __restrict__ o,
    float* __restrict__ out)
{
    const int idx = blockIdx.x * blockDim.x + threadIdx.x;
    if (idx >= MTOT * EMB / 4) return;
    const int m = idx >> 8;
    float4 g = ((const float4*)org)[idx];
    float4 w = ((const float4*)o)[m];
    float4 r;
    r.x = g.x * fmaf(g.x, fmaf(g.x, fmaf(g.x, w.w, w.z), w.y), w.x);
    r.y = g.y * fmaf(g.y, fmaf(g.y, fmaf(g.y, w.w, w.z), w.y), w.x);
    r.z = g.z * fmaf(g.z, fmaf(g.z, fmaf(g.z, w.w, w.z), w.y), w.x);
    r.w = g.w * fmaf(g.w, fmaf(g.w, fmaf(g.w, w.w, w.z), w.y), w.x);
    ((float4*)out)[idx] = r;
}

// ------------------------------ launch -------------------------------------
extern "C" void kernel_launch(void* const* d_in, const int* in_sizes, int n_in,
                              void* d_out, int out_size)
{
    const float* x   = (const float*)d_in[0];
    const float* Wq  = (const float*)d_in[1];
    const float* bq  = (const float*)d_in[2];
    const float* Wk  = (const float*)d_in[3];
    const float* bk  = (const float*)d_in[4];
    const float* Wv  = (const float*)d_in[5];
    const float* bv  = (const float*)d_in[6];
    const float* Wo1 = (const float*)d_in[7];
    const float* bo1 = (const float*)d_in[8];
    const float* Wo2 = (const float*)d_in[9];
    const float* bo2 = (const float*)d_in[10];
    float* out = (float*)d_out;

    float *h, *org, *o;
    __nv_bfloat16 *xhi, *xlo, *wthi, *wtlo;
    cudaGetSymbolAddress((void**)&h, g_h);
    cudaGetSymbolAddress((void**)&org, g_org);
    cudaGetSymbolAddress((void**)&o, g_o);
    cudaGetSymbolAddress((void**)&xhi, g_xhi);
    cudaGetSymbolAddress((void**)&xlo, g_xlo);
    cudaGetSymbolAddress((void**)&wthi, g_wthi);
    cudaGetSymbolAddress((void**)&wtlo, g_wtlo);

    cudaFuncSetAttribute(proj_mma_kernel,
                         cudaFuncAttributeMaxDynamicSharedMemorySize, PROJ_SMEM_BYTES);
    cudaFuncSetAttribute(attn_mma_kernel,
                         cudaFuncAttributeMaxDynamicSharedMemorySize, ATT_SMEM_BYTES);

    // 1) split x and W^T into bf16 hi/lo
    const int nv4 = MTOT * EMB / 4;
    split_x_kernel<<<(nv4 + 255) / 256, 256>>>(x, xhi, xlo);
    split_wt_kernel<<<dim3(EMB / 32, EMB / 32, 4), dim3(32, 8)>>>(
        Wq, Wk, Wv, Wo1, wthi, wtlo);

    // 2) HMMA projections: q,k,v as fp16 hi/lo; h as fp32+relu
    proj_mma_kernel<<<dim3(EMB / 128, MTOT / 128, 4), 256, PROJ_SMEM_BYTES>>>(
        xhi, xlo, wthi, wtlo, bq, bk, bv, bo1);

    // 3) order weights o = h @ Wo2 + bo2
    owt_kernel<<<(MTOT * 32 + 255) / 256, 256>>>(h, Wo2, bo2, o);

    // 4) HMMA flash attention -> org
    attn_mma_kernel<<<dim3(SEQ / 128, HEADS, BATCH), 256, ATT_SMEM_BYTES>>>(org);

    // 5) polynomial mixing -> out
    mix_kernel<<<(nv4 + 255) / 256, 256>>>(org, o, out);
}

// round 5
// speedup vs baseline: 2.6012x; 1.0001x over previous
#include <cuda_runtime.h>
#include <cuda_bf16.h>
#include <cuda_fp16.h>
#include <cstdint>
#include <math_constants.h>

// Problem constants
#define BATCH 2
#define SEQ   2048
#define EMB   1024
#define HEADS 16
#define DHEAD 64
#define MTOT  (BATCH*SEQ)      // 4096
#define NORD  4

// ---------------- scratch (device globals; no cudaMalloc allowed) ------------
__device__ float g_h[MTOT * EMB];     // relu(x@Wo1 + bo1)
__device__ float g_org[MTOT * EMB];   // attention output (pre-mixing)
__device__ float g_o[MTOT * NORD];    // order weights

// fp16 hi/lo split q,k,v (written by proj epilogue, consumed by attention)
__device__ __align__(16) __half g_qh[MTOT * EMB];
__device__ __align__(16) __half g_ql[MTOT * EMB];
__device__ __align__(16) __half g_kh[MTOT * EMB];
__device__ __align__(16) __half g_kl[MTOT * EMB];
__device__ __align__(16) __half g_vh[MTOT * EMB];
__device__ __align__(16) __half g_vl[MTOT * EMB];

// bf16 split operands for HMMA projection GEMMs
__device__ __align__(16) __nv_bfloat16 g_xhi[MTOT * EMB];
__device__ __align__(16) __nv_bfloat16 g_xlo[MTOT * EMB];
__device__ __align__(16) __nv_bfloat16 g_wthi[4 * EMB * EMB];  // W^T per weight, [n][k]
__device__ __align__(16) __nv_bfloat16 g_wtlo[4 * EMB * EMB];

// ======================= PTX helpers (arch-portable) =========================
__device__ __forceinline__ uint32_t smem_u32(const void* p) {
    uint32_t a;
    asm("{ .reg .u64 t; cvta.to.shared.u64 t, %1; cvt.u32.u64 %0, t; }"
        : "=r"(a) : "l"(p));
    return a;
}

#define CP_ASYNC16(dst, src) \
    asm volatile("cp.async.cg.shared.global [%0], [%1], 16;" :: "r"(dst), "l"(src))
#define CP_COMMIT() asm volatile("cp.async.commit_group;" ::: "memory")
#define CP_WAIT(n)  asm volatile("cp.async.wait_group %0;" :: "n"(n) : "memory")

__device__ __forceinline__ void ldsm_x4(uint32_t* r, uint32_t addr) {
    asm volatile("ldmatrix.sync.aligned.m8n8.x4.shared.b16 {%0,%1,%2,%3}, [%4];"
        : "=r"(r[0]), "=r"(r[1]), "=r"(r[2]), "=r"(r[3]) : "r"(addr));
}
__device__ __forceinline__ void ldsm_x4_t(uint32_t* r, uint32_t addr) {
    asm volatile("ldmatrix.sync.aligned.m8n8.x4.trans.shared.b16 {%0,%1,%2,%3}, [%4];"
        : "=r"(r[0]), "=r"(r[1]), "=r"(r[2]), "=r"(r[3]) : "r"(addr));
}

// D(f32) += A(bf16) * B(bf16), m16n8k16
__device__ __forceinline__ void mma16816(float* c, const uint32_t* a, const uint32_t* b) {
    asm volatile(
        "mma.sync.aligned.m16n8k16.row.col.f32.bf16.bf16.f32 "
        "{%0,%1,%2,%3}, {%4,%5,%6,%7}, {%8,%9}, {%0,%1,%2,%3};"
        : "+f"(c[0]), "+f"(c[1]), "+f"(c[2]), "+f"(c[3])
        : "r"(a[0]), "r"(a[1]), "r"(a[2]), "r"(a[3]), "r"(b[0]), "r"(b[1]));
}
// D(f32) += A(f16) * B(f16), m16n8k16
__device__ __forceinline__ void mma16816h(float* c, const uint32_t* a, const uint32_t* b) {
    asm volatile(
        "mma.sync.aligned.m16n8k16.row.col.f32.f16.f16.f32 "
        "{%0,%1,%2,%3}, {%4,%5,%6,%7}, {%8,%9}, {%0,%1,%2,%3};"
        : "+f"(c[0]), "+f"(c[1]), "+f"(c[2]), "+f"(c[3])
        : "r"(a[0]), "r"(a[1]), "r"(a[2]), "r"(a[3]), "r"(b[0]), "r"(b[1]));
}

__device__ __forceinline__ uint32_t pack_h2(float a, float b) {
    __half2 h = __floats2half2_rn(a, b);
    return *reinterpret_cast<uint32_t*>(&h);
}

// ====================== split / transpose prep kernels =======================
__global__ __launch_bounds__(256) void split_x_kernel(
    const float* __restrict__ x, __nv_bfloat16* __restrict__ hi,
    __nv_bfloat16* __restrict__ lo)
{
    const int i4 = blockIdx.x * blockDim.x + threadIdx.x;
    if (i4 >= MTOT * EMB / 4) return;
    float4 v = ((const float4*)x)[i4];
    __nv_bfloat16 h0 = __float2bfloat16(v.x);
    __nv_bfloat16 h1 = __float2bfloat16(v.y);
    __nv_bfloat16 h2 = __float2bfloat16(v.z);
    __nv_bfloat16 h3 = __float2bfloat16(v.w);
    __nv_bfloat16 l0 = __float2bfloat16(v.x - __bfloat162float(h0));
    __nv_bfloat16 l1 = __float2bfloat16(v.y - __bfloat162float(h1));
    __nv_bfloat16 l2 = __float2bfloat16(v.z - __bfloat162float(h2));
    __nv_bfloat16 l3 = __float2bfloat16(v.w - __bfloat162float(h3));
    *(__nv_bfloat162*)(hi + 4 * (size_t)i4)     = __halves2bfloat162(h0, h1);
    *(__nv_bfloat162*)(hi + 4 * (size_t)i4 + 2) = __halves2bfloat162(h2, h3);
    *(__nv_bfloat162*)(lo + 4 * (size_t)i4)     = __halves2bfloat162(l0, l1);
    *(__nv_bfloat162*)(lo + 4 * (size_t)i4 + 2) = __halves2bfloat162(l2, l3);
}

// transpose W [k][n] -> W^T [n][k] with hi/lo split, per-weight (blockIdx.z)
__global__ __launch_bounds__(256) void split_wt_kernel(
    const float* __restrict__ Wq, const float* __restrict__ Wk,
    const float* __restrict__ Wv, const float* __restrict__ Wo1,
    __nv_bfloat16* __restrict__ wthi, __nv_bfloat16* __restrict__ wtlo)
{
    const int z = blockIdx.z;
    const float* W = (z == 0) ? Wq : (z == 1) ? Wk : (z == 2) ? Wv : Wo1;
    __shared__ float ts[32][33];
    const int n0 = blockIdx.x * 32;
    const int k0 = blockIdx.y * 32;
    const int tx = threadIdx.x, ty = threadIdx.y;   // 32 x 8
#pragma unroll
    for (int i = 0; i < 4; i++)
        ts[ty + 8 * i][tx] = W[(size_t)(k0 + ty + 8 * i) * EMB + n0 + tx];
    __syncthreads();
    __nv_bfloat16* oh = wthi + (size_t)z * EMB * EMB;
    __nv_bfloat16* ol = wtlo + (size_t)z * EMB * EMB;
#pragma unroll
    for (int i = 0; i < 4; i++) {
        const int n = n0 + ty + 8 * i;
        float v = ts[tx][ty + 8 * i];          // = W[k0+tx][n]
        __nv_bfloat16 h = __float2bfloat16(v);
        __nv_bfloat16 l = __float2bfloat16(v - __bfloat162float(h));
        oh[(size_t)n * EMB + k0 + tx] = h;
        ol[(size_t)n * EMB + k0 + tx] = l;
    }
}

// =================== HMMA projection GEMM (bf16x3 split) =====================
// C[256x128] tile = X[256x1024] @ W[1024x128] + b  via  hi*hi + hi*lo + lo*hi.
// 8 warps, each 64x64. BK=32. 3-stage cp.async ring. MMA:LDSM = 6:1.
// smem stage rows: [0,256) Ah | [256,512) Al | [512,640) Bh | [640,768) Bl
#define PROW 80                           // bytes per smem row (64 + 16 pad)
#define STAGE_BYTES (768 * PROW)          // 61440
#define PROJ_SMEM_BYTES (3 * STAGE_BYTES) // 184320

__global__ __launch_bounds__(256, 1) void proj_mma_kernel(
    const __nv_bfloat16* __restrict__ xhi, const __nv_bfloat16* __restrict__ xlo,
    const __nv_bfloat16* __restrict__ wthi, const __nv_bfloat16* __restrict__ wtlo,
    const float* __restrict__ bq, const float* __restrict__ bk,
    const float* __restrict__ bv, const float* __restrict__ bo1)
{
    extern __shared__ char smem[];
    const uint32_t sbase = smem_u32(smem);

    const int z = blockIdx.z;
    const float* bias = (z == 0) ? bq : (z == 1) ? bk : (z == 2) ? bv : bo1;
    __half* Ch = (z == 0) ? g_qh : (z == 1) ? g_kh : (z == 2) ? g_vh : nullptr;
    __half* Cl = (z == 0) ? g_ql : (z == 1) ? g_kl : (z == 2) ? g_vl : nullptr;

    const int tid = threadIdx.x;
    const int wid = tid >> 5;
    const int lane = tid & 31;
    const int wr = wid >> 1;          // warp row (0..3): rows wr*64
    const int wc = wid & 1;           // warp col (0..1): cols wc*64
    const int m0 = blockIdx.y * 256;
    const int n0 = blockIdx.x * 128;

    const __nv_bfloat16* Ah = xhi + (size_t)m0 * EMB;
    const __nv_bfloat16* Al = xlo + (size_t)m0 * EMB;
    const __nv_bfloat16* Bh = wthi + (size_t)z * EMB * EMB + (size_t)n0 * EMB;
    const __nv_bfloat16* Bl = wtlo + (size_t)z * EMB * EMB + (size_t)n0 * EMB;

    // stage loader: 3072 x 16B chunks; each unrolled t covers one operand region
    auto load_stage = [&](int s, int kc) {
        const uint32_t dbase = sbase + (uint32_t)s * STAGE_BYTES;
        const int r64 = tid >> 2;          // 0..63
        const int c16 = tid & 3;           // 16B column
#pragma unroll
        for (int t = 0; t < 12; t++) {
            const int grow = t * 64 + r64;        // global smem row 0..767
            const __nv_bfloat16* src;
            if (t < 4)       src = Ah + (size_t)grow * EMB;
            else if (t < 8)  src = Al + (size_t)(grow - 256) * EMB;
            else if (t < 10) src = Bh + (size_t)(grow - 512) * EMB;
            else             src = Bl + (size_t)(grow - 640) * EMB;
            CP_ASYNC16(dbase + (uint32_t)grow * PROW + c16 * 16,
                       src + kc * 32 + c16 * 8);
        }
    };

    float acc[4][8][4];
#pragma unroll
    for (int mi = 0; mi < 4; mi++)
#pragma unroll
        for (int nj = 0; nj < 8; nj++)
#pragma unroll
            for (int e = 0; e < 4; e++) acc[mi][nj][e] = 0.0f;

    const int arow = lane & 15;
    const int ahalf = lane >> 4;
    const int brow = (lane & 7) + ((lane >> 4) << 3);
    const int bkoff = ((lane >> 3) & 1) * 16;

    load_stage(0, 0); CP_COMMIT();
    load_stage(1, 1); CP_COMMIT();

    const int NCH = EMB / 32;    // 32
    int s = 0, ps = 2;
    for (int kc = 0; kc < NCH; kc++) {
        if (kc + 1 < NCH) CP_WAIT(1); else CP_WAIT(0);
        __syncthreads();
        if (kc + 2 < NCH) {
            load_stage(ps, kc + 2);
            CP_COMMIT();
            if (++ps == 3) ps = 0;
        }

        const uint32_t st = sbase + (uint32_t)s * STAGE_BYTES;
        if (++s == 3) s = 0;
#pragma unroll
        for (int k16 = 0; k16 < 2; k16++) {
            uint32_t ah[4][4], al[4][4];
#pragma unroll
            for (int mi = 0; mi < 4; mi++) {
                const uint32_t ra = (uint32_t)(wr * 64 + mi * 16 + arow) * PROW
                                    + k16 * 32 + ahalf * 16;
                ldsm_x4(ah[mi], st + ra);
                ldsm_x4(al[mi], st + 256 * PROW + ra);
            }
#pragma unroll
            for (int p = 0; p < 4; p++) {
                const uint32_t rb = (uint32_t)(wc * 64 + p * 16 + brow) * PROW
                                    + k16 * 32 + bkoff;
                uint32_t th[4], tl[4];
                ldsm_x4(th, st + 512 * PROW + rb);
                ldsm_x4(tl, st + 640 * PROW + rb);
#pragma unroll
                for (int mi = 0; mi < 4; mi++) {
                    mma16816(acc[mi][2 * p],     ah[mi], th);
                    mma16816(acc[mi][2 * p + 1], ah[mi], th + 2);
                    mma16816(acc[mi][2 * p],     ah[mi], tl);
                    mma16816(acc[mi][2 * p + 1], ah[mi], tl + 2);
                    mma16816(acc[mi][2 * p],     al[mi], th);
                    mma16816(acc[mi][2 * p + 1], al[mi], th + 2);
                }
            }
        }
    }

    // epilogue
    const int erow = lane >> 2;
    const int ecol = (lane & 3) * 2;
#pragma unroll
    for (int mi = 0; mi < 4; mi++) {
#pragma unroll
        for (int nj = 0; nj < 8; nj++) {
            const int row = m0 + wr * 64 + mi * 16 + erow;
            const int col = n0 + wc * 64 + nj * 8 + ecol;
            const float b0 = bias[col], b1 = bias[col + 1];
            float v00 = acc[mi][nj][0] + b0, v01 = acc[mi][nj][1] + b1;
            float v10 = acc[mi][nj][2] + b0, v11 = acc[mi][nj][3] + b1;
            if (z == 3) {
                float2 r0 = { fmaxf(v00, 0.0f), fmaxf(v01, 0.0f) };
                float2 r1 = { fmaxf(v10, 0.0f), fmaxf(v11, 0.0f) };
                *(float2*)(g_h + (size_t)row * EMB + col) = r0;
                *(float2*)(g_h + (size_t)(row + 8) * EMB + col) = r1;
            } else {
                __half h00 = __float2half_rn(v00), h01 = __float2half_rn(v01);
                __half h10 = __float2half_rn(v10), h11 = __float2half_rn(v11);
                *(uint32_t*)(Ch + (size_t)row * EMB + col) = pack_h2(v00, v01);
                *(uint32_t*)(Ch + (size_t)(row + 8) * EMB + col) = pack_h2(v10, v11);
                *(uint32_t*)(Cl + (size_t)row * EMB + col) =
                    pack_h2(v00 - __half2float(h00), v01 - __half2float(h01));
                *(uint32_t*)(Cl + (size_t)(row + 8) * EMB + col) =
                    pack_h2(v10 - __half2float(h10), v11 - __half2float(h11));
            }
        }
    }
}

// ------------- order-weight head: o = relu_h @ Wo2 + bo2 (N=4) ---------------
__global__ __launch_bounds__(256) void owt_kernel(
    const float* __restrict__ h, const float* __restrict__ Wo2,
    const float* __restrict__ bo2, float* __restrict__ o)
{
    const int warp = (blockIdx.x * blockDim.x + threadIdx.x) >> 5;
    const int lane = threadIdx.x & 31;
    if (warp >= MTOT) return;
    const float* hr = h + (size_t)warp * EMB;
    float a0 = 0.f, a1 = 0.f, a2 = 0.f, a3 = 0.f;
#pragma unroll 4
    for (int k = lane; k < EMB; k += 32) {
        float hv = hr[k];
        float4 w = *(const float4*)(Wo2 + (size_t)k * 4);
        a0 = fmaf(hv, w.x, a0);
        a1 = fmaf(hv, w.y, a1);
        a2 = fmaf(hv, w.z, a2);
        a3 = fmaf(hv, w.w, a3);
    }
#pragma unroll
    for (int m = 16; m > 0; m >>= 1) {
        a0 += __shfl_xor_sync(0xffffffffu, a0, m);
        a1 += __shfl_xor_sync(0xffffffffu, a1, m);
        a2 += __shfl_xor_sync(0xffffffffu, a2, m);
        a3 += __shfl_xor_sync(0xffffffffu, a3, m);
    }
    if (lane == 0) {
        o[warp * 4 + 0] = a0 + bo2[0];
        o[warp * 4 + 1] = a1 + bo2[1];
        o[warp * 4 + 2] = a2 + bo2[2];
        o[warp * 4 + 3] = a3 + bo2[3];
    }
}

// =================== HMMA flash attention (fp16x3 split) =====================
// CTA: 128 queries x 1 head. K/V tiles of 64. 8 warps x 16 rows.
#define ASTR 144
#define QBUF (128 * ASTR)
#define KVBUF (64 * ASTR)
#define ATT_STAGE (4 * KVBUF)
#define ATT_SMEM_BYTES (2 * QBUF + 2 * ATT_STAGE)   // 110592

__global__ __launch_bounds__(256, 1) void attn_mma_kernel(float* __restrict__ O)
{
    extern __shared__ char smem[];
    const uint32_t sb = smem_u32(smem);
    const uint32_t sQH = sb, sQL = sb + QBUF, sST = sb + 2 * QBUF;

    const int qt = blockIdx.x;
    const int hd = blockIdx.y;
    const int b  = blockIdx.z;
    const int q0 = qt * 128;
    const int tid = threadIdx.x;
    const int wid = tid >> 5;
    const int lane = tid & 31;
    const size_t tok0 = (size_t)b * SEQ;
    const size_t hoff = (size_t)hd * DHEAD;

    const __half* Qh = g_qh + (tok0 + q0) * EMB + hoff;
    const __half* Ql = g_ql + (tok0 + q0) * EMB + hoff;
    const __half* Kh = g_kh + tok0 * EMB + hoff;
    const __half* Kl = g_kl + tok0 * EMB + hoff;
    const __half* Vh = g_vh + tok0 * EMB + hoff;
    const __half* Vl = g_vl + tok0 * EMB + hoff;

#pragma unroll
    for (int t = 0; t < 8; t++) {
        const int idx = tid + t * 256;
        const int arr = idx >> 10;
        const int w = idx & 1023;
        const int row = w >> 3;
        const int c = w & 7;
        const uint32_t dst = (arr ? sQL : sQH) + row * ASTR + c * 16;
        const void* src = (arr ? Ql : Qh) + (size_t)row * EMB + c * 8;
        CP_ASYNC16(dst, src);
    }
    CP_COMMIT();

    auto load_stage = [&](int s, int kt) {
        const int k0 = kt * 64;
        const __half* srcs[4] = { Kh, Kl, Vh, Vl };
        const uint32_t dbase = sST + (uint32_t)s * ATT_STAGE;
#pragma unroll
        for (int t = 0; t < 8; t++) {
            const int idx = tid + t * 256;
            const int arr = idx >> 9;
            const int w = idx & 511;
            const int row = w >> 3;
            const int c = w & 7;
            const uint32_t dst = dbase + arr * KVBUF + row * ASTR + c * 16;
            const void* src = srcs[arr] + (size_t)(k0 + row) * EMB + c * 8;
            CP_ASYNC16(dst, src);
        }
    };

    load_stage(0, 0);
    CP_COMMIT();
    CP_WAIT(1);
    __syncthreads();

    uint32_t aqh[4][4], aql[4][4];
    {
        const uint32_t qrow = (uint32_t)(wid * 16 + (lane & 15));
#pragma unroll
        for (int ks = 0; ks < 4; ks++) {
            const uint32_t off = qrow * ASTR + ks * 32 + (lane >> 4) * 16;
            ldsm_x4(aqh[ks], sQH + off);
            ldsm_x4(aql[ks], sQL + off);
        }
    }

    float m0 = -CUDART_INF_F, m1 = -CUDART_INF_F, l0 = 0.f, l1 = 0.f;
    float oacc[8][4];
#pragma unroll
    for (int nt = 0; nt < 8; nt++)
#pragma unroll
        for (int e = 0; e < 4; e++) oacc[nt][e] = 0.f;

    const uint32_t kbrow = (uint32_t)((lane & 7) + ((lane >> 4) << 3));
    const uint32_t kboff = (uint32_t)(((lane >> 3) & 1) << 4);
    const uint32_t vbrow = (uint32_t)((lane & 7) + (((lane >> 3) & 1) << 3));
    const uint32_t vboff = (uint32_t)((lane >> 4) << 4);

    const int NT = SEQ / 64;
    for (int kt = 0; kt < NT; kt++) {
        const int s = kt & 1;
        if (kt + 1 < NT) {
            load_stage(s ^ 1, kt + 1);
            CP_COMMIT();
            CP_WAIT(1);
        } else {
            CP_WAIT(0);
        }
        __syncthreads();

        const uint32_t st = sST + (uint32_t)s * ATT_STAGE;

        float sacc[8][4];
#pragma unroll
        for (int nt = 0; nt < 8; nt++)
#pragma unroll
            for (int e = 0; e < 4; e++) sacc[nt][e] = 0.f;

#pragma unroll
        for (int ks = 0; ks < 4; ks++) {
#pragma unroll
            for (int p = 0; p < 4; p++) {
                const uint32_t boff = (p * 16 + kbrow) * ASTR + ks * 32 + kboff;
                uint32_t th[4], tl[4];
                ldsm_x4(th, st + 0 * KVBUF + boff);
                ldsm_x4(tl, st + 1 * KVBUF + boff);
                mma16816h(sacc[2 * p],     aqh[ks], th);
                mma16816h(sacc[2 * p + 1], aqh[ks], th + 2);
                mma16816h(sacc[2 * p],     aqh[ks], tl);
                mma16816h(sacc[2 * p + 1], aqh[ks], tl + 2);
                mma16816h(sacc[2 * p],     aql[ks], th);
                mma16816h(sacc[2 * p + 1], aql[ks], th + 2);
            }
        }

        float tmax0 = -CUDART_INF_F, tmax1 = -CUDART_INF_F;
#pragma unroll
        for (int nt = 0; nt < 8; nt++) {
            tmax0 = fmaxf(tmax0, fmaxf(sacc[nt][0], sacc[nt][1]));
            tmax1 = fmaxf(tmax1, fmaxf(sacc[nt][2], sacc[nt][3]));
        }
#pragma unroll
        for (int m = 1; m < 4; m <<= 1) {
            tmax0 = fmaxf(tmax0, __shfl_xor_sync(0xffffffffu, tmax0, m));
            tmax1 = fmaxf(tmax1, __shfl_xor_sync(0xffffffffu, tmax1, m));
        }
        const float mnew0 = fmaxf(m0, tmax0);
        const float mnew1 = fmaxf(m1, tmax1);
        const float sc0 = __expf(m0 - mnew0);
        const float sc1 = __expf(m1 - mnew1);

        uint32_t ph[8][2], pl[8][2];
        float sum0 = 0.f, sum1 = 0.f;
#pragma unroll
        for (int nt = 0; nt < 8; nt++) {
            float p00 = __expf(sacc[nt][0] - mnew0);
            float p01 = __expf(sacc[nt][1] - mnew0);
            float p10 = __expf(sacc[nt][2] - mnew1);
            float p11 = __expf(sacc[nt][3] - mnew1);
            sum0 += p00 + p01;
            sum1 += p10 + p11;
            __half h00 = __float2half_rn(p00), h01 = __float2half_rn(p01);
            __half h10 = __float2half_rn(p10), h11 = __float2half_rn(p11);
            __half2 hv0 = __halves2half2(h00, h01);
            __half2 hv1 = __halves2half2(h10, h11);
            ph[nt][0] = *reinterpret_cast<uint32_t*>(&hv0);
            ph[nt][1] = *reinterpret_cast<uint32_t*>(&hv1);
            pl[nt][0] = pack_h2(p00 - __half2float(h00), p01 - __half2float(h01));
            pl[nt][1] = pack_h2(p10 - __half2float(h10), p11 - __half2float(h11));
        }
#pragma unroll
        for (int m = 1; m < 4; m <<= 1) {
            sum0 += __shfl_xor_sync(0xffffffffu, sum0, m);
            sum1 += __shfl_xor_sync(0xffffffffu, sum1, m);
        }
        l0 = l0 * sc0 + sum0;
        l1 = l1 * sc1 + sum1;
        m0 = mnew0;
        m1 = mnew1;
#pragma unroll
        for (int nt = 0; nt < 8; nt++) {
            oacc[nt][0] *= sc0; oacc[nt][1] *= sc0;
            oacc[nt][2] *= sc1; oacc[nt][3] *= sc1;
        }

#pragma unroll
        for (int ks = 0; ks < 4; ks++) {
            uint32_t Ah_[4] = { ph[2 * ks][0], ph[2 * ks][1],
                                ph[2 * ks + 1][0], ph[2 * ks + 1][1] };
            uint32_t Al_[4] = { pl[2 * ks][0], pl[2 * ks][1],
                                pl[2 * ks + 1][0], pl[2 * ks + 1][1] };
#pragma unroll
            for (int p = 0; p < 4; p++) {
                const uint32_t voff = (ks * 16 + vbrow) * ASTR + p * 32 + vboff;
                uint32_t th[4], tl[4];
                ldsm_x4_t(th, st + 2 * KVBUF + voff);
                ldsm_x4_t(tl, st + 3 * KVBUF + voff);
                mma16816h(oacc[2 * p],     Ah_, th);
                mma16816h(oacc[2 * p + 1], Ah_, th + 2);
                mma16816h(oacc[2 * p],     Ah_, tl);
                mma16816h(oacc[2 * p + 1], Ah_, tl + 2);
                mma16816h(oacc[2 * p],     Al_, th);
                mma16816h(oacc[2 * p + 1], Al_, th + 2);
            }
        }
        __syncthreads();
    }

    const float inv0 = 1.0f / l0;
    const float inv1 = 1.0f / l1;
    const int r0 = q0 + wid * 16 + (lane >> 2);
    const int r1 = r0 + 8;
#pragma unroll
    for (int nt = 0; nt < 8; nt++) {
        const int col = (int)hoff + nt * 8 + (lane & 3) * 2;
        float2 w0 = { oacc[nt][0] * inv0, oacc[nt][1] * inv0 };
        float2 w1 = { oacc[nt][2] * inv1, oacc[nt][3] * inv1 };
        *(float2*)(O + (tok0 + r0) * EMB + col) = w0;
        *(float2*)(O + (tok0 + r1) * EMB + col) = w1;
    }
}

// ------------- polynomial order-weighted mixing (elementwise) ----------------
__global__ __launch_bounds__(256) void mix_kernel(
    const float* __restrict__ org, const float* __restrict__ o,
    float* __restrict__ out)
{
    const int idx = blockIdx.x * blockDim.x + threadIdx.x;
    if (idx >= MTOT * EMB / 4) return;
    const int m = idx >> 8;
    float4 g = ((const float4*)org)[idx];
    float4 w = ((const float4*)o)[m];
    float4 r;
    r.x = g.x * fmaf(g.x, fmaf(g.x, fmaf(g.x, w.w, w.z), w.y), w.x);
    r.y = g.y * fmaf(g.y, fmaf(g.y, fmaf(g.y, w.w, w.z), w.y), w.x);
    r.z = g.z * fmaf(g.z, fmaf(g.z, fmaf(g.z, w.w, w.z), w.y), w.x);
    r.w = g.w * fmaf(g.w, fmaf(g.w, fmaf(g.w, w.w, w.z), w.y), w.x);
    ((float4*)out)[idx] = r;
}

// ------------------------------ launch -------------------------------------
extern "C" void kernel_launch(void* const* d_in, const int* in_sizes, int n_in,
                              void* d_out, int out_size)
{
    const float* x   = (const float*)d_in[0];
    const float* Wq  = (const float*)d_in[1];
    const float* bq  = (const float*)d_in[2];
    const float* Wk  = (const float*)d_in[3];
    const float* bk  = (const float*)d_in[4];
    const float* Wv  = (const float*)d_in[5];
    const float* bv  = (const float*)d_in[6];
    const float* Wo1 = (const float*)d_in[7];
    const float* bo1 = (const float*)d_in[8];
    const float* Wo2 = (const float*)d_in[9];
    const float* bo2 = (const float*)d_in[10];
    float* out = (float*)d_out;

    float *h, *org, *o;
    __nv_bfloat16 *xhi, *xlo, *wthi, *wtlo;
    cudaGetSymbolAddress((void**)&h, g_h);
    cudaGetSymbolAddress((void**)&org, g_org);
    cudaGetSymbolAddress((void**)&o, g_o);
    cudaGetSymbolAddress((void**)&xhi, g_xhi);
    cudaGetSymbolAddress((void**)&xlo, g_xlo);
    cudaGetSymbolAddress((void**)&wthi, g_wthi);
    cudaGetSymbolAddress((void**)&wtlo, g_wtlo);

    cudaFuncSetAttribute(proj_mma_kernel,
                         cudaFuncAttributeMaxDynamicSharedMemorySize, PROJ_SMEM_BYTES);
    cudaFuncSetAttribute(attn_mma_kernel,
                         cudaFuncAttributeMaxDynamicSharedMemorySize, ATT_SMEM_BYTES);

    // 1) split x and W^T into bf16 hi/lo
    const int nv4 = MTOT * EMB / 4;
    split_x_kernel<<<(nv4 + 255) / 256, 256>>>(x, xhi, xlo);
    split_wt_kernel<<<dim3(EMB / 32, EMB / 32, 4), dim3(32, 8)>>>(
        Wq, Wk, Wv, Wo1, wthi, wtlo);

    // 2) HMMA projections: q,k,v as fp16 hi/lo; h as fp32+relu
    proj_mma_kernel<<<dim3(EMB / 128, MTOT / 256, 4), 256, PROJ_SMEM_BYTES>>>(
        xhi, xlo, wthi, wtlo, bq, bk, bv, bo1);

    // 3) order weights o = h @ Wo2 + bo2
    owt_kernel<<<(MTOT * 32 + 255) / 256, 256>>>(h, Wo2, bo2, o);

    // 4) HMMA flash attention -> org
    attn_mma_kernel<<<dim3(SEQ / 128, HEADS, BATCH), 256, ATT_SMEM_BYTES>>>(org);

    // 5) polynomial mixing -> out
    mix_kernel<<<(nv4 + 255) / 256, 256>>>(org, o, out);
}

// round 7
// speedup vs baseline: 2.7741x; 1.0664x over previous
#include <cuda_runtime.h>
#include <cuda_fp16.h>
#include <cstdint>
#include <math_constants.h>

// Problem constants
#define BATCH 2
#define SEQ   2048
#define EMB   1024
#define HEADS 16
#define DHEAD 64
#define MTOT  (BATCH*SEQ)      // 4096
#define NORD  4

// ---------------- scratch (device globals; no cudaMalloc allowed) ------------
__device__ float g_h[MTOT * EMB];     // relu(x@Wo1 + bo1)
__device__ float g_org[MTOT * EMB];   // attention output (pre-mixing)
__device__ float g_o[MTOT * NORD];    // order weights

// fp16 split q, k, v
__device__ __align__(16) __half g_qh[MTOT * EMB];
__device__ __align__(16) __half g_ql[MTOT * EMB];
__device__ __align__(16) __half g_kh[MTOT * EMB];
__device__ __align__(16) __half g_kl[MTOT * EMB];
__device__ __align__(16) __half g_vh[MTOT * EMB];
__device__ __align__(16) __half g_vl[MTOT * EMB];

// fp16 operands for projection GEMMs: x split (lo used for q,k only), W^T split
__device__ __align__(16) __half g_xh[MTOT * EMB];
__device__ __align__(16) __half g_xl[MTOT * EMB];
__device__ __align__(16) __half g_wthi[4 * EMB * EMB];  // W^T per weight, [n][k]
__device__ __align__(16) __half g_wtlo[4 * EMB * EMB];

// ======================= PTX helpers (arch-portable) =========================
__device__ __forceinline__ uint32_t smem_u32(const void* p) {
    uint32_t a;
    asm("{ .reg .u64 t; cvta.to.shared.u64 t, %1; cvt.u32.u64 %0, t; }"
        : "=r"(a) : "l"(p));
    return a;
}

#define CP_ASYNC16(dst, src) \
    asm volatile("cp.async.cg.shared.global [%0], [%1], 16;" :: "r"(dst), "l"(src))
#define CP_COMMIT() asm volatile("cp.async.commit_group;" ::: "memory")
#define CP_WAIT(n)  asm volatile("cp.async.wait_group %0;" :: "n"(n) : "memory")

__device__ __forceinline__ void ldsm_x4(uint32_t* r, uint32_t addr) {
    asm volatile("ldmatrix.sync.aligned.m8n8.x4.shared.b16 {%0,%1,%2,%3}, [%4];"
        : "=r"(r[0]), "=r"(r[1]), "=r"(r[2]), "=r"(r[3]) : "r"(addr));
}
__device__ __forceinline__ void ldsm_x4_t(uint32_t* r, uint32_t addr) {
    asm volatile("ldmatrix.sync.aligned.m8n8.x4.trans.shared.b16 {%0,%1,%2,%3}, [%4];"
        : "=r"(r[0]), "=r"(r[1]), "=r"(r[2]), "=r"(r[3]) : "r"(addr));
}

// D(f32) += A(f16) * B(f16), m16n8k16
__device__ __forceinline__ void mma16816h(float* c, const uint32_t* a, const uint32_t* b) {
    asm volatile(
        "mma.sync.aligned.m16n8k16.row.col.f32.f16.f16.f32 "
        "{%0,%1,%2,%3}, {%4,%5,%6,%7}, {%8,%9}, {%0,%1,%2,%3};"
        : "+f"(c[0]), "+f"(c[1]), "+f"(c[2]), "+f"(c[3])
        : "r"(a[0]), "r"(a[1]), "r"(a[2]), "r"(a[3]), "r"(b[0]), "r"(b[1]));
}

__device__ __forceinline__ uint32_t pack_h2(float a, float b) {
    __half2 h = __floats2half2_rn(a, b);
    return *reinterpret_cast<uint32_t*>(&h);
}

// ====================== prep kernels =========================================
// split x -> fp16 hi + lo
__global__ __launch_bounds__(256) void split_x_kernel(
    const float* __restrict__ x, __half* __restrict__ hi, __half* __restrict__ lo)
{
    const int i4 = blockIdx.x * blockDim.x + threadIdx.x;
    if (i4 >= MTOT * EMB / 4) return;
    float4 v = ((const float4*)x)[i4];
    __half h0 = __float2half_rn(v.x), h1 = __float2half_rn(v.y);
    __half h2 = __float2half_rn(v.z), h3 = __float2half_rn(v.w);
    uint2 rh, rl;
    __half2 p01 = __halves2half2(h0, h1), p23 = __halves2half2(h2, h3);
    rh.x = *reinterpret_cast<uint32_t*>(&p01);
    rh.y = *reinterpret_cast<uint32_t*>(&p23);
    rl.x = pack_h2(v.x - __half2float(h0), v.y - __half2float(h1));
    rl.y = pack_h2(v.z - __half2float(h2), v.w - __half2float(h3));
    *(uint2*)(hi + 4 * (size_t)i4) = rh;
    *(uint2*)(lo + 4 * (size_t)i4) = rl;
}

// transpose W [k][n] -> W^T [n][k] with fp16 hi/lo split, per-weight (blockIdx.z)
__global__ __launch_bounds__(256) void split_wt_kernel(
    const float* __restrict__ Wq, const float* __restrict__ Wk,
    const float* __restrict__ Wv, const float* __restrict__ Wo1,
    __half* __restrict__ wthi, __half* __restrict__ wtlo)
{
    const int z = blockIdx.z;
    const float* W = (z == 0) ? Wq : (z == 1) ? Wk : (z == 2) ? Wv : Wo1;
    __shared__ float ts[32][33];
    const int n0 = blockIdx.x * 32;
    const int k0 = blockIdx.y * 32;
    const int tx = threadIdx.x, ty = threadIdx.y;   // 32 x 8
#pragma unroll
    for (int i = 0; i < 4; i++)
        ts[ty + 8 * i][tx] = W[(size_t)(k0 + ty + 8 * i) * EMB + n0 + tx];
    __syncthreads();
    __half* oh = wthi + (size_t)z * EMB * EMB;
    __half* ol = wtlo + (size_t)z * EMB * EMB;
#pragma unroll
    for (int i = 0; i < 4; i++) {
        const int n = n0 + ty + 8 * i;
        float v = ts[tx][ty + 8 * i];          // = W[k0+tx][n]
        __half h = __float2half_rn(v);
        __half l = __float2half_rn(v - __half2float(h));
        oh[(size_t)n * EMB + k0 + tx] = h;
        ol[(size_t)n * EMB + k0 + tx] = l;
    }
}

// =================== HMMA projection GEMM (fp16) =============================
// C[256x128] tile = X[256x1024] @ (Wh+Wl)[1024x128] + b.
// z in {0,1} (q,k): 3 passes (xh*Wh + xh*Wl + xl*Wh) -> logit-accurate.
// z in {2,3} (v,h): 2 passes (xh*Wh + xh*Wl).
// 8 warps, each 64x64. BK=32. 3-stage cp.async ring.
// smem stage rows: [0,256) A | [256,512) Al | [512,640) Bh | [640,768) Bl
#define PROW 80                           // bytes per smem row (64 + 16 pad)
#define STAGE_BYTES (768 * PROW)          // 61440
#define PROJ_SMEM_BYTES (3 * STAGE_BYTES) // 184320

__global__ __launch_bounds__(256, 1) void proj_mma_kernel(
    const __half* __restrict__ xh, const __half* __restrict__ xl,
    const __half* __restrict__ wthi, const __half* __restrict__ wtlo,
    const float* __restrict__ bq, const float* __restrict__ bk,
    const float* __restrict__ bv, const float* __restrict__ bo1)
{
    extern __shared__ char smem[];
    const uint32_t sbase = smem_u32(smem);

    const int z = blockIdx.z;
    const bool split_a = (z < 2);
    const float* bias = (z == 0) ? bq : (z == 1) ? bk : (z == 2) ? bv : bo1;

    const int tid = threadIdx.x;
    const int wid = tid >> 5;
    const int lane = tid & 31;
    const int wr = wid >> 1;          // warp row (0..3): rows wr*64
    const int wc = wid & 1;           // warp col (0..1): cols wc*64
    const int m0 = blockIdx.y * 256;
    const int n0 = blockIdx.x * 128;

    const __half* A  = xh + (size_t)m0 * EMB;
    const __half* Al = xl + (size_t)m0 * EMB;
    const __half* Bh = wthi + (size_t)z * EMB * EMB + (size_t)n0 * EMB;
    const __half* Bl = wtlo + (size_t)z * EMB * EMB + (size_t)n0 * EMB;

    auto load_stage = [&](int s, int kc) {
        const uint32_t dbase = sbase + (uint32_t)s * STAGE_BYTES;
        const int r64 = tid >> 2;          // 0..63
        const int c16 = tid & 3;           // 16B column
#pragma unroll
        for (int t = 0; t < 12; t++) {
            const int grow = t * 64 + r64;        // smem row 0..767
            const __half* src;
            if (t < 4)       src = A  + (size_t)grow * EMB;
            else if (t < 8)  { if (!split_a) continue;
                               src = Al + (size_t)(grow - 256) * EMB; }
            else if (t < 10) src = Bh + (size_t)(grow - 512) * EMB;
            else             src = Bl + (size_t)(grow - 640) * EMB;
            CP_ASYNC16(dbase + (uint32_t)grow * PROW + c16 * 16,
                       src + kc * 32 + c16 * 8);
        }
    };

    float acc[4][8][4];
#pragma unroll
    for (int mi = 0; mi < 4; mi++)
#pragma unroll
        for (int nj = 0; nj < 8; nj++)
#pragma unroll
            for (int e = 0; e < 4; e++) acc[mi][nj][e] = 0.0f;

    const int arow = lane & 15;
    const int ahalf = lane >> 4;
    const int brow = (lane & 7) + ((lane >> 4) << 3);
    const int bkoff = ((lane >> 3) & 1) * 16;

    load_stage(0, 0); CP_COMMIT();
    load_stage(1, 1); CP_COMMIT();

    const int NCH = EMB / 32;    // 32
    int s = 0, ps = 2;
    for (int kc = 0; kc < NCH; kc++) {
        if (kc + 1 < NCH) CP_WAIT(1); else CP_WAIT(0);
        __syncthreads();
        if (kc + 2 < NCH) {
            load_stage(ps, kc + 2);
            CP_COMMIT();
            if (++ps == 3) ps = 0;
        }

        const uint32_t st = sbase + (uint32_t)s * STAGE_BYTES;
        if (++s == 3) s = 0;
#pragma unroll
        for (int k16 = 0; k16 < 2; k16++) {
            uint32_t ah[4][4], al[4][4];
#pragma unroll
            for (int mi = 0; mi < 4; mi++) {
                const uint32_t ra = (uint32_t)(wr * 64 + mi * 16 + arow) * PROW
                                    + k16 * 32 + ahalf * 16;
                ldsm_x4(ah[mi], st + ra);
                if (split_a) ldsm_x4(al[mi], st + 256 * PROW + ra);
            }
#pragma unroll
            for (int p = 0; p < 4; p++) {
                const uint32_t rb = (uint32_t)(wc * 64 + p * 16 + brow) * PROW
                                    + k16 * 32 + bkoff;
                uint32_t th[4], tl[4];
                ldsm_x4(th, st + 512 * PROW + rb);
                ldsm_x4(tl, st + 640 * PROW + rb);
#pragma unroll
                for (int mi = 0; mi < 4; mi++) {
                    mma16816h(acc[mi][2 * p],     ah[mi], th);
                    mma16816h(acc[mi][2 * p + 1], ah[mi], th + 2);
                    mma16816h(acc[mi][2 * p],     ah[mi], tl);
                    mma16816h(acc[mi][2 * p + 1], ah[mi], tl + 2);
                    if (split_a) {
                        mma16816h(acc[mi][2 * p],     al[mi], th);
                        mma16816h(acc[mi][2 * p + 1], al[mi], th + 2);
                    }
                }
            }
        }
    }

    // epilogue: z<3 -> fp16 hi/lo split pair; z==3 -> fp32 relu h
    const int erow = lane >> 2;
    const int ecol = (lane & 3) * 2;
#pragma unroll
    for (int mi = 0; mi < 4; mi++) {
#pragma unroll
        for (int nj = 0; nj < 8; nj++) {
            const int row = m0 + wr * 64 + mi * 16 + erow;
            const int col = n0 + wc * 64 + nj * 8 + ecol;
            const float b0 = bias[col], b1 = bias[col + 1];
            float v00 = acc[mi][nj][0] + b0, v01 = acc[mi][nj][1] + b1;
            float v10 = acc[mi][nj][2] + b0, v11 = acc[mi][nj][3] + b1;
            const size_t o0 = (size_t)row * EMB + col;
            const size_t o1 = (size_t)(row + 8) * EMB + col;
            if (z == 3) {
                float2 r0 = { fmaxf(v00, 0.0f), fmaxf(v01, 0.0f) };
                float2 r1 = { fmaxf(v10, 0.0f), fmaxf(v11, 0.0f) };
                *(float2*)(g_h + o0) = r0;
                *(float2*)(g_h + o1) = r1;
            } else {
                __half* Ch = (z == 0) ? g_qh : (z == 1) ? g_kh : g_vh;
                __half* Cl = (z == 0) ? g_ql : (z == 1) ? g_kl : g_vl;
                __half h00 = __float2half_rn(v00), h01 = __float2half_rn(v01);
                __half h10 = __float2half_rn(v10), h11 = __float2half_rn(v11);
                *(uint32_t*)(Ch + o0) = pack_h2(v00, v01);
                *(uint32_t*)(Ch + o1) = pack_h2(v10, v11);
                *(uint32_t*)(Cl + o0) =
                    pack_h2(v00 - __half2float(h00), v01 - __half2float(h01));
                *(uint32_t*)(Cl + o1) =
                    pack_h2(v10 - __half2float(h10), v11 - __half2float(h11));
            }
        }
    }
}

// ------------- order-weight head: o = relu_h @ Wo2 + bo2 (N=4) ---------------
__global__ __launch_bounds__(256) void owt_kernel(
    const float* __restrict__ h, const float* __restrict__ Wo2,
    const float* __restrict__ bo2, float* __restrict__ o)
{
    const int warp = (blockIdx.x * blockDim.x + threadIdx.x) >> 5;
    const int lane = threadIdx.x & 31;
    if (warp >= MTOT) return;
    const float* hr = h + (size_t)warp * EMB;
    float a0 = 0.f, a1 = 0.f, a2 = 0.f, a3 = 0.f;
#pragma unroll 4
    for (int k = lane; k < EMB; k += 32) {
        float hv = hr[k];
        float4 w = *(const float4*)(Wo2 + (size_t)k * 4);
        a0 = fmaf(hv, w.x, a0);
        a1 = fmaf(hv, w.y, a1);
        a2 = fmaf(hv, w.z, a2);
        a3 = fmaf(hv, w.w, a3);
    }
#pragma unroll
    for (int m = 16; m > 0; m >>= 1) {
        a0 += __shfl_xor_sync(0xffffffffu, a0, m);
        a1 += __shfl_xor_sync(0xffffffffu, a1, m);
        a2 += __shfl_xor_sync(0xffffffffu, a2, m);
        a3 += __shfl_xor_sync(0xffffffffu, a3, m);
    }
    if (lane == 0) {
        o[warp * 4 + 0] = a0 + bo2[0];
        o[warp * 4 + 1] = a1 + bo2[1];
        o[warp * 4 + 2] = a2 + bo2[2];
        o[warp * 4 + 3] = a3 + bo2[3];
    }
}

// =================== HMMA flash attention ====================================
// CTA: 128 queries x 1 head. K/V tiles of 64. 8 warps x 16 rows.
// S = (Qh+Ql)(Kh+Kl)^T (3 passes, logit-accurate).
// P single fp16 (l sums the ROUNDED P -> zero-mean PV noise).
// O += P (Vh+Vl) (2 passes).
#define ASTR 144
#define QBUF (128 * ASTR)
#define KVBUF (64 * ASTR)
#define ATT_STAGE (4 * KVBUF)             // Kh, Kl, Vh, Vl
#define ATT_SMEM_BYTES (2 * QBUF + 2 * ATT_STAGE)   // 110592

__global__ __launch_bounds__(256, 1) void attn_mma_kernel(float* __restrict__ O)
{
    extern __shared__ char smem[];
    const uint32_t sb = smem_u32(smem);
    const uint32_t sQH = sb, sQL = sb + QBUF, sST = sb + 2 * QBUF;

    const int qt = blockIdx.x;
    const int hd = blockIdx.y;
    const int b  = blockIdx.z;
    const int q0 = qt * 128;
    const int tid = threadIdx.x;
    const int wid = tid >> 5;
    const int lane = tid & 31;
    const size_t tok0 = (size_t)b * SEQ;
    const size_t hoff = (size_t)hd * DHEAD;

    const __half* Qh = g_qh + (tok0 + q0) * EMB + hoff;
    const __half* Ql = g_ql + (tok0 + q0) * EMB + hoff;
    const __half* Kh = g_kh + tok0 * EMB + hoff;
    const __half* Kl = g_kl + tok0 * EMB + hoff;
    const __half* Vh = g_vh + tok0 * EMB + hoff;
    const __half* Vl = g_vl + tok0 * EMB + hoff;

    // Q load (hi + lo), own commit group
#pragma unroll
    for (int t = 0; t < 8; t++) {
        const int idx = tid + t * 256;     // 0..2047
        const int arr = idx >> 10;
        const int w = idx & 1023;
        const int row = w >> 3;
        const int c = w & 7;
        const uint32_t dst = (arr ? sQL : sQH) + row * ASTR + c * 16;
        const void* src = (arr ? Ql : Qh) + (size_t)row * EMB + c * 8;
        CP_ASYNC16(dst, src);
    }
    CP_COMMIT();

    auto load_stage = [&](int s, int kt) {
        const int k0 = kt * 64;
        const __half* srcs[4] = { Kh, Kl, Vh, Vl };
        const uint32_t dbase = sST + (uint32_t)s * ATT_STAGE;
#pragma unroll
        for (int t = 0; t < 8; t++) {
            const int idx = tid + t * 256;   // 0..2047
            const int arr = idx >> 9;
            const int w = idx & 511;
            const int row = w >> 3;
            const int c = w & 7;
            const uint32_t dst = dbase + arr * KVBUF + row * ASTR + c * 16;
            const void* src = srcs[arr] + (size_t)(k0 + row) * EMB + c * 8;
            CP_ASYNC16(dst, src);
        }
    };

    load_stage(0, 0);
    CP_COMMIT();
    CP_WAIT(1);
    __syncthreads();

    // Q fragments (resident)
    uint32_t aqh[4][4], aql[4][4];
    {
        const uint32_t qrow = (uint32_t)(wid * 16 + (lane & 15));
#pragma unroll
        for (int ks = 0; ks < 4; ks++) {
            const uint32_t off = qrow * ASTR + ks * 32 + (lane >> 4) * 16;
            ldsm_x4(aqh[ks], sQH + off);
            ldsm_x4(aql[ks], sQL + off);
        }
    }

    float m0 = -CUDART_INF_F, m1 = -CUDART_INF_F, l0 = 0.f, l1 = 0.f;
    float oacc[8][4];
#pragma unroll
    for (int nt = 0; nt < 8; nt++)
#pragma unroll
        for (int e = 0; e < 4; e++) oacc[nt][e] = 0.f;

    const uint32_t kbrow = (uint32_t)((lane & 7) + ((lane >> 4) << 3));
    const uint32_t kboff = (uint32_t)(((lane >> 3) & 1) << 4);
    const uint32_t vbrow = (uint32_t)((lane & 7) + (((lane >> 3) & 1) << 3));
    const uint32_t vboff = (uint32_t)((lane >> 4) << 4);

    const int NT = SEQ / 64;
    for (int kt = 0; kt < NT; kt++) {
        const int s = kt & 1;
        if (kt + 1 < NT) {
            load_stage(s ^ 1, kt + 1);
            CP_COMMIT();
            CP_WAIT(1);
        } else {
            CP_WAIT(0);
        }
        __syncthreads();

        const uint32_t st = sST + (uint32_t)s * ATT_STAGE;

        // ---- S = (Qh+Ql)(Kh+Kl)^T : 3 passes ----
        float sacc[8][4];
#pragma unroll
        for (int nt = 0; nt < 8; nt++)
#pragma unroll
            for (int e = 0; e < 4; e++) sacc[nt][e] = 0.f;

#pragma unroll
        for (int ks = 0; ks < 4; ks++) {
#pragma unroll
            for (int p = 0; p < 4; p++) {
                const uint32_t boff = (p * 16 + kbrow) * ASTR + ks * 32 + kboff;
                uint32_t th[4], tl[4];
                ldsm_x4(th, st + 0 * KVBUF + boff);
                ldsm_x4(tl, st + 1 * KVBUF + boff);
                mma16816h(sacc[2 * p],     aqh[ks], th);
                mma16816h(sacc[2 * p + 1], aqh[ks], th + 2);
                mma16816h(sacc[2 * p],     aqh[ks], tl);
                mma16816h(sacc[2 * p + 1], aqh[ks], tl + 2);
                mma16816h(sacc[2 * p],     aql[ks], th);
                mma16816h(sacc[2 * p + 1], aql[ks], th + 2);
            }
        }

        // ---- online softmax ----
        float tmax0 = -CUDART_INF_F, tmax1 = -CUDART_INF_F;
#pragma unroll
        for (int nt = 0; nt < 8; nt++) {
            tmax0 = fmaxf(tmax0, fmaxf(sacc[nt][0], sacc[nt][1]));
            tmax1 = fmaxf(tmax1, fmaxf(sacc[nt][2], sacc[nt][3]));
        }
#pragma unroll
        for (int m = 1; m < 4; m <<= 1) {
            tmax0 = fmaxf(tmax0, __shfl_xor_sync(0xffffffffu, tmax0, m));
            tmax1 = fmaxf(tmax1, __shfl_xor_sync(0xffffffffu, tmax1, m));
        }
        const float mnew0 = fmaxf(m0, tmax0);
        const float mnew1 = fmaxf(m1, tmax1);
        const float sc0 = __expf(m0 - mnew0);
        const float sc1 = __expf(m1 - mnew1);

        uint32_t ph[8][2];
        float sum0 = 0.f, sum1 = 0.f;
#pragma unroll
        for (int nt = 0; nt < 8; nt++) {
            float p00 = __expf(sacc[nt][0] - mnew0);
            float p01 = __expf(sacc[nt][1] - mnew0);
            float p10 = __expf(sacc[nt][2] - mnew1);
            float p11 = __expf(sacc[nt][3] - mnew1);
            __half h00 = __float2half_rn(p00), h01 = __float2half_rn(p01);
            __half h10 = __float2half_rn(p10), h11 = __float2half_rn(p11);
            // l sums the ROUNDED probabilities -> O/l unbiased
            sum0 += __half2float(h00) + __half2float(h01);
            sum1 += __half2float(h10) + __half2float(h11);
            __half2 hv0 = __halves2half2(h00, h01);
            __half2 hv1 = __halves2half2(h10, h11);
            ph[nt][0] = *reinterpret_cast<uint32_t*>(&hv0);
            ph[nt][1] = *reinterpret_cast<uint32_t*>(&hv1);
        }
#pragma unroll
        for (int m = 1; m < 4; m <<= 1) {
            sum0 += __shfl_xor_sync(0xffffffffu, sum0, m);
            sum1 += __shfl_xor_sync(0xffffffffu, sum1, m);
        }
        l0 = l0 * sc0 + sum0;
        l1 = l1 * sc1 + sum1;
        m0 = mnew0;
        m1 = mnew1;
#pragma unroll
        for (int nt = 0; nt < 8; nt++) {
            oacc[nt][0] *= sc0; oacc[nt][1] *= sc0;
            oacc[nt][2] *= sc1; oacc[nt][3] *= sc1;
        }

        // ---- O += P (Vh+Vl) : 2 passes ----
#pragma unroll
        for (int ks = 0; ks < 4; ks++) {
            uint32_t Ah_[4] = { ph[2 * ks][0], ph[2 * ks][1],
                                ph[2 * ks + 1][0], ph[2 * ks + 1][1] };
#pragma unroll
            for (int p = 0; p < 4; p++) {
                const uint32_t voff = (ks * 16 + vbrow) * ASTR + p * 32 + vboff;
                uint32_t th[4], tl[4];
                ldsm_x4_t(th, st + 2 * KVBUF + voff);
                ldsm_x4_t(tl, st + 3 * KVBUF + voff);
                mma16816h(oacc[2 * p],     Ah_, th);
                mma16816h(oacc[2 * p + 1], Ah_, th + 2);
                mma16816h(oacc[2 * p],     Ah_, tl);
                mma16816h(oacc[2 * p + 1], Ah_, tl + 2);
            }
        }
        __syncthreads();
    }

    const float inv0 = 1.0f / l0;
    const float inv1 = 1.0f / l1;
    const int r0 = q0 + wid * 16 + (lane >> 2);
    const int r1 = r0 + 8;
#pragma unroll
    for (int nt = 0; nt < 8; nt++) {
        const int col = (int)hoff + nt * 8 + (lane & 3) * 2;
        float2 w0 = { oacc[nt][0] * inv0, oacc[nt][1] * inv0 };
        float2 w1 = { oacc[nt][2] * inv1, oacc[nt][3] * inv1 };
        *(float2*)(O + (tok0 + r0) * EMB + col) = w0;
        *(float2*)(O + (tok0 + r1) * EMB + col) = w1;
    }
}

// ------------- polynomial order-weighted mixing (elementwise) ----------------
__global__ __launch_bounds__(256) void mix_kernel(
    const float* __restrict__ org, const float* __restrict__ o,
    float* __restrict__ out)
{
    const int idx = blockIdx.x * blockDim.x + threadIdx.x;
    if (idx >= MTOT * EMB / 4) return;
    const int m = idx >> 8;
    float4 g = ((const float4*)org)[idx];
    float4 w = ((const float4*)o)[m];
    float4 r;
    r.x = g.x * fmaf(g.x, fmaf(g.x, fmaf(g.x, w.w, w.z), w.y), w.x);
    r.y = g.y * fmaf(g.y, fmaf(g.y, fmaf(g.y, w.w, w.z), w.y), w.x);
    r.z = g.z * fmaf(g.z, fmaf(g.z, fmaf(g.z, w.w, w.z), w.y), w.x);
    r.w = g.w * fmaf(g.w, fmaf(g.w, fmaf(g.w, w.w, w.z), w.y), w.x);
    ((float4*)out)[idx] = r;
}

// ------------------------------ launch -------------------------------------
extern "C" void kernel_launch(void* const* d_in, const int* in_sizes, int n_in,
                              void* d_out, int out_size)
{
    const float* x   = (const float*)d_in[0];
    const float* Wq  = (const float*)d_in[1];
    const float* bq  = (const float*)d_in[2];
    const float* Wk  = (const float*)d_in[3];
    const float* bk  = (const float*)d_in[4];
    const float* Wv  = (const float*)d_in[5];
    const float* bv  = (const float*)d_in[6];
    const float* Wo1 = (const float*)d_in[7];
    const float* bo1 = (const float*)d_in[8];
    const float* Wo2 = (const float*)d_in[9];
    const float* bo2 = (const float*)d_in[10];
    float* out = (float*)d_out;

    float *h, *org, *o;
    __half *xh, *xl, *wthi, *wtlo;
    cudaGetSymbolAddress((void**)&h, g_h);
    cudaGetSymbolAddress((void**)&org, g_org);
    cudaGetSymbolAddress((void**)&o, g_o);
    cudaGetSymbolAddress((void**)&xh, g_xh);
    cudaGetSymbolAddress((void**)&xl, g_xl);
    cudaGetSymbolAddress((void**)&wthi, g_wthi);
    cudaGetSymbolAddress((void**)&wtlo, g_wtlo);

    cudaFuncSetAttribute(proj_mma_kernel,
                         cudaFuncAttributeMaxDynamicSharedMemorySize, PROJ_SMEM_BYTES);
    cudaFuncSetAttribute(attn_mma_kernel,
                         cudaFuncAttributeMaxDynamicSharedMemorySize, ATT_SMEM_BYTES);

    // 1) split x into fp16 hi/lo; split W^T into fp16 hi/lo
    const int nv4 = MTOT * EMB / 4;
    split_x_kernel<<<(nv4 + 255) / 256, 256>>>(x, xh, xl);
    split_wt_kernel<<<dim3(EMB / 32, EMB / 32, 4), dim3(32, 8)>>>(
        Wq, Wk, Wv, Wo1, wthi, wtlo);

    // 2) HMMA projections: q,k 3-pass; v,h 2-pass
    proj_mma_kernel<<<dim3(EMB / 128, MTOT / 256, 4), 256, PROJ_SMEM_BYTES>>>(
        xh, xl, wthi, wtlo, bq, bk, bv, bo1);

    // 3) order weights o = h @ Wo2 + bo2
    owt_kernel<<<(MTOT * 32 + 255) / 256, 256>>>(h, Wo2, bo2, o);

    // 4) HMMA flash attention (QK 3-pass, PV 2-pass) -> org
    attn_mma_kernel<<<dim3(SEQ / 128, HEADS, BATCH), 256, ATT_SMEM_BYTES>>>(org);

    // 5) polynomial mixing -> out
    mix_kernel<<<(nv4 + 255) / 256, 256>>>(org, o, out);
}

// round 8
// speedup vs baseline: 2.8441x; 1.0252x over previous
#include <cuda_runtime.h>
#include <cuda_fp16.h>
#include <cstdint>
#include <math_constants.h>

// Problem constants
#define BATCH 2
#define SEQ   2048
#define EMB   1024
#define HEADS 16
#define DHEAD 64
#define MTOT  (BATCH*SEQ)      // 4096
#define NORD  4

// ---------------- scratch (device globals; no cudaMalloc allowed) ------------
__device__ float g_h[MTOT * EMB];     // relu(x@Wo1 + bo1)
__device__ float g_o[MTOT * NORD];    // order weights

// fp16 split q, k, v
__device__ __align__(16) __half g_qh[MTOT * EMB];
__device__ __align__(16) __half g_ql[MTOT * EMB];
__device__ __align__(16) __half g_kh[MTOT * EMB];
__device__ __align__(16) __half g_kl[MTOT * EMB];
__device__ __align__(16) __half g_vh[MTOT * EMB];
__device__ __align__(16) __half g_vl[MTOT * EMB];

// fp16 operands for projection GEMMs: x split (lo used for q,k only), W^T split
__device__ __align__(16) __half g_xh[MTOT * EMB];
__device__ __align__(16) __half g_xl[MTOT * EMB];
__device__ __align__(16) __half g_wthi[4 * EMB * EMB];  // W^T per weight, [n][k]
__device__ __align__(16) __half g_wtlo[4 * EMB * EMB];

// ======================= PTX helpers (arch-portable) =========================
__device__ __forceinline__ uint32_t smem_u32(const void* p) {
    uint32_t a;
    asm("{ .reg .u64 t; cvta.to.shared.u64 t, %1; cvt.u32.u64 %0, t; }"
        : "=r"(a) : "l"(p));
    return a;
}

#define CP_ASYNC16(dst, src) \
    asm volatile("cp.async.cg.shared.global [%0], [%1], 16;" :: "r"(dst), "l"(src))
#define CP_COMMIT() asm volatile("cp.async.commit_group;" ::: "memory")
#define CP_WAIT(n)  asm volatile("cp.async.wait_group %0;" :: "n"(n) : "memory")

__device__ __forceinline__ void ldsm_x4(uint32_t* r, uint32_t addr) {
    asm volatile("ldmatrix.sync.aligned.m8n8.x4.shared.b16 {%0,%1,%2,%3}, [%4];"
        : "=r"(r[0]), "=r"(r[1]), "=r"(r[2]), "=r"(r[3]) : "r"(addr));
}
__device__ __forceinline__ void ldsm_x4_t(uint32_t* r, uint32_t addr) {
    asm volatile("ldmatrix.sync.aligned.m8n8.x4.trans.shared.b16 {%0,%1,%2,%3}, [%4];"
        : "=r"(r[0]), "=r"(r[1]), "=r"(r[2]), "=r"(r[3]) : "r"(addr));
}

// D(f32) += A(f16) * B(f16), m16n8k16
__device__ __forceinline__ void mma16816h(float* c, const uint32_t* a, const uint32_t* b) {
    asm volatile(
        "mma.sync.aligned.m16n8k16.row.col.f32.f16.f16.f32 "
        "{%0,%1,%2,%3}, {%4,%5,%6,%7}, {%8,%9}, {%0,%1,%2,%3};"
        : "+f"(c[0]), "+f"(c[1]), "+f"(c[2]), "+f"(c[3])
        : "r"(a[0]), "r"(a[1]), "r"(a[2]), "r"(a[3]), "r"(b[0]), "r"(b[1]));
}

__device__ __forceinline__ uint32_t pack_h2(float a, float b) {
    __half2 h = __floats2half2_rn(a, b);
    return *reinterpret_cast<uint32_t*>(&h);
}

// ====================== prep kernels =========================================
// split x -> fp16 hi + lo
__global__ __launch_bounds__(256) void split_x_kernel(
    const float* __restrict__ x, __half* __restrict__ hi, __half* __restrict__ lo)
{
    const int i4 = blockIdx.x * blockDim.x + threadIdx.x;
    if (i4 >= MTOT * EMB / 4) return;
    float4 v = ((const float4*)x)[i4];
    __half h0 = __float2half_rn(v.x), h1 = __float2half_rn(v.y);
    __half h2 = __float2half_rn(v.z), h3 = __float2half_rn(v.w);
    uint2 rh, rl;
    __half2 p01 = __halves2half2(h0, h1), p23 = __halves2half2(h2, h3);
    rh.x = *reinterpret_cast<uint32_t*>(&p01);
    rh.y = *reinterpret_cast<uint32_t*>(&p23);
    rl.x = pack_h2(v.x - __half2float(h0), v.y - __half2float(h1));
    rl.y = pack_h2(v.z - __half2float(h2), v.w - __half2float(h3));
    *(uint2*)(hi + 4 * (size_t)i4) = rh;
    *(uint2*)(lo + 4 * (size_t)i4) = rl;
}

// transpose W [k][n] -> W^T [n][k] with fp16 hi/lo split, per-weight (blockIdx.z)
__global__ __launch_bounds__(256) void split_wt_kernel(
    const float* __restrict__ Wq, const float* __restrict__ Wk,
    const float* __restrict__ Wv, const float* __restrict__ Wo1,
    __half* __restrict__ wthi, __half* __restrict__ wtlo)
{
    const int z = blockIdx.z;
    const float* W = (z == 0) ? Wq : (z == 1) ? Wk : (z == 2) ? Wv : Wo1;
    __shared__ float ts[32][33];
    const int n0 = blockIdx.x * 32;
    const int k0 = blockIdx.y * 32;
    const int tx = threadIdx.x, ty = threadIdx.y;   // 32 x 8
#pragma unroll
    for (int i = 0; i < 4; i++)
        ts[ty + 8 * i][tx] = W[(size_t)(k0 + ty + 8 * i) * EMB + n0 + tx];
    __syncthreads();
    __half* oh = wthi + (size_t)z * EMB * EMB;
    __half* ol = wtlo + (size_t)z * EMB * EMB;
#pragma unroll
    for (int i = 0; i < 4; i++) {
        const int n = n0 + ty + 8 * i;
        float v = ts[tx][ty + 8 * i];          // = W[k0+tx][n]
        __half h = __float2half_rn(v);
        __half l = __float2half_rn(v - __half2float(h));
        oh[(size_t)n * EMB + k0 + tx] = h;
        ol[(size_t)n * EMB + k0 + tx] = l;
    }
}

// =================== HMMA projection GEMM (fp16) =============================
// C[256x128] tile = X[256x1024] @ W[1024x128] + b.
// z in {0,1} (q,k): 3 passes (xh*Wh + xh*Wl + xl*Wh) -> logit-accurate.
// z in {2,3} (v,h): 1 pass (xh*Wh) -> linear-path, error ~u/sqrt(3).
// 8 warps, each 64x64. BK=32. 3-stage cp.async ring.
// smem stage rows: [0,256) A | [256,512) Al | [512,640) Bh | [640,768) Bl
#define PROW 80                           // bytes per smem row (64 + 16 pad)
#define STAGE_BYTES (768 * PROW)          // 61440
#define PROJ_SMEM_BYTES (3 * STAGE_BYTES) // 184320

__global__ __launch_bounds__(256, 1) void proj_mma_kernel(
    const __half* __restrict__ xh, const __half* __restrict__ xl,
    const __half* __restrict__ wthi, const __half* __restrict__ wtlo,
    const float* __restrict__ bq, const float* __restrict__ bk,
    const float* __restrict__ bv, const float* __restrict__ bo1)
{
    extern __shared__ char smem[];
    const uint32_t sbase = smem_u32(smem);

    const int z = blockIdx.z;
    const bool split_ab = (z < 2);     // q,k: split A and split B (3 passes)
    const float* bias = (z == 0) ? bq : (z == 1) ? bk : (z == 2) ? bv : bo1;

    const int tid = threadIdx.x;
    const int wid = tid >> 5;
    const int lane = tid & 31;
    const int wr = wid >> 1;          // warp row (0..3): rows wr*64
    const int wc = wid & 1;           // warp col (0..1): cols wc*64
    const int m0 = blockIdx.y * 256;
    const int n0 = blockIdx.x * 128;

    const __half* A  = xh + (size_t)m0 * EMB;
    const __half* Al = xl + (size_t)m0 * EMB;
    const __half* Bh = wthi + (size_t)z * EMB * EMB + (size_t)n0 * EMB;
    const __half* Bl = wtlo + (size_t)z * EMB * EMB + (size_t)n0 * EMB;

    auto load_stage = [&](int s, int kc) {
        const uint32_t dbase = sbase + (uint32_t)s * STAGE_BYTES;
        const int r64 = tid >> 2;          // 0..63
        const int c16 = tid & 3;           // 16B column
#pragma unroll
        for (int t = 0; t < 12; t++) {
            const int grow = t * 64 + r64;        // smem row 0..767
            const __half* src;
            if (t < 4)       src = A  + (size_t)grow * EMB;
            else if (t < 8)  { if (!split_ab) continue;
                               src = Al + (size_t)(grow - 256) * EMB; }
            else if (t < 10) src = Bh + (size_t)(grow - 512) * EMB;
            else             { if (!split_ab) continue;
                               src = Bl + (size_t)(grow - 640) * EMB; }
            CP_ASYNC16(dbase + (uint32_t)grow * PROW + c16 * 16,
                       src + kc * 32 + c16 * 8);
        }
    };

    float acc[4][8][4];
#pragma unroll
    for (int mi = 0; mi < 4; mi++)
#pragma unroll
        for (int nj = 0; nj < 8; nj++)
#pragma unroll
            for (int e = 0; e < 4; e++) acc[mi][nj][e] = 0.0f;

    const int arow = lane & 15;
    const int ahalf = lane >> 4;
    const int brow = (lane & 7) + ((lane >> 4) << 3);
    const int bkoff = ((lane >> 3) & 1) * 16;

    load_stage(0, 0); CP_COMMIT();
    load_stage(1, 1); CP_COMMIT();

    const int NCH = EMB / 32;    // 32
    int s = 0, ps = 2;
    for (int kc = 0; kc < NCH; kc++) {
        if (kc + 1 < NCH) CP_WAIT(1); else CP_WAIT(0);
        __syncthreads();
        if (kc + 2 < NCH) {
            load_stage(ps, kc + 2);
            CP_COMMIT();
            if (++ps == 3) ps = 0;
        }

        const uint32_t st = sbase + (uint32_t)s * STAGE_BYTES;
        if (++s == 3) s = 0;
#pragma unroll
        for (int k16 = 0; k16 < 2; k16++) {
            uint32_t ah[4][4], al[4][4];
#pragma unroll
            for (int mi = 0; mi < 4; mi++) {
                const uint32_t ra = (uint32_t)(wr * 64 + mi * 16 + arow) * PROW
                                    + k16 * 32 + ahalf * 16;
                ldsm_x4(ah[mi], st + ra);
                if (split_ab) ldsm_x4(al[mi], st + 256 * PROW + ra);
            }
#pragma unroll
            for (int p = 0; p < 4; p++) {
                const uint32_t rb = (uint32_t)(wc * 64 + p * 16 + brow) * PROW
                                    + k16 * 32 + bkoff;
                uint32_t th[4], tl[4];
                ldsm_x4(th, st + 512 * PROW + rb);
                if (split_ab) ldsm_x4(tl, st + 640 * PROW + rb);
#pragma unroll
                for (int mi = 0; mi < 4; mi++) {
                    mma16816h(acc[mi][2 * p],     ah[mi], th);
                    mma16816h(acc[mi][2 * p + 1], ah[mi], th + 2);
                    if (split_ab) {
                        mma16816h(acc[mi][2 * p],     ah[mi], tl);
                        mma16816h(acc[mi][2 * p + 1], ah[mi], tl + 2);
                        mma16816h(acc[mi][2 * p],     al[mi], th);
                        mma16816h(acc[mi][2 * p + 1], al[mi], th + 2);
                    }
                }
            }
        }
    }

    // epilogue: z<3 -> fp16 hi/lo split pair; z==3 -> fp32 relu h
    const int erow = lane >> 2;
    const int ecol = (lane & 3) * 2;
#pragma unroll
    for (int mi = 0; mi < 4; mi++) {
#pragma unroll
        for (int nj = 0; nj < 8; nj++) {
            const int row = m0 + wr * 64 + mi * 16 + erow;
            const int col = n0 + wc * 64 + nj * 8 + ecol;
            const float b0 = bias[col], b1 = bias[col + 1];
            float v00 = acc[mi][nj][0] + b0, v01 = acc[mi][nj][1] + b1;
            float v10 = acc[mi][nj][2] + b0, v11 = acc[mi][nj][3] + b1;
            const size_t o0 = (size_t)row * EMB + col;
            const size_t o1 = (size_t)(row + 8) * EMB + col;
            if (z == 3) {
                float2 r0 = { fmaxf(v00, 0.0f), fmaxf(v01, 0.0f) };
                float2 r1 = { fmaxf(v10, 0.0f), fmaxf(v11, 0.0f) };
                *(float2*)(g_h + o0) = r0;
                *(float2*)(g_h + o1) = r1;
            } else {
                __half* Ch = (z == 0) ? g_qh : (z == 1) ? g_kh : g_vh;
                __half* Cl = (z == 0) ? g_ql : (z == 1) ? g_kl : g_vl;
                __half h00 = __float2half_rn(v00), h01 = __float2half_rn(v01);
                __half h10 = __float2half_rn(v10), h11 = __float2half_rn(v11);
                *(uint32_t*)(Ch + o0) = pack_h2(v00, v01);
                *(uint32_t*)(Ch + o1) = pack_h2(v10, v11);
                *(uint32_t*)(Cl + o0) =
                    pack_h2(v00 - __half2float(h00), v01 - __half2float(h01));
                *(uint32_t*)(Cl + o1) =
                    pack_h2(v10 - __half2float(h10), v11 - __half2float(h11));
            }
        }
    }
}

// ------------- order-weight head: o = relu_h @ Wo2 + bo2 (N=4) ---------------
__global__ __launch_bounds__(256) void owt_kernel(
    const float* __restrict__ h, const float* __restrict__ Wo2,
    const float* __restrict__ bo2, float* __restrict__ o)
{
    const int warp = (blockIdx.x * blockDim.x + threadIdx.x) >> 5;
    const int lane = threadIdx.x & 31;
    if (warp >= MTOT) return;
    const float* hr = h + (size_t)warp * EMB;
    float a0 = 0.f, a1 = 0.f, a2 = 0.f, a3 = 0.f;
#pragma unroll 4
    for (int k = lane; k < EMB; k += 32) {
        float hv = hr[k];
        float4 w = *(const float4*)(Wo2 + (size_t)k * 4);
        a0 = fmaf(hv, w.x, a0);
        a1 = fmaf(hv, w.y, a1);
        a2 = fmaf(hv, w.z, a2);
        a3 = fmaf(hv, w.w, a3);
    }
#pragma unroll
    for (int m = 16; m > 0; m >>= 1) {
        a0 += __shfl_xor_sync(0xffffffffu, a0, m);
        a1 += __shfl_xor_sync(0xffffffffu, a1, m);
        a2 += __shfl_xor_sync(0xffffffffu, a2, m);
        a3 += __shfl_xor_sync(0xffffffffu, a3, m);
    }
    if (lane == 0) {
        o[warp * 4 + 0] = a0 + bo2[0];
        o[warp * 4 + 1] = a1 + bo2[1];
        o[warp * 4 + 2] = a2 + bo2[2];
        o[warp * 4 + 3] = a3 + bo2[3];
    }
}

// =================== HMMA flash attention + fused mixing =====================
// CTA: 128 queries x 1 head. K/V tiles of 64. 8 warps x 16 rows.
// S = (Qh+Ql)(Kh+Kl)^T (3 passes); P single fp16 (l sums rounded P);
// O += P (Vh+Vl) (2 passes). Epilogue: org = O/l, then the order-weighted
// polynomial with per-token o -> writes final output directly.
#define ASTR 144
#define QBUF (128 * ASTR)
#define KVBUF (64 * ASTR)
#define ATT_STAGE (4 * KVBUF)             // Kh, Kl, Vh, Vl
#define ATT_SMEM_BYTES (2 * QBUF + 2 * ATT_STAGE)   // 110592

__global__ __launch_bounds__(256, 1) void attn_mma_kernel(
    const float* __restrict__ ow, float* __restrict__ out)
{
    extern __shared__ char smem[];
    const uint32_t sb = smem_u32(smem);
    const uint32_t sQH = sb, sQL = sb + QBUF, sST = sb + 2 * QBUF;

    const int qt = blockIdx.x;
    const int hd = blockIdx.y;
    const int b  = blockIdx.z;
    const int q0 = qt * 128;
    const int tid = threadIdx.x;
    const int wid = tid >> 5;
    const int lane = tid & 31;
    const size_t tok0 = (size_t)b * SEQ;
    const size_t hoff = (size_t)hd * DHEAD;

    const __half* Qh = g_qh + (tok0 + q0) * EMB + hoff;
    const __half* Ql = g_ql + (tok0 + q0) * EMB + hoff;
    const __half* Kh = g_kh + tok0 * EMB + hoff;
    const __half* Kl = g_kl + tok0 * EMB + hoff;
    const __half* Vh = g_vh + tok0 * EMB + hoff;
    const __half* Vl = g_vl + tok0 * EMB + hoff;

    // Q load (hi + lo), own commit group
#pragma unroll
    for (int t = 0; t < 8; t++) {
        const int idx = tid + t * 256;     // 0..2047
        const int arr = idx >> 10;
        const int w = idx & 1023;
        const int row = w >> 3;
        const int c = w & 7;
        const uint32_t dst = (arr ? sQL : sQH) + row * ASTR + c * 16;
        const void* src = (arr ? Ql : Qh) + (size_t)row * EMB + c * 8;
        CP_ASYNC16(dst, src);
    }
    CP_COMMIT();

    auto load_stage = [&](int s, int kt) {
        const int k0 = kt * 64;
        const __half* srcs[4] = { Kh, Kl, Vh, Vl };
        const uint32_t dbase = sST + (uint32_t)s * ATT_STAGE;
#pragma unroll
        for (int t = 0; t < 8; t++) {
            const int idx = tid + t * 256;   // 0..2047
            const int arr = idx >> 9;
            const int w = idx & 511;
            const int row = w >> 3;
            const int c = w & 7;
            const uint32_t dst = dbase + arr * KVBUF + row * ASTR + c * 16;
            const void* src = srcs[arr] + (size_t)(k0 + row) * EMB + c * 8;
            CP_ASYNC16(dst, src);
        }
    };

    load_stage(0, 0);
    CP_COMMIT();
    CP_WAIT(1);
    __syncthreads();

    // Q fragments (resident)
    uint32_t aqh[4][4], aql[4][4];
    {
        const uint32_t qrow = (uint32_t)(wid * 16 + (lane & 15));
#pragma unroll
        for (int ks = 0; ks < 4; ks++) {
            const uint32_t off = qrow * ASTR + ks * 32 + (lane >> 4) * 16;
            ldsm_x4(aqh[ks], sQH + off);
            ldsm_x4(aql[ks], sQL + off);
        }
    }

    float m0 = -CUDART_INF_F, m1 = -CUDART_INF_F, l0 = 0.f, l1 = 0.f;
    float oacc[8][4];
#pragma unroll
    for (int nt = 0; nt < 8; nt++)
#pragma unroll
        for (int e = 0; e < 4; e++) oacc[nt][e] = 0.f;

    const uint32_t kbrow = (uint32_t)((lane & 7) + ((lane >> 4) << 3));
    const uint32_t kboff = (uint32_t)(((lane >> 3) & 1) << 4);
    const uint32_t vbrow = (uint32_t)((lane & 7) + (((lane >> 3) & 1) << 3));
    const uint32_t vboff = (uint32_t)((lane >> 4) << 4);

    const int NT = SEQ / 64;
    for (int kt = 0; kt < NT; kt++) {
        const int s = kt & 1;
        if (kt + 1 < NT) {
            load_stage(s ^ 1, kt + 1);
            CP_COMMIT();
            CP_WAIT(1);
        } else {
            CP_WAIT(0);
        }
        __syncthreads();

        const uint32_t st = sST + (uint32_t)s * ATT_STAGE;

        // ---- S = (Qh+Ql)(Kh+Kl)^T : 3 passes ----
        float sacc[8][4];
#pragma unroll
        for (int nt = 0; nt < 8; nt++)
#pragma unroll
            for (int e = 0; e < 4; e++) sacc[nt][e] = 0.f;

#pragma unroll
        for (int ks = 0; ks < 4; ks++) {
#pragma unroll
            for (int p = 0; p < 4; p++) {
                const uint32_t boff = (p * 16 + kbrow) * ASTR + ks * 32 + kboff;
                uint32_t th[4], tl[4];
                ldsm_x4(th, st + 0 * KVBUF + boff);
                ldsm_x4(tl, st + 1 * KVBUF + boff);
                mma16816h(sacc[2 * p],     aqh[ks], th);
                mma16816h(sacc[2 * p + 1], aqh[ks], th + 2);
                mma16816h(sacc[2 * p],     aqh[ks], tl);
                mma16816h(sacc[2 * p + 1], aqh[ks], tl + 2);
                mma16816h(sacc[2 * p],     aql[ks], th);
                mma16816h(sacc[2 * p + 1], aql[ks], th + 2);
            }
        }

        // ---- online softmax ----
        float tmax0 = -CUDART_INF_F, tmax1 = -CUDART_INF_F;
#pragma unroll
        for (int nt = 0; nt < 8; nt++) {
            tmax0 = fmaxf(tmax0, fmaxf(sacc[nt][0], sacc[nt][1]));
            tmax1 = fmaxf(tmax1, fmaxf(sacc[nt][2], sacc[nt][3]));
        }
#pragma unroll
        for (int m = 1; m < 4; m <<= 1) {
            tmax0 = fmaxf(tmax0, __shfl_xor_sync(0xffffffffu, tmax0, m));
            tmax1 = fmaxf(tmax1, __shfl_xor_sync(0xffffffffu, tmax1, m));
        }
        const float mnew0 = fmaxf(m0, tmax0);
        const float mnew1 = fmaxf(m1, tmax1);
        const float sc0 = __expf(m0 - mnew0);
        const float sc1 = __expf(m1 - mnew1);

        uint32_t ph[8][2];
        float sum0 = 0.f, sum1 = 0.f;
#pragma unroll
        for (int nt = 0; nt < 8; nt++) {
            float p00 = __expf(sacc[nt][0] - mnew0);
            float p01 = __expf(sacc[nt][1] - mnew0);
            float p10 = __expf(sacc[nt][2] - mnew1);
            float p11 = __expf(sacc[nt][3] - mnew1);
            __half h00 = __float2half_rn(p00), h01 = __float2half_rn(p01);
            __half h10 = __float2half_rn(p10), h11 = __float2half_rn(p11);
            // l sums the ROUNDED probabilities -> O/l unbiased
            sum0 += __half2float(h00) + __half2float(h01);
            sum1 += __half2float(h10) + __half2float(h11);
            __half2 hv0 = __halves2half2(h00, h01);
            __half2 hv1 = __halves2half2(h10, h11);
            ph[nt][0] = *reinterpret_cast<uint32_t*>(&hv0);
            ph[nt][1] = *reinterpret_cast<uint32_t*>(&hv1);
        }
#pragma unroll
        for (int m = 1; m < 4; m <<= 1) {
            sum0 += __shfl_xor_sync(0xffffffffu, sum0, m);
            sum1 += __shfl_xor_sync(0xffffffffu, sum1, m);
        }
        l0 = l0 * sc0 + sum0;
        l1 = l1 * sc1 + sum1;
        m0 = mnew0;
        m1 = mnew1;
#pragma unroll
        for (int nt = 0; nt < 8; nt++) {
            oacc[nt][0] *= sc0; oacc[nt][1] *= sc0;
            oacc[nt][2] *= sc1; oacc[nt][3] *= sc1;
        }

        // ---- O += P (Vh+Vl) : 2 passes ----
#pragma unroll
        for (int ks = 0; ks < 4; ks++) {
            uint32_t Ah_[4] = { ph[2 * ks][0], ph[2 * ks][1],
                                ph[2 * ks + 1][0], ph[2 * ks + 1][1] };
#pragma unroll
            for (int p = 0; p < 4; p++) {
                const uint32_t voff = (ks * 16 + vbrow) * ASTR + p * 32 + vboff;
                uint32_t th[4], tl[4];
                ldsm_x4_t(th, st + 2 * KVBUF + voff);
                ldsm_x4_t(tl, st + 3 * KVBUF + voff);
                mma16816h(oacc[2 * p],     Ah_, th);
                mma16816h(oacc[2 * p + 1], Ah_, th + 2);
                mma16816h(oacc[2 * p],     Ah_, tl);
                mma16816h(oacc[2 * p + 1], Ah_, tl + 2);
            }
        }
        __syncthreads();
    }

    // ---- fused epilogue: org = O/l, then polynomial mixing -> out ----
    const float inv0 = 1.0f / l0;
    const float inv1 = 1.0f / l1;
    const int r0 = q0 + wid * 16 + (lane >> 2);
    const int r1 = r0 + 8;
    const float4 w0v = ((const float4*)ow)[tok0 + r0];
    const float4 w1v = ((const float4*)ow)[tok0 + r1];
#pragma unroll
    for (int nt = 0; nt < 8; nt++) {
        const int col = (int)hoff + nt * 8 + (lane & 3) * 2;
        float g00 = oacc[nt][0] * inv0, g01 = oacc[nt][1] * inv0;
        float g10 = oacc[nt][2] * inv1, g11 = oacc[nt][3] * inv1;
        float2 o0, o1;
        o0.x = g00 * fmaf(g00, fmaf(g00, fmaf(g00, w0v.w, w0v.z), w0v.y), w0v.x);
        o0.y = g01 * fmaf(g01, fmaf(g01, fmaf(g01, w0v.w, w0v.z), w0v.y), w0v.x);
        o1.x = g10 * fmaf(g10, fmaf(g10, fmaf(g10, w1v.w, w1v.z), w1v.y), w1v.x);
        o1.y = g11 * fmaf(g11, fmaf(g11, fmaf(g11, w1v.w, w1v.z), w1v.y), w1v.x);
        *(float2*)(out + (tok0 + r0) * EMB + col) = o0;
        *(float2*)(out + (tok0 + r1) * EMB + col) = o1;
    }
}

// ------------------------------ launch -------------------------------------
extern "C" void kernel_launch(void* const* d_in, const int* in_sizes, int n_in,
                              void* d_out, int out_size)
{
    const float* x   = (const float*)d_in[0];
    const float* Wq  = (const float*)d_in[1];
    const float* bq  = (const float*)d_in[2];
    const float* Wk  = (const float*)d_in[3];
    const float* bk  = (const float*)d_in[4];
    const float* Wv  = (const float*)d_in[5];
    const float* bv  = (const float*)d_in[6];
    const float* Wo1 = (const float*)d_in[7];
    const float* bo1 = (const float*)d_in[8];
    const float* Wo2 = (const float*)d_in[9];
    const float* bo2 = (const float*)d_in[10];
    float* out = (float*)d_out;

    float *h, *o;
    __half *xh, *xl, *wthi, *wtlo;
    cudaGetSymbolAddress((void**)&h, g_h);
    cudaGetSymbolAddress((void**)&o, g_o);
    cudaGetSymbolAddress((void**)&xh, g_xh);
    cudaGetSymbolAddress((void**)&xl, g_xl);
    cudaGetSymbolAddress((void**)&wthi, g_wthi);
    cudaGetSymbolAddress((void**)&wtlo, g_wtlo);

    cudaFuncSetAttribute(proj_mma_kernel,
                         cudaFuncAttributeMaxDynamicSharedMemorySize, PROJ_SMEM_BYTES);
    cudaFuncSetAttribute(attn_mma_kernel,
                         cudaFuncAttributeMaxDynamicSharedMemorySize, ATT_SMEM_BYTES);

    // 1) split x into fp16 hi/lo; split W^T into fp16 hi/lo
    const int nv4 = MTOT * EMB / 4;
    split_x_kernel<<<(nv4 + 255) / 256, 256>>>(x, xh, xl);
    split_wt_kernel<<<dim3(EMB / 32, EMB / 32, 4), dim3(32, 8)>>>(
        Wq, Wk, Wv, Wo1, wthi, wtlo);

    // 2) HMMA projections: q,k 3-pass; v,h 1-pass
    proj_mma_kernel<<<dim3(EMB / 128, MTOT / 256, 4), 256, PROJ_SMEM_BYTES>>>(
        xh, xl, wthi, wtlo, bq, bk, bv, bo1);

    // 3) order weights o = h @ Wo2 + bo2
    owt_kernel<<<(MTOT * 32 + 255) / 256, 256>>>(h, Wo2, bo2, o);

    // 4) HMMA flash attention (QK 3-pass, PV 2-pass) + fused mixing -> out
    attn_mma_kernel<<<dim3(SEQ / 128, HEADS, BATCH), 256, ATT_SMEM_BYTES>>>(o, out);
}

// round 9
// speedup vs baseline: 3.1331x; 1.1016x over previous
#include <cuda_runtime.h>
#include <cuda_fp16.h>
#include <cstdint>
#include <math_constants.h>

// Problem constants
#define BATCH 2
#define SEQ   2048
#define EMB   1024
#define HEADS 16
#define DHEAD 64
#define MTOT  (BATCH*SEQ)      // 4096
#define NORD  4

// ---------------- scratch (device globals; no cudaMalloc allowed) ------------
__device__ float g_h[MTOT * EMB];     // relu(x@Wo1 + bo1)
__device__ float g_o[MTOT * NORD];    // order weights

// fp16 q (split), k (single, accurate-rounded), v (split)
__device__ __align__(16) __half g_qh[MTOT * EMB];
__device__ __align__(16) __half g_ql[MTOT * EMB];
__device__ __align__(16) __half g_kh[MTOT * EMB];
__device__ __align__(16) __half g_vh[MTOT * EMB];
__device__ __align__(16) __half g_vl[MTOT * EMB];

// fp16 operands for projection GEMMs: x split (lo used for q,k only), W^T split
__device__ __align__(16) __half g_xh[MTOT * EMB];
__device__ __align__(16) __half g_xl[MTOT * EMB];
__device__ __align__(16) __half g_wthi[4 * EMB * EMB];  // W^T per weight, [n][k]
__device__ __align__(16) __half g_wtlo[4 * EMB * EMB];

// ======================= PTX helpers (arch-portable) =========================
__device__ __forceinline__ uint32_t smem_u32(const void* p) {
    uint32_t a;
    asm("{ .reg .u64 t; cvta.to.shared.u64 t, %1; cvt.u32.u64 %0, t; }"
        : "=r"(a) : "l"(p));
    return a;
}

#define CP_ASYNC16(dst, src) \
    asm volatile("cp.async.cg.shared.global [%0], [%1], 16;" :: "r"(dst), "l"(src))
#define CP_COMMIT() asm volatile("cp.async.commit_group;" ::: "memory")
#define CP_WAIT(n)  asm volatile("cp.async.wait_group %0;" :: "n"(n) : "memory")

__device__ __forceinline__ void ldsm_x4(uint32_t* r, uint32_t addr) {
    asm volatile("ldmatrix.sync.aligned.m8n8.x4.shared.b16 {%0,%1,%2,%3}, [%4];"
        : "=r"(r[0]), "=r"(r[1]), "=r"(r[2]), "=r"(r[3]) : "r"(addr));
}
__device__ __forceinline__ void ldsm_x4_t(uint32_t* r, uint32_t addr) {
    asm volatile("ldmatrix.sync.aligned.m8n8.x4.trans.shared.b16 {%0,%1,%2,%3}, [%4];"
        : "=r"(r[0]), "=r"(r[1]), "=r"(r[2]), "=r"(r[3]) : "r"(addr));
}

// D(f32) += A(f16) * B(f16), m16n8k16
__device__ __forceinline__ void mma16816h(float* c, const uint32_t* a, const uint32_t* b) {
    asm volatile(
        "mma.sync.aligned.m16n8k16.row.col.f32.f16.f16.f32 "
        "{%0,%1,%2,%3}, {%4,%5,%6,%7}, {%8,%9}, {%0,%1,%2,%3};"
        : "+f"(c[0]), "+f"(c[1]), "+f"(c[2]), "+f"(c[3])
        : "r"(a[0]), "r"(a[1]), "r"(a[2]), "r"(a[3]), "r"(b[0]), "r"(b[1]));
}

__device__ __forceinline__ uint32_t pack_h2(float a, float b) {
    __half2 h = __floats2half2_rn(a, b);
    return *reinterpret_cast<uint32_t*>(&h);
}

// ====================== prep kernels =========================================
// split x -> fp16 hi + lo
__global__ __launch_bounds__(256) void split_x_kernel(
    const float* __restrict__ x, __half* __restrict__ hi, __half* __restrict__ lo)
{
    const int i4 = blockIdx.x * blockDim.x + threadIdx.x;
    if (i4 >= MTOT * EMB / 4) return;
    float4 v = ((const float4*)x)[i4];
    __half h0 = __float2half_rn(v.x), h1 = __float2half_rn(v.y);
    __half h2 = __float2half_rn(v.z), h3 = __float2half_rn(v.w);
    uint2 rh, rl;
    __half2 p01 = __halves2half2(h0, h1), p23 = __halves2half2(h2, h3);
    rh.x = *reinterpret_cast<uint32_t*>(&p01);
    rh.y = *reinterpret_cast<uint32_t*>(&p23);
    rl.x = pack_h2(v.x - __half2float(h0), v.y - __half2float(h1));
    rl.y = pack_h2(v.z - __half2float(h2), v.w - __half2float(h3));
    *(uint2*)(hi + 4 * (size_t)i4) = rh;
    *(uint2*)(lo + 4 * (size_t)i4) = rl;
}

// transpose W [k][n] -> W^T [n][k] with fp16 hi/lo split, per-weight (blockIdx.z)
__global__ __launch_bounds__(256) void split_wt_kernel(
    const float* __restrict__ Wq, const float* __restrict__ Wk,
    const float* __restrict__ Wv, const float* __restrict__ Wo1,
    __half* __restrict__ wthi, __half* __restrict__ wtlo)
{
    const int z = blockIdx.z;
    const float* W = (z == 0) ? Wq : (z == 1) ? Wk : (z == 2) ? Wv : Wo1;
    __shared__ float ts[32][33];
    const int n0 = blockIdx.x * 32;
    const int k0 = blockIdx.y * 32;
    const int tx = threadIdx.x, ty = threadIdx.y;   // 32 x 8
#pragma unroll
    for (int i = 0; i < 4; i++)
        ts[ty + 8 * i][tx] = W[(size_t)(k0 + ty + 8 * i) * EMB + n0 + tx];
    __syncthreads();
    __half* oh = wthi + (size_t)z * EMB * EMB;
    __half* ol = wtlo + (size_t)z * EMB * EMB;
#pragma unroll
    for (int i = 0; i < 4; i++) {
        const int n = n0 + ty + 8 * i;
        float v = ts[tx][ty + 8 * i];          // = W[k0+tx][n]
        __half h = __float2half_rn(v);
        __half l = __float2half_rn(v - __half2float(h));
        oh[(size_t)n * EMB + k0 + tx] = h;
        ol[(size_t)n * EMB + k0 + tx] = l;
    }
}

// =================== HMMA projection GEMM (fp16) =============================
// C[256x128] tile = X[256x1024] @ W[1024x128] + b.
// z in {0,1} (q,k): 3 passes (xh*Wh + xh*Wl + xl*Wh) -> accurate.
// z in {2,3} (v,h): 1 pass (xh*Wh) -> linear-path.
// 8 warps, each 64x64. BK=32. 3-stage cp.async ring.
// smem stage rows: [0,256) A | [256,512) Al | [512,640) Bh | [640,768) Bl
#define PROW 80                           // bytes per smem row (64 + 16 pad)
#define STAGE_BYTES (768 * PROW)          // 61440
#define PROJ_SMEM_BYTES (3 * STAGE_BYTES) // 184320

__global__ __launch_bounds__(256, 1) void proj_mma_kernel(
    const __half* __restrict__ xh, const __half* __restrict__ xl,
    const __half* __restrict__ wthi, const __half* __restrict__ wtlo,
    const float* __restrict__ bq, const float* __restrict__ bk,
    const float* __restrict__ bv, const float* __restrict__ bo1)
{
    extern __shared__ char smem[];
    const uint32_t sbase = smem_u32(smem);

    const int z = blockIdx.z;
    const bool split_ab = (z < 2);     // q,k: split A and split B (3 passes)
    const float* bias = (z == 0) ? bq : (z == 1) ? bk : (z == 2) ? bv : bo1;

    const int tid = threadIdx.x;
    const int wid = tid >> 5;
    const int lane = tid & 31;
    const int wr = wid >> 1;          // warp row (0..3): rows wr*64
    const int wc = wid & 1;           // warp col (0..1): cols wc*64
    const int m0 = blockIdx.y * 256;
    const int n0 = blockIdx.x * 128;

    const __half* A  = xh + (size_t)m0 * EMB;
    const __half* Al = xl + (size_t)m0 * EMB;
    const __half* Bh = wthi + (size_t)z * EMB * EMB + (size_t)n0 * EMB;
    const __half* Bl = wtlo + (size_t)z * EMB * EMB + (size_t)n0 * EMB;

    auto load_stage = [&](int s, int kc) {
        const uint32_t dbase = sbase + (uint32_t)s * STAGE_BYTES;
        const int r64 = tid >> 2;          // 0..63
        const int c16 = tid & 3;           // 16B column
#pragma unroll
        for (int t = 0; t < 12; t++) {
            const int grow = t * 64 + r64;        // smem row 0..767
            const __half* src;
            if (t < 4)       src = A  + (size_t)grow * EMB;
            else if (t < 8)  { if (!split_ab) continue;
                               src = Al + (size_t)(grow - 256) * EMB; }
            else if (t < 10) src = Bh + (size_t)(grow - 512) * EMB;
            else             { if (!split_ab) continue;
                               src = Bl + (size_t)(grow - 640) * EMB; }
            CP_ASYNC16(dbase + (uint32_t)grow * PROW + c16 * 16,
                       src + kc * 32 + c16 * 8);
        }
    };

    float acc[4][8][4];
#pragma unroll
    for (int mi = 0; mi < 4; mi++)
#pragma unroll
        for (int nj = 0; nj < 8; nj++)
#pragma unroll
            for (int e = 0; e < 4; e++) acc[mi][nj][e] = 0.0f;

    const int arow = lane & 15;
    const int ahalf = lane >> 4;
    const int brow = (lane & 7) + ((lane >> 4) << 3);
    const int bkoff = ((lane >> 3) & 1) * 16;

    load_stage(0, 0); CP_COMMIT();
    load_stage(1, 1); CP_COMMIT();

    const int NCH = EMB / 32;    // 32
    int s = 0, ps = 2;
    for (int kc = 0; kc < NCH; kc++) {
        if (kc + 1 < NCH) CP_WAIT(1); else CP_WAIT(0);
        __syncthreads();
        if (kc + 2 < NCH) {
            load_stage(ps, kc + 2);
            CP_COMMIT();
            if (++ps == 3) ps = 0;
        }

        const uint32_t st = sbase + (uint32_t)s * STAGE_BYTES;
        if (++s == 3) s = 0;
#pragma unroll
        for (int k16 = 0; k16 < 2; k16++) {
            uint32_t ah[4][4], al[4][4];
#pragma unroll
            for (int mi = 0; mi < 4; mi++) {
                const uint32_t ra = (uint32_t)(wr * 64 + mi * 16 + arow) * PROW
                                    + k16 * 32 + ahalf * 16;
                ldsm_x4(ah[mi], st + ra);
                if (split_ab) ldsm_x4(al[mi], st + 256 * PROW + ra);
            }
#pragma unroll
            for (int p = 0; p < 4; p++) {
                const uint32_t rb = (uint32_t)(wc * 64 + p * 16 + brow) * PROW
                                    + k16 * 32 + bkoff;
                uint32_t th[4], tl[4];
                ldsm_x4(th, st + 512 * PROW + rb);
                if (split_ab) ldsm_x4(tl, st + 640 * PROW + rb);
#pragma unroll
                for (int mi = 0; mi < 4; mi++) {
                    mma16816h(acc[mi][2 * p],     ah[mi], th);
                    mma16816h(acc[mi][2 * p + 1], ah[mi], th + 2);
                    if (split_ab) {
                        mma16816h(acc[mi][2 * p],     ah[mi], tl);
                        mma16816h(acc[mi][2 * p + 1], ah[mi], tl + 2);
                        mma16816h(acc[mi][2 * p],     al[mi], th);
                        mma16816h(acc[mi][2 * p + 1], al[mi], th + 2);
                    }
                }
            }
        }
    }

    // epilogue: z=0 -> qh+ql; z=1 -> kh single; z=2 -> vh+vl; z=3 -> fp32 relu h
    const int erow = lane >> 2;
    const int ecol = (lane & 3) * 2;
#pragma unroll
    for (int mi = 0; mi < 4; mi++) {
#pragma unroll
        for (int nj = 0; nj < 8; nj++) {
            const int row = m0 + wr * 64 + mi * 16 + erow;
            const int col = n0 + wc * 64 + nj * 8 + ecol;
            const float b0 = bias[col], b1 = bias[col + 1];
            float v00 = acc[mi][nj][0] + b0, v01 = acc[mi][nj][1] + b1;
            float v10 = acc[mi][nj][2] + b0, v11 = acc[mi][nj][3] + b1;
            const size_t o0 = (size_t)row * EMB + col;
            const size_t o1 = (size_t)(row + 8) * EMB + col;
            if (z == 3) {
                float2 r0 = { fmaxf(v00, 0.0f), fmaxf(v01, 0.0f) };
                float2 r1 = { fmaxf(v10, 0.0f), fmaxf(v11, 0.0f) };
                *(float2*)(g_h + o0) = r0;
                *(float2*)(g_h + o1) = r1;
            } else if (z == 1) {
                *(uint32_t*)(g_kh + o0) = pack_h2(v00, v01);
                *(uint32_t*)(g_kh + o1) = pack_h2(v10, v11);
            } else {
                __half* Ch = (z == 0) ? g_qh : g_vh;
                __half* Cl = (z == 0) ? g_ql : g_vl;
                __half h00 = __float2half_rn(v00), h01 = __float2half_rn(v01);
                __half h10 = __float2half_rn(v10), h11 = __float2half_rn(v11);
                *(uint32_t*)(Ch + o0) = pack_h2(v00, v01);
                *(uint32_t*)(Ch + o1) = pack_h2(v10, v11);
                *(uint32_t*)(Cl + o0) =
                    pack_h2(v00 - __half2float(h00), v01 - __half2float(h01));
                *(uint32_t*)(Cl + o1) =
                    pack_h2(v10 - __half2float(h10), v11 - __half2float(h11));
            }
        }
    }
}

// ------------- order-weight head: o = relu_h @ Wo2 + bo2 (N=4) ---------------
__global__ __launch_bounds__(256) void owt_kernel(
    const float* __restrict__ h, const float* __restrict__ Wo2,
    const float* __restrict__ bo2, float* __restrict__ o)
{
    const int warp = (blockIdx.x * blockDim.x + threadIdx.x) >> 5;
    const int lane = threadIdx.x & 31;
    if (warp >= MTOT) return;
    const float* hr = h + (size_t)warp * EMB;
    float a0 = 0.f, a1 = 0.f, a2 = 0.f, a3 = 0.f;
#pragma unroll 4
    for (int k = lane; k < EMB; k += 32) {
        float hv = hr[k];
        float4 w = *(const float4*)(Wo2 + (size_t)k * 4);
        a0 = fmaf(hv, w.x, a0);
        a1 = fmaf(hv, w.y, a1);
        a2 = fmaf(hv, w.z, a2);
        a3 = fmaf(hv, w.w, a3);
    }
#pragma unroll
    for (int m = 16; m > 0; m >>= 1) {
        a0 += __shfl_xor_sync(0xffffffffu, a0, m);
        a1 += __shfl_xor_sync(0xffffffffu, a1, m);
        a2 += __shfl_xor_sync(0xffffffffu, a2, m);
        a3 += __shfl_xor_sync(0xffffffffu, a3, m);
    }
    if (lane == 0) {
        o[warp * 4 + 0] = a0 + bo2[0];
        o[warp * 4 + 1] = a1 + bo2[1];
        o[warp * 4 + 2] = a2 + bo2[2];
        o[warp * 4 + 3] = a3 + bo2[3];
    }
}

// =================== HMMA flash attention + fused mixing =====================
// CTA: 128 queries x 1 head. K/V tiles of 64. 8 warps x 16 rows.
// S = (Qh+Ql) Kh^T (2 passes; K single, accurate-rounded).
// P single fp16 (l sums rounded P); O += P (Vh+Vl) (2 passes).
// Epilogue: org = O/l, then order-weighted polynomial -> final out.
#define ASTR 144
#define QBUF (128 * ASTR)
#define KVBUF (64 * ASTR)
#define ATT_STAGE (3 * KVBUF)             // Kh, Vh, Vl
#define ATT_SMEM_BYTES (2 * QBUF + 2 * ATT_STAGE)   // 92160

__global__ __launch_bounds__(256, 1) void attn_mma_kernel(
    const float* __restrict__ ow, float* __restrict__ out)
{
    extern __shared__ char smem[];
    const uint32_t sb = smem_u32(smem);
    const uint32_t sQH = sb, sQL = sb + QBUF, sST = sb + 2 * QBUF;

    const int qt = blockIdx.x;
    const int hd = blockIdx.y;
    const int b  = blockIdx.z;
    const int q0 = qt * 128;
    const int tid = threadIdx.x;
    const int wid = tid >> 5;
    const int lane = tid & 31;
    const size_t tok0 = (size_t)b * SEQ;
    const size_t hoff = (size_t)hd * DHEAD;

    const __half* Qh = g_qh + (tok0 + q0) * EMB + hoff;
    const __half* Ql = g_ql + (tok0 + q0) * EMB + hoff;
    const __half* Kh = g_kh + tok0 * EMB + hoff;
    const __half* Vh = g_vh + tok0 * EMB + hoff;
    const __half* Vl = g_vl + tok0 * EMB + hoff;

    // Q load (hi + lo), own commit group
#pragma unroll
    for (int t = 0; t < 8; t++) {
        const int idx = tid + t * 256;     // 0..2047
        const int arr = idx >> 10;
        const int w = idx & 1023;
        const int row = w >> 3;
        const int c = w & 7;
        const uint32_t dst = (arr ? sQL : sQH) + row * ASTR + c * 16;
        const void* src = (arr ? Ql : Qh) + (size_t)row * EMB + c * 8;
        CP_ASYNC16(dst, src);
    }
    CP_COMMIT();

    auto load_stage = [&](int s, int kt) {
        const int k0 = kt * 64;
        const __half* srcs[3] = { Kh, Vh, Vl };
        const uint32_t dbase = sST + (uint32_t)s * ATT_STAGE;
#pragma unroll
        for (int t = 0; t < 6; t++) {
            const int idx = tid + t * 256;   // 0..1535
            const int arr = idx >> 9;
            const int w = idx & 511;
            const int row = w >> 3;
            const int c = w & 7;
            const uint32_t dst = dbase + arr * KVBUF + row * ASTR + c * 16;
            const void* src = srcs[arr] + (size_t)(k0 + row) * EMB + c * 8;
            CP_ASYNC16(dst, src);
        }
    };

    load_stage(0, 0);
    CP_COMMIT();
    CP_WAIT(1);
    __syncthreads();

    // Q fragments (resident)
    uint32_t aqh[4][4], aql[4][4];
    {
        const uint32_t qrow = (uint32_t)(wid * 16 + (lane & 15));
#pragma unroll
        for (int ks = 0; ks < 4; ks++) {
            const uint32_t off = qrow * ASTR + ks * 32 + (lane >> 4) * 16;
            ldsm_x4(aqh[ks], sQH + off);
            ldsm_x4(aql[ks], sQL + off);
        }
    }

    float m0 = -CUDART_INF_F, m1 = -CUDART_INF_F, l0 = 0.f, l1 = 0.f;
    float oacc[8][4];
#pragma unroll
    for (int nt = 0; nt < 8; nt++)
#pragma unroll
        for (int e = 0; e < 4; e++) oacc[nt][e] = 0.f;

    const uint32_t kbrow = (uint32_t)((lane & 7) + ((lane >> 4) << 3));
    const uint32_t kboff = (uint32_t)(((lane >> 3) & 1) << 4);
    const uint32_t vbrow = (uint32_t)((lane & 7) + (((lane >> 3) & 1) << 3));
    const uint32_t vboff = (uint32_t)((lane >> 4) << 4);

    const int NT = SEQ / 64;
    for (int kt = 0; kt < NT; kt++) {
        const int s = kt & 1;
        if (kt + 1 < NT) {
            load_stage(s ^ 1, kt + 1);
            CP_COMMIT();
            CP_WAIT(1);
        } else {
            CP_WAIT(0);
        }
        __syncthreads();

        const uint32_t st = sST + (uint32_t)s * ATT_STAGE;

        // ---- S = (Qh+Ql) Kh^T : 2 passes ----
        float sacc[8][4];
#pragma unroll
        for (int nt = 0; nt < 8; nt++)
#pragma unroll
            for (int e = 0; e < 4; e++) sacc[nt][e] = 0.f;

#pragma unroll
        for (int ks = 0; ks < 4; ks++) {
#pragma unroll
            for (int p = 0; p < 4; p++) {
                const uint32_t boff = (p * 16 + kbrow) * ASTR + ks * 32 + kboff;
                uint32_t th[4];
                ldsm_x4(th, st + boff);
                mma16816h(sacc[2 * p],     aqh[ks], th);
                mma16816h(sacc[2 * p + 1], aqh[ks], th + 2);
                mma16816h(sacc[2 * p],     aql[ks], th);
                mma16816h(sacc[2 * p + 1], aql[ks], th + 2);
            }
        }

        // ---- online softmax ----
        float tmax0 = -CUDART_INF_F, tmax1 = -CUDART_INF_F;
#pragma unroll
        for (int nt = 0; nt < 8; nt++) {
            tmax0 = fmaxf(tmax0, fmaxf(sacc[nt][0], sacc[nt][1]));
            tmax1 = fmaxf(tmax1, fmaxf(sacc[nt][2], sacc[nt][3]));
        }
#pragma unroll
        for (int m = 1; m < 4; m <<= 1) {
            tmax0 = fmaxf(tmax0, __shfl_xor_sync(0xffffffffu, tmax0, m));
            tmax1 = fmaxf(tmax1, __shfl_xor_sync(0xffffffffu, tmax1, m));
        }
        const float mnew0 = fmaxf(m0, tmax0);
        const float mnew1 = fmaxf(m1, tmax1);
        const float sc0 = __expf(m0 - mnew0);
        const float sc1 = __expf(m1 - mnew1);

        uint32_t ph[8][2];
        float sum0 = 0.f, sum1 = 0.f;
#pragma unroll
        for (int nt = 0; nt < 8; nt++) {
            float p00 = __expf(sacc[nt][0] - mnew0);
            float p01 = __expf(sacc[nt][1] - mnew0);
            float p10 = __expf(sacc[nt][2] - mnew1);
            float p11 = __expf(sacc[nt][3] - mnew1);
            __half h00 = __float2half_rn(p00), h01 = __float2half_rn(p01);
            __half h10 = __float2half_rn(p10), h11 = __float2half_rn(p11);
            // l sums the ROUNDED probabilities -> O/l unbiased
            sum0 += __half2float(h00) + __half2float(h01);
            sum1 += __half2float(h10) + __half2float(h11);
            __half2 hv0 = __halves2half2(h00, h01);
            __half2 hv1 = __halves2half2(h10, h11);
            ph[nt][0] = *reinterpret_cast<uint32_t*>(&hv0);
            ph[nt][1] = *reinterpret_cast<uint32_t*>(&hv1);
        }
#pragma unroll
        for (int m = 1; m < 4; m <<= 1) {
            sum0 += __shfl_xor_sync(0xffffffffu, sum0, m);
            sum1 += __shfl_xor_sync(0xffffffffu, sum1, m);
        }
        l0 = l0 * sc0 + sum0;
        l1 = l1 * sc1 + sum1;
        m0 = mnew0;
        m1 = mnew1;
#pragma unroll
        for (int nt = 0; nt < 8; nt++) {
            oacc[nt][0] *= sc0; oacc[nt][1] *= sc0;
            oacc[nt][2] *= sc1; oacc[nt][3] *= sc1;
        }

        // ---- O += P (Vh+Vl) : 2 passes ----
#pragma unroll
        for (int ks = 0; ks < 4; ks++) {
            uint32_t Ah_[4] = { ph[2 * ks][0], ph[2 * ks][1],
                                ph[2 * ks + 1][0], ph[2 * ks + 1][1] };
#pragma unroll
            for (int p = 0; p < 4; p++) {
                const uint32_t voff = (ks * 16 + vbrow) * ASTR + p * 32 + vboff;
                uint32_t th[4], tl[4];
                ldsm_x4_t(th, st + 1 * KVBUF + voff);
                ldsm_x4_t(tl, st + 2 * KVBUF + voff);
                mma16816h(oacc[2 * p],     Ah_, th);
                mma16816h(oacc[2 * p + 1], Ah_, th + 2);
                mma16816h(oacc[2 * p],     Ah_, tl);
                mma16816h(oacc[2 * p + 1], Ah_, tl + 2);
            }
        }
        __syncthreads();
    }

    // ---- fused epilogue: org = O/l, then polynomial mixing -> out ----
    const float inv0 = 1.0f / l0;
    const float inv1 = 1.0f / l1;
    const int r0 = q0 + wid * 16 + (lane >> 2);
    const int r1 = r0 + 8;
    const float4 w0v = ((const float4*)ow)[tok0 + r0];
    const float4 w1v = ((const float4*)ow)[tok0 + r1];
#pragma unroll
    for (int nt = 0; nt < 8; nt++) {
        const int col = (int)hoff + nt * 8 + (lane & 3) * 2;
        float g00 = oacc[nt][0] * inv0, g01 = oacc[nt][1] * inv0;
        float g10 = oacc[nt][2] * inv1, g11 = oacc[nt][3] * inv1;
        float2 o0, o1;
        o0.x = g00 * fmaf(g00, fmaf(g00, fmaf(g00, w0v.w, w0v.z), w0v.y), w0v.x);
        o0.y = g01 * fmaf(g01, fmaf(g01, fmaf(g01, w0v.w, w0v.z), w0v.y), w0v.x);
        o1.x = g10 * fmaf(g10, fmaf(g10, fmaf(g10, w1v.w, w1v.z), w1v.y), w1v.x);
        o1.y = g11 * fmaf(g11, fmaf(g11, fmaf(g11, w1v.w, w1v.z), w1v.y), w1v.x);
        *(float2*)(out + (tok0 + r0) * EMB + col) = o0;
        *(float2*)(out + (tok0 + r1) * EMB + col) = o1;
    }
}

// ------------------------------ launch -------------------------------------
extern "C" void kernel_launch(void* const* d_in, const int* in_sizes, int n_in,
                              void* d_out, int out_size)
{
    const float* x   = (const float*)d_in[0];
    const float* Wq  = (const float*)d_in[1];
    const float* bq  = (const float*)d_in[2];
    const float* Wk  = (const float*)d_in[3];
    const float* bk  = (const float*)d_in[4];
    const float* Wv  = (const float*)d_in[5];
    const float* bv  = (const float*)d_in[6];
    const float* Wo1 = (const float*)d_in[7];
    const float* bo1 = (const float*)d_in[8];
    const float* Wo2 = (const float*)d_in[9];
    const float* bo2 = (const float*)d_in[10];
    float* out = (float*)d_out;

    float *h, *o;
    __half *xh, *xl, *wthi, *wtlo;
    cudaGetSymbolAddress((void**)&h, g_h);
    cudaGetSymbolAddress((void**)&o, g_o);
    cudaGetSymbolAddress((void**)&xh, g_xh);
    cudaGetSymbolAddress((void**)&xl, g_xl);
    cudaGetSymbolAddress((void**)&wthi, g_wthi);
    cudaGetSymbolAddress((void**)&wtlo, g_wtlo);

    cudaFuncSetAttribute(proj_mma_kernel,
                         cudaFuncAttributeMaxDynamicSharedMemorySize, PROJ_SMEM_BYTES);
    cudaFuncSetAttribute(attn_mma_kernel,
                         cudaFuncAttributeMaxDynamicSharedMemorySize, ATT_SMEM_BYTES);

    // 1) split x into fp16 hi/lo; split W^T into fp16 hi/lo
    const int nv4 = MTOT * EMB / 4;
    split_x_kernel<<<(nv4 + 255) / 256, 256>>>(x, xh, xl);
    split_wt_kernel<<<dim3(EMB / 32, EMB / 32, 4), dim3(32, 8)>>>(
        Wq, Wk, Wv, Wo1, wthi, wtlo);

    // 2) HMMA projections: q,k 3-pass; v,h 1-pass
    proj_mma_kernel<<<dim3(EMB / 128, MTOT / 256, 4), 256, PROJ_SMEM_BYTES>>>(
        xh, xl, wthi, wtlo, bq, bk, bv, bo1);

    // 3) order weights o = h @ Wo2 + bo2
    owt_kernel<<<(MTOT * 32 + 255) / 256, 256>>>(h, Wo2, bo2, o);

    // 4) HMMA flash attention (QK 2-pass w/ accurate single-K, PV 2-pass)
    //    + fused polynomial mixing -> out
    attn_mma_kernel<<<dim3(SEQ / 128, HEADS, BATCH), 256, ATT_SMEM_BYTES>>>(o, out);
}

// round 10
// speedup vs baseline: 3.2401x; 1.0341x over previous
#include <cuda_runtime.h>
#include <cuda_fp16.h>
#include <cstdint>
#include <math_constants.h>

// Problem constants
#define BATCH 2
#define SEQ   2048
#define EMB   1024
#define HEADS 16
#define DHEAD 64
#define MTOT  (BATCH*SEQ)      // 4096
#define NORD  4

// ---------------- scratch (device globals; no cudaMalloc allowed) ------------
__device__ float g_h[MTOT * EMB];     // relu(x@Wo1 + bo1)
__device__ float g_o[MTOT * NORD];    // order weights

// fp16 q (split), k (single, accurate-rounded), v (split)
__device__ __align__(16) __half g_qh[MTOT * EMB];
__device__ __align__(16) __half g_ql[MTOT * EMB];
__device__ __align__(16) __half g_kh[MTOT * EMB];
__device__ __align__(16) __half g_vh[MTOT * EMB];
__device__ __align__(16) __half g_vl[MTOT * EMB];

// fp16 operands for projection GEMMs: x split (lo used for q,k only), W^T split
__device__ __align__(16) __half g_xh[MTOT * EMB];
__device__ __align__(16) __half g_xl[MTOT * EMB];
__device__ __align__(16) __half g_wthi[4 * EMB * EMB];  // W^T per weight, [n][k]
__device__ __align__(16) __half g_wtlo[4 * EMB * EMB];

// ======================= PTX helpers (arch-portable) =========================
__device__ __forceinline__ uint32_t smem_u32(const void* p) {
    uint32_t a;
    asm("{ .reg .u64 t; cvta.to.shared.u64 t, %1; cvt.u32.u64 %0, t; }"
        : "=r"(a) : "l"(p));
    return a;
}

#define CP_ASYNC16(dst, src) \
    asm volatile("cp.async.cg.shared.global [%0], [%1], 16;" :: "r"(dst), "l"(src))
#define CP_COMMIT() asm volatile("cp.async.commit_group;" ::: "memory")
#define CP_WAIT(n)  asm volatile("cp.async.wait_group %0;" :: "n"(n) : "memory")

__device__ __forceinline__ void ldsm_x4(uint32_t* r, uint32_t addr) {
    asm volatile("ldmatrix.sync.aligned.m8n8.x4.shared.b16 {%0,%1,%2,%3}, [%4];"
        : "=r"(r[0]), "=r"(r[1]), "=r"(r[2]), "=r"(r[3]) : "r"(addr));
}
__device__ __forceinline__ void ldsm_x4_t(uint32_t* r, uint32_t addr) {
    asm volatile("ldmatrix.sync.aligned.m8n8.x4.trans.shared.b16 {%0,%1,%2,%3}, [%4];"
        : "=r"(r[0]), "=r"(r[1]), "=r"(r[2]), "=r"(r[3]) : "r"(addr));
}

// D(f32) += A(f16) * B(f16), m16n8k16
__device__ __forceinline__ void mma16816h(float* c, const uint32_t* a, const uint32_t* b) {
    asm volatile(
        "mma.sync.aligned.m16n8k16.row.col.f32.f16.f16.f32 "
        "{%0,%1,%2,%3}, {%4,%5,%6,%7}, {%8,%9}, {%0,%1,%2,%3};"
        : "+f"(c[0]), "+f"(c[1]), "+f"(c[2]), "+f"(c[3])
        : "r"(a[0]), "r"(a[1]), "r"(a[2]), "r"(a[3]), "r"(b[0]), "r"(b[1]));
}

__device__ __forceinline__ uint32_t pack_h2(float a, float b) {
    __half2 h = __floats2half2_rn(a, b);
    return *reinterpret_cast<uint32_t*>(&h);
}

// ====================== prep kernels =========================================
// split x -> fp16 hi + lo
__global__ __launch_bounds__(256) void split_x_kernel(
    const float* __restrict__ x, __half* __restrict__ hi, __half* __restrict__ lo)
{
    const int i4 = blockIdx.x * blockDim.x + threadIdx.x;
    if (i4 >= MTOT * EMB / 4) return;
    float4 v = ((const float4*)x)[i4];
    __half h0 = __float2half_rn(v.x), h1 = __float2half_rn(v.y);
    __half h2 = __float2half_rn(v.z), h3 = __float2half_rn(v.w);
    uint2 rh, rl;
    __half2 p01 = __halves2half2(h0, h1), p23 = __halves2half2(h2, h3);
    rh.x = *reinterpret_cast<uint32_t*>(&p01);
    rh.y = *reinterpret_cast<uint32_t*>(&p23);
    rl.x = pack_h2(v.x - __half2float(h0), v.y - __half2float(h1));
    rl.y = pack_h2(v.z - __half2float(h2), v.w - __half2float(h3));
    *(uint2*)(hi + 4 * (size_t)i4) = rh;
    *(uint2*)(lo + 4 * (size_t)i4) = rl;
}

// transpose W [k][n] -> W^T [n][k] with fp16 hi/lo split, per-weight (blockIdx.z)
__global__ __launch_bounds__(256) void split_wt_kernel(
    const float* __restrict__ Wq, const float* __restrict__ Wk,
    const float* __restrict__ Wv, const float* __restrict__ Wo1,
    __half* __restrict__ wthi, __half* __restrict__ wtlo)
{
    const int z = blockIdx.z;
    const float* W = (z == 0) ? Wq : (z == 1) ? Wk : (z == 2) ? Wv : Wo1;
    __shared__ float ts[32][33];
    const int n0 = blockIdx.x * 32;
    const int k0 = blockIdx.y * 32;
    const int tx = threadIdx.x, ty = threadIdx.y;   // 32 x 8
#pragma unroll
    for (int i = 0; i < 4; i++)
        ts[ty + 8 * i][tx] = W[(size_t)(k0 + ty + 8 * i) * EMB + n0 + tx];
    __syncthreads();
    __half* oh = wthi + (size_t)z * EMB * EMB;
    __half* ol = wtlo + (size_t)z * EMB * EMB;
#pragma unroll
    for (int i = 0; i < 4; i++) {
        const int n = n0 + ty + 8 * i;
        float v = ts[tx][ty + 8 * i];          // = W[k0+tx][n]
        __half h = __float2half_rn(v);
        __half l = __float2half_rn(v - __half2float(h));
        oh[(size_t)n * EMB + k0 + tx] = h;
        ol[(size_t)n * EMB + k0 + tx] = l;
    }
}

// =================== HMMA projection GEMM (fp16) =============================
// C[256x128] tile = X[256x1024] @ W[1024x128] + b.
// z in {0,1} (q,k): 3 passes (xh*Wh + xh*Wl + xl*Wh) -> accurate.
// z in {2,3} (v,h): 1 pass (xh*Wh) -> linear-path.
// 8 warps, each 64x64. BK=32. 3-stage cp.async ring.
// smem stage rows: [0,256) A | [256,512) Al | [512,640) Bh | [640,768) Bl
#define PROW 80                           // bytes per smem row (64 + 16 pad)
#define STAGE_BYTES (768 * PROW)          // 61440
#define PROJ_SMEM_BYTES (3 * STAGE_BYTES) // 184320

__global__ __launch_bounds__(256, 1) void proj_mma_kernel(
    const __half* __restrict__ xh, const __half* __restrict__ xl,
    const __half* __restrict__ wthi, const __half* __restrict__ wtlo,
    const float* __restrict__ bq, const float* __restrict__ bk,
    const float* __restrict__ bv, const float* __restrict__ bo1)
{
    extern __shared__ char smem[];
    const uint32_t sbase = smem_u32(smem);

    const int z = blockIdx.z;
    const bool split_ab = (z < 2);     // q,k: split A and split B (3 passes)
    const float* bias = (z == 0) ? bq : (z == 1) ? bk : (z == 2) ? bv : bo1;

    const int tid = threadIdx.x;
    const int wid = tid >> 5;
    const int lane = tid & 31;
    const int wr = wid >> 1;          // warp row (0..3): rows wr*64
    const int wc = wid & 1;           // warp col (0..1): cols wc*64
    const int m0 = blockIdx.y * 256;
    const int n0 = blockIdx.x * 128;

    const __half* A  = xh + (size_t)m0 * EMB;
    const __half* Al = xl + (size_t)m0 * EMB;
    const __half* Bh = wthi + (size_t)z * EMB * EMB + (size_t)n0 * EMB;
    const __half* Bl = wtlo + (size_t)z * EMB * EMB + (size_t)n0 * EMB;

    auto load_stage = [&](int s, int kc) {
        const uint32_t dbase = sbase + (uint32_t)s * STAGE_BYTES;
        const int r64 = tid >> 2;          // 0..63
        const int c16 = tid & 3;           // 16B column
#pragma unroll
        for (int t = 0; t < 12; t++) {
            const int grow = t * 64 + r64;        // smem row 0..767
            const __half* src;
            if (t < 4)       src = A  + (size_t)grow * EMB;
            else if (t < 8)  { if (!split_ab) continue;
                               src = Al + (size_t)(grow - 256) * EMB; }
            else if (t < 10) src = Bh + (size_t)(grow - 512) * EMB;
            else             { if (!split_ab) continue;
                               src = Bl + (size_t)(grow - 640) * EMB; }
            CP_ASYNC16(dbase + (uint32_t)grow * PROW + c16 * 16,
                       src + kc * 32 + c16 * 8);
        }
    };

    float acc[4][8][4];
#pragma unroll
    for (int mi = 0; mi < 4; mi++)
#pragma unroll
        for (int nj = 0; nj < 8; nj++)
#pragma unroll
            for (int e = 0; e < 4; e++) acc[mi][nj][e] = 0.0f;

    const int arow = lane & 15;
    const int ahalf = lane >> 4;
    const int brow = (lane & 7) + ((lane >> 4) << 3);
    const int bkoff = ((lane >> 3) & 1) * 16;

    load_stage(0, 0); CP_COMMIT();
    load_stage(1, 1); CP_COMMIT();

    const int NCH = EMB / 32;    // 32
    int s = 0, ps = 2;
    for (int kc = 0; kc < NCH; kc++) {
        if (kc + 1 < NCH) CP_WAIT(1); else CP_WAIT(0);
        __syncthreads();
        if (kc + 2 < NCH) {
            load_stage(ps, kc + 2);
            CP_COMMIT();
            if (++ps == 3) ps = 0;
        }

        const uint32_t st = sbase + (uint32_t)s * STAGE_BYTES;
        if (++s == 3) s = 0;
#pragma unroll
        for (int k16 = 0; k16 < 2; k16++) {
            uint32_t ah[4][4], al[4][4];
#pragma unroll
            for (int mi = 0; mi < 4; mi++) {
                const uint32_t ra = (uint32_t)(wr * 64 + mi * 16 + arow) * PROW
                                    + k16 * 32 + ahalf * 16;
                ldsm_x4(ah[mi], st + ra);
                if (split_ab) ldsm_x4(al[mi], st + 256 * PROW + ra);
            }
#pragma unroll
            for (int p = 0; p < 4; p++) {
                const uint32_t rb = (uint32_t)(wc * 64 + p * 16 + brow) * PROW
                                    + k16 * 32 + bkoff;
                uint32_t th[4], tl[4];
                ldsm_x4(th, st + 512 * PROW + rb);
                if (split_ab) ldsm_x4(tl, st + 640 * PROW + rb);
#pragma unroll
                for (int mi = 0; mi < 4; mi++) {
                    mma16816h(acc[mi][2 * p],     ah[mi], th);
                    mma16816h(acc[mi][2 * p + 1], ah[mi], th + 2);
                    if (split_ab) {
                        mma16816h(acc[mi][2 * p],     ah[mi], tl);
                        mma16816h(acc[mi][2 * p + 1], ah[mi], tl + 2);
                        mma16816h(acc[mi][2 * p],     al[mi], th);
                        mma16816h(acc[mi][2 * p + 1], al[mi], th + 2);
                    }
                }
            }
        }
    }

    // epilogue: z=0 -> qh+ql; z=1 -> kh single; z=2 -> vh+vl; z=3 -> fp32 relu h
    const int erow = lane >> 2;
    const int ecol = (lane & 3) * 2;
#pragma unroll
    for (int mi = 0; mi < 4; mi++) {
#pragma unroll
        for (int nj = 0; nj < 8; nj++) {
            const int row = m0 + wr * 64 + mi * 16 + erow;
            const int col = n0 + wc * 64 + nj * 8 + ecol;
            const float b0 = bias[col], b1 = bias[col + 1];
            float v00 = acc[mi][nj][0] + b0, v01 = acc[mi][nj][1] + b1;
            float v10 = acc[mi][nj][2] + b0, v11 = acc[mi][nj][3] + b1;
            const size_t o0 = (size_t)row * EMB + col;
            const size_t o1 = (size_t)(row + 8) * EMB + col;
            if (z == 3) {
                float2 r0 = { fmaxf(v00, 0.0f), fmaxf(v01, 0.0f) };
                float2 r1 = { fmaxf(v10, 0.0f), fmaxf(v11, 0.0f) };
                *(float2*)(g_h + o0) = r0;
                *(float2*)(g_h + o1) = r1;
            } else if (z == 1) {
                *(uint32_t*)(g_kh + o0) = pack_h2(v00, v01);
                *(uint32_t*)(g_kh + o1) = pack_h2(v10, v11);
            } else {
                __half* Ch = (z == 0) ? g_qh : g_vh;
                __half* Cl = (z == 0) ? g_ql : g_vl;
                __half h00 = __float2half_rn(v00), h01 = __float2half_rn(v01);
                __half h10 = __float2half_rn(v10), h11 = __float2half_rn(v11);
                *(uint32_t*)(Ch + o0) = pack_h2(v00, v01);
                *(uint32_t*)(Ch + o1) = pack_h2(v10, v11);
                *(uint32_t*)(Cl + o0) =
                    pack_h2(v00 - __half2float(h00), v01 - __half2float(h01));
                *(uint32_t*)(Cl + o1) =
                    pack_h2(v10 - __half2float(h10), v11 - __half2float(h11));
            }
        }
    }
}

// ------------- order-weight head: o = relu_h @ Wo2 + bo2 (N=4) ---------------
// one warp per row; float4 h loads for MLP (memory-bound: 16MB read)
__global__ __launch_bounds__(256) void owt_kernel(
    const float* __restrict__ h, const float* __restrict__ Wo2,
    const float* __restrict__ bo2, float* __restrict__ o)
{
    const int warp = (blockIdx.x * blockDim.x + threadIdx.x) >> 5;
    const int lane = threadIdx.x & 31;
    if (warp >= MTOT) return;
    const float4* hr = (const float4*)(h + (size_t)warp * EMB);
    const float4* w4 = (const float4*)Wo2;
    float a0 = 0.f, a1 = 0.f, a2 = 0.f, a3 = 0.f;
#pragma unroll
    for (int k4 = lane; k4 < EMB / 4; k4 += 32) {
        float4 hv = hr[k4];
        float4 w0 = w4[k4 * 4 + 0];
        float4 w1 = w4[k4 * 4 + 1];
        float4 w2 = w4[k4 * 4 + 2];
        float4 w3 = w4[k4 * 4 + 3];
        a0 = fmaf(hv.x, w0.x, fmaf(hv.y, w1.x, fmaf(hv.z, w2.x, fmaf(hv.w, w3.x, a0))));
        a1 = fmaf(hv.x, w0.y, fmaf(hv.y, w1.y, fmaf(hv.z, w2.y, fmaf(hv.w, w3.y, a1))));
        a2 = fmaf(hv.x, w0.z, fmaf(hv.y, w1.z, fmaf(hv.z, w2.z, fmaf(hv.w, w3.z, a2))));
        a3 = fmaf(hv.x, w0.w, fmaf(hv.y, w1.w, fmaf(hv.z, w2.w, fmaf(hv.w, w3.w, a3))));
    }
#pragma unroll
    for (int m = 16; m > 0; m >>= 1) {
        a0 += __shfl_xor_sync(0xffffffffu, a0, m);
        a1 += __shfl_xor_sync(0xffffffffu, a1, m);
        a2 += __shfl_xor_sync(0xffffffffu, a2, m);
        a3 += __shfl_xor_sync(0xffffffffu, a3, m);
    }
    if (lane == 0) {
        o[warp * 4 + 0] = a0 + bo2[0];
        o[warp * 4 + 1] = a1 + bo2[1];
        o[warp * 4 + 2] = a2 + bo2[2];
        o[warp * 4 + 3] = a3 + bo2[3];
    }
}

// =================== HMMA flash attention + fused mixing =====================
// CTA: 256 queries x 1 head (halves the K/V LDGSTS stream per unit work).
// 8 warps; warp owns rows wid*32..wid*32+31 as two 16-row groups.
// S = (Qh+Ql) Kh^T (2 passes); P single fp16 (l sums rounded P);
// O += P (Vh+Vl) (2 passes). Fused polynomial mixing epilogue.
#define ASTR 144
#define QROWS 256
#define QBUF (QROWS * ASTR)               // 36864
#define KVBUF (64 * ASTR)                 // 9216
#define ATT_STAGE (3 * KVBUF)             // Kh, Vh, Vl
#define ATT_SMEM_BYTES (2 * QBUF + 2 * ATT_STAGE)   // 129024

__global__ __launch_bounds__(256, 1) void attn_mma_kernel(
    const float* __restrict__ ow, float* __restrict__ out)
{
    extern __shared__ char smem[];
    const uint32_t sb = smem_u32(smem);
    const uint32_t sQH = sb, sQL = sb + QBUF, sST = sb + 2 * QBUF;

    const int qt = blockIdx.x;     // 0..7
    const int hd = blockIdx.y;
    const int b  = blockIdx.z;
    const int q0 = qt * QROWS;
    const int tid = threadIdx.x;
    const int wid = tid >> 5;
    const int lane = tid & 31;
    const size_t tok0 = (size_t)b * SEQ;
    const size_t hoff = (size_t)hd * DHEAD;

    const __half* Qh = g_qh + (tok0 + q0) * EMB + hoff;
    const __half* Ql = g_ql + (tok0 + q0) * EMB + hoff;
    const __half* Kh = g_kh + tok0 * EMB + hoff;
    const __half* Vh = g_vh + tok0 * EMB + hoff;
    const __half* Vl = g_vl + tok0 * EMB + hoff;

    // Q load (hi + lo, 256 rows), own commit group
#pragma unroll
    for (int t = 0; t < 16; t++) {
        const int idx = tid + t * 256;     // 0..4095
        const int arr = idx >> 11;
        const int w = idx & 2047;
        const int row = w >> 3;            // 0..255
        const int c = w & 7;
        const uint32_t dst = (arr ? sQL : sQH) + row * ASTR + c * 16;
        const void* src = (arr ? Ql : Qh) + (size_t)row * EMB + c * 8;
        CP_ASYNC16(dst, src);
    }
    CP_COMMIT();

    auto load_stage = [&](int s, int kt) {
        const int k0 = kt * 64;
        const __half* srcs[3] = { Kh, Vh, Vl };
        const uint32_t dbase = sST + (uint32_t)s * ATT_STAGE;
#pragma unroll
        for (int t = 0; t < 6; t++) {
            const int idx = tid + t * 256;   // 0..1535
            const int arr = idx >> 9;
            const int w = idx & 511;
            const int row = w >> 3;
            const int c = w & 7;
            const uint32_t dst = dbase + arr * KVBUF + row * ASTR + c * 16;
            const void* src = srcs[arr] + (size_t)(k0 + row) * EMB + c * 8;
            CP_ASYNC16(dst, src);
        }
    };

    load_stage(0, 0);
    CP_COMMIT();
    CP_WAIT(1);
    __syncthreads();

    float mm[2][2], ll[2][2];
    float oacc[2][8][4];
#pragma unroll
    for (int g = 0; g < 2; g++) {
        mm[g][0] = -CUDART_INF_F; mm[g][1] = -CUDART_INF_F;
        ll[g][0] = 0.f; ll[g][1] = 0.f;
#pragma unroll
        for (int nt = 0; nt < 8; nt++)
#pragma unroll
            for (int e = 0; e < 4; e++) oacc[g][nt][e] = 0.f;
    }

    const uint32_t kbrow = (uint32_t)((lane & 7) + ((lane >> 4) << 3));
    const uint32_t kboff = (uint32_t)(((lane >> 3) & 1) << 4);
    const uint32_t vbrow = (uint32_t)((lane & 7) + (((lane >> 3) & 1) << 3));
    const uint32_t vboff = (uint32_t)((lane >> 4) << 4);
    const uint32_t qlrow = (uint32_t)(lane & 15);
    const uint32_t qhalf = (uint32_t)((lane >> 4) * 16);

    const int NT = SEQ / 64;
    for (int kt = 0; kt < NT; kt++) {
        const int s = kt & 1;
        if (kt + 1 < NT) {
            load_stage(s ^ 1, kt + 1);
            CP_COMMIT();
            CP_WAIT(1);
        } else {
            CP_WAIT(0);
        }
        __syncthreads();

        const uint32_t st = sST + (uint32_t)s * ATT_STAGE;

        // ---- S = (Qh+Ql) Kh^T : 2 passes, 2 row-groups ----
        float sacc[2][8][4];
#pragma unroll
        for (int g = 0; g < 2; g++)
#pragma unroll
            for (int nt = 0; nt < 8; nt++)
#pragma unroll
                for (int e = 0; e < 4; e++) sacc[g][nt][e] = 0.f;

#pragma unroll
        for (int ks = 0; ks < 4; ks++) {
            uint32_t qh[2][4], ql[2][4];
#pragma unroll
            for (int g = 0; g < 2; g++) {
                const uint32_t off = (uint32_t)(wid * 32 + g * 16 + qlrow) * ASTR
                                     + ks * 32 + qhalf;
                ldsm_x4(qh[g], sQH + off);
                ldsm_x4(ql[g], sQL + off);
            }
#pragma unroll
            for (int p = 0; p < 4; p++) {
                const uint32_t boff = (p * 16 + kbrow) * ASTR + ks * 32 + kboff;
                uint32_t th[4];
                ldsm_x4(th, st + boff);
#pragma unroll
                for (int g = 0; g < 2; g++) {
                    mma16816h(sacc[g][2 * p],     qh[g], th);
                    mma16816h(sacc[g][2 * p + 1], qh[g], th + 2);
                    mma16816h(sacc[g][2 * p],     ql[g], th);
                    mma16816h(sacc[g][2 * p + 1], ql[g], th + 2);
                }
            }
        }

        // ---- online softmax per group ----
        uint32_t ph[2][8][2];
#pragma unroll
        for (int g = 0; g < 2; g++) {
            float tmax0 = -CUDART_INF_F, tmax1 = -CUDART_INF_F;
#pragma unroll
            for (int nt = 0; nt < 8; nt++) {
                tmax0 = fmaxf(tmax0, fmaxf(sacc[g][nt][0], sacc[g][nt][1]));
                tmax1 = fmaxf(tmax1, fmaxf(sacc[g][nt][2], sacc[g][nt][3]));
            }
#pragma unroll
            for (int m = 1; m < 4; m <<= 1) {
                tmax0 = fmaxf(tmax0, __shfl_xor_sync(0xffffffffu, tmax0, m));
                tmax1 = fmaxf(tmax1, __shfl_xor_sync(0xffffffffu, tmax1, m));
            }
            const float mnew0 = fmaxf(mm[g][0], tmax0);
            const float mnew1 = fmaxf(mm[g][1], tmax1);
            const float sc0 = __expf(mm[g][0] - mnew0);
            const float sc1 = __expf(mm[g][1] - mnew1);

            float sum0 = 0.f, sum1 = 0.f;
#pragma unroll
            for (int nt = 0; nt < 8; nt++) {
                float p00 = __expf(sacc[g][nt][0] - mnew0);
                float p01 = __expf(sacc[g][nt][1] - mnew0);
                float p10 = __expf(sacc[g][nt][2] - mnew1);
                float p11 = __expf(sacc[g][nt][3] - mnew1);
                __half h00 = __float2half_rn(p00), h01 = __float2half_rn(p01);
                __half h10 = __float2half_rn(p10), h11 = __float2half_rn(p11);
                // l sums the ROUNDED probabilities -> O/l unbiased
                sum0 += __half2float(h00) + __half2float(h01);
                sum1 += __half2float(h10) + __half2float(h11);
                __half2 hv0 = __halves2half2(h00, h01);
                __half2 hv1 = __halves2half2(h10, h11);
                ph[g][nt][0] = *reinterpret_cast<uint32_t*>(&hv0);
                ph[g][nt][1] = *reinterpret_cast<uint32_t*>(&hv1);
            }
#pragma unroll
            for (int m = 1; m < 4; m <<= 1) {
                sum0 += __shfl_xor_sync(0xffffffffu, sum0, m);
                sum1 += __shfl_xor_sync(0xffffffffu, sum1, m);
            }
            ll[g][0] = ll[g][0] * sc0 + sum0;
            ll[g][1] = ll[g][1] * sc1 + sum1;
            mm[g][0] = mnew0;
            mm[g][1] = mnew1;
#pragma unroll
            for (int nt = 0; nt < 8; nt++) {
                oacc[g][nt][0] *= sc0; oacc[g][nt][1] *= sc0;
                oacc[g][nt][2] *= sc1; oacc[g][nt][3] *= sc1;
            }
        }

        // ---- O += P (Vh+Vl) : 2 passes, 2 row-groups ----
#pragma unroll
        for (int ks = 0; ks < 4; ks++) {
            uint32_t Ah0[4] = { ph[0][2 * ks][0], ph[0][2 * ks][1],
                                ph[0][2 * ks + 1][0], ph[0][2 * ks + 1][1] };
            uint32_t Ah1[4] = { ph[1][2 * ks][0], ph[1][2 * ks][1],
                                ph[1][2 * ks + 1][0], ph[1][2 * ks + 1][1] };
#pragma unroll
            for (int p = 0; p < 4; p++) {
                const uint32_t voff = (ks * 16 + vbrow) * ASTR + p * 32 + vboff;
                uint32_t th[4], tl[4];
                ldsm_x4_t(th, st + 1 * KVBUF + voff);
                ldsm_x4_t(tl, st + 2 * KVBUF + voff);
                mma16816h(oacc[0][2 * p],     Ah0, th);
                mma16816h(oacc[0][2 * p + 1], Ah0, th + 2);
                mma16816h(oacc[0][2 * p],     Ah0, tl);
                mma16816h(oacc[0][2 * p + 1], Ah0, tl + 2);
                mma16816h(oacc[1][2 * p],     Ah1, th);
                mma16816h(oacc[1][2 * p + 1], Ah1, th + 2);
                mma16816h(oacc[1][2 * p],     Ah1, tl);
                mma16816h(oacc[1][2 * p + 1], Ah1, tl + 2);
            }
        }
        __syncthreads();
    }

    // ---- fused epilogue: org = O/l, then polynomial mixing -> out ----
#pragma unroll
    for (int g = 0; g < 2; g++) {
        const float inv0 = 1.0f / ll[g][0];
        const float inv1 = 1.0f / ll[g][1];
        const int r0 = q0 + wid * 32 + g * 16 + (lane >> 2);
        const int r1 = r0 + 8;
        const float4 w0v = ((const float4*)ow)[tok0 + r0];
        const float4 w1v = ((const float4*)ow)[tok0 + r1];
#pragma unroll
        for (int nt = 0; nt < 8; nt++) {
            const int col = (int)hoff + nt * 8 + (lane & 3) * 2;
            float g00 = oacc[g][nt][0] * inv0, g01 = oacc[g][nt][1] * inv0;
            float g10 = oacc[g][nt][2] * inv1, g11 = oacc[g][nt][3] * inv1;
            float2 o0, o1;
            o0.x = g00 * fmaf(g00, fmaf(g00, fmaf(g00, w0v.w, w0v.z), w0v.y), w0v.x);
            o0.y = g01 * fmaf(g01, fmaf(g01, fmaf(g01, w0v.w, w0v.z), w0v.y), w0v.x);
            o1.x = g10 * fmaf(g10, fmaf(g10, fmaf(g10, w1v.w, w1v.z), w1v.y), w1v.x);
            o1.y = g11 * fmaf(g11, fmaf(g11, fmaf(g11, w1v.w, w1v.z), w1v.y), w1v.x);
            *(float2*)(out + (tok0 + r0) * EMB + col) = o0;
            *(float2*)(out + (tok0 + r1) * EMB + col) = o1;
        }
    }
}

// ------------------------------ launch -------------------------------------
extern "C" void kernel_launch(void* const* d_in, const int* in_sizes, int n_in,
                              void* d_out, int out_size)
{
    const float* x   = (const float*)d_in[0];
    const float* Wq  = (const float*)d_in[1];
    const float* bq  = (const float*)d_in[2];
    const float* Wk  = (const float*)d_in[3];
    const float* bk  = (const float*)d_in[4];
    const float* Wv  = (const float*)d_in[5];
    const float* bv  = (const float*)d_in[6];
    const float* Wo1 = (const float*)d_in[7];
    const float* bo1 = (const float*)d_in[8];
    const float* Wo2 = (const float*)d_in[9];
    const float* bo2 = (const float*)d_in[10];
    float* out = (float*)d_out;

    float *h, *o;
    __half *xh, *xl, *wthi, *wtlo;
    cudaGetSymbolAddress((void**)&h, g_h);
    cudaGetSymbolAddress((void**)&o, g_o);
    cudaGetSymbolAddress((void**)&xh, g_xh);
    cudaGetSymbolAddress((void**)&xl, g_xl);
    cudaGetSymbolAddress((void**)&wthi, g_wthi);
    cudaGetSymbolAddress((void**)&wtlo, g_wtlo);

    cudaFuncSetAttribute(proj_mma_kernel,
                         cudaFuncAttributeMaxDynamicSharedMemorySize, PROJ_SMEM_BYTES);
    cudaFuncSetAttribute(attn_mma_kernel,
                         cudaFuncAttributeMaxDynamicSharedMemorySize, ATT_SMEM_BYTES);

    // 1) split x into fp16 hi/lo; split W^T into fp16 hi/lo
    const int nv4 = MTOT * EMB / 4;
    split_x_kernel<<<(nv4 + 255) / 256, 256>>>(x, xh, xl);
    split_wt_kernel<<<dim3(EMB / 32, EMB / 32, 4), dim3(32, 8)>>>(
        Wq, Wk, Wv, Wo1, wthi, wtlo);

    // 2) HMMA projections: q,k 3-pass; v,h 1-pass
    proj_mma_kernel<<<dim3(EMB / 128, MTOT / 256, 4), 256, PROJ_SMEM_BYTES>>>(
        xh, xl, wthi, wtlo, bq, bk, bv, bo1);

    // 3) order weights o = h @ Wo2 + bo2
    owt_kernel<<<(MTOT * 32 + 255) / 256, 256>>>(h, Wo2, bo2, o);

    // 4) HMMA flash attention (256-q CTAs) + fused polynomial mixing -> out
    attn_mma_kernel<<<dim3(SEQ / QROWS, HEADS, BATCH), 256, ATT_SMEM_BYTES>>>(o, out);
}